// round 4
// baseline (speedup 1.0000x reference)
#include <cuda_runtime.h>
#include <stdint.h>
#include <math_constants.h>

#define BN_EPS 1e-3f
#define BK 32
#define AS_STRIDE 36
#define BS_STRIDE 136
#define ASZ (128 * AS_STRIDE)
#define BSZ (BK * BS_STRIDE)
#define SMEM_GEMM ((2 * ASZ + 2 * BSZ) * 4)

// Segment layout (static): degree-0..4
static const int SEG_START[5] = {0, 4096, 16384, 36864, 57344};
static const int SEG_SIZE[5]  = {4096, 12288, 20480, 20480, 8192};
static const int REL_OFF[5]   = {0, 0, 12288, 32768, 53248};

// -------- scratch (static device globals; no runtime allocation) --------
__device__ float g_rel [61440 * 256];
__device__ float g_bufA[65536 * 256];
__device__ float g_bufB[65536 * 256];
__device__ float g_h   [65536 * 512];
__device__ int   g_cnt [1024];
__device__ int   g_off [1025];
__device__ int   g_cur [1024];
__device__ int   g_perm[65536];

// ======================= MMA helpers =======================
__device__ __forceinline__ uint32_t f2tf(float f) {
    uint32_t r; asm("cvt.rna.tf32.f32 %0, %1;" : "=r"(r) : "f"(f)); return r;
}

__device__ __forceinline__ void mma8(float* d, const uint32_t* a, const uint32_t* b) {
    asm volatile("mma.sync.aligned.m16n8k8.row.col.f32.tf32.tf32.f32 "
        "{%0,%1,%2,%3}, {%4,%5,%6,%7}, {%8,%9}, {%0,%1,%2,%3};"
        : "+f"(d[0]), "+f"(d[1]), "+f"(d[2]), "+f"(d[3])
        : "r"(a[0]), "r"(a[1]), "r"(a[2]), "r"(a[3]), "r"(b[0]), "r"(b[1]));
}

struct Frag { float a[16]; float b[16]; };

// global -> regs prefetch of one BK chunk
__device__ __forceinline__ void load_g(
    Frag& f, const float* __restrict__ A, int K, int kt, bool avec,
    const float* __restrict__ W, int nstride, int col0, int tid)
{
    const int ar = tid >> 1, ac0 = (tid & 1) * 16;
    const float* Ap = A + (long)ar * K + kt + ac0;
    if (avec) {
#pragma unroll
        for (int q = 0; q < 4; q++) {
            float4 v = *reinterpret_cast<const float4*>(Ap + q * 4);
            f.a[q * 4 + 0] = v.x; f.a[q * 4 + 1] = v.y;
            f.a[q * 4 + 2] = v.z; f.a[q * 4 + 3] = v.w;
        }
    } else {
#pragma unroll
        for (int i = 0; i < 16; i++) {
            int k = kt + ac0 + i;
            f.a[i] = (k < K) ? Ap[i] : 0.f;
        }
    }
    const int kr = tid >> 3, nb0 = (tid & 7) * 16;
    const int k = kt + kr;
    if (k < K) {
        const float* Bp = W + (long)k * nstride + col0 + nb0;
#pragma unroll
        for (int q = 0; q < 4; q++) {
            float4 v = *reinterpret_cast<const float4*>(Bp + q * 4);
            f.b[q * 4 + 0] = v.x; f.b[q * 4 + 1] = v.y;
            f.b[q * 4 + 2] = v.z; f.b[q * 4 + 3] = v.w;
        }
    } else {
#pragma unroll
        for (int i = 0; i < 16; i++) f.b[i] = 0.f;
    }
}

// regs -> smem (tf32 convert on store)
__device__ __forceinline__ void store_s(
    uint32_t* As, uint32_t* Bs, const Frag& f, int tid)
{
    const int ar = tid >> 1, ac0 = (tid & 1) * 16;
    uint32_t* Ad = As + ar * AS_STRIDE + ac0;
#pragma unroll
    for (int i = 0; i < 16; i++) Ad[i] = f2tf(f.a[i]);
    const int kr = tid >> 3, nb0 = (tid & 7) * 16;
    uint32_t* Bd = Bs + kr * BS_STRIDE + nb0;
#pragma unroll
    for (int i = 0; i < 16; i++) Bd[i] = f2tf(f.b[i]);
}

__device__ __forceinline__ void gemm_compute(
    const uint32_t* As, const uint32_t* Bs,
    float acc[16][4], int wm, int wn, int gid, int tig)
{
#pragma unroll
    for (int kk = 0; kk < 4; kk++) {
        const int kb = kk * 8;
        uint32_t a[4][4], b[4][2];
#pragma unroll
        for (int mt = 0; mt < 4; mt++) {
            int r = wm * 64 + mt * 16;
            a[mt][0] = As[(r + gid) * AS_STRIDE + kb + tig];
            a[mt][1] = As[(r + gid + 8) * AS_STRIDE + kb + tig];
            a[mt][2] = As[(r + gid) * AS_STRIDE + kb + tig + 4];
            a[mt][3] = As[(r + gid + 8) * AS_STRIDE + kb + tig + 4];
        }
#pragma unroll
        for (int nt = 0; nt < 4; nt++) {
            int c = wn * 32 + nt * 8;
            b[nt][0] = Bs[(kb + tig) * BS_STRIDE + c + gid];
            b[nt][1] = Bs[(kb + tig + 4) * BS_STRIDE + c + gid];
        }
#pragma unroll
        for (int mt = 0; mt < 4; mt++)
#pragma unroll
            for (int nt = 0; nt < 4; nt++)
                mma8(acc[mt * 4 + nt], a[mt], b[nt]);
    }
}

// run one GEMM pass with reg-prefetch double buffering
__device__ __forceinline__ void gemm_pass(
    uint32_t* As2, uint32_t* Bs2,
    const float* __restrict__ A, int K, int KCH, bool avec,
    const float* __restrict__ W, int nstride, int col0,
    float acc[16][4], int tid, int wm, int wn, int gid, int tig)
{
    Frag f;
    load_g(f, A, K, 0, avec, W, nstride, col0, tid);
    store_s(As2, Bs2, f, tid);
    __syncthreads();
    for (int kc = 0; kc < KCH; kc++) {
        int cur = kc & 1;
        if (kc + 1 < KCH)
            load_g(f, A, K, (kc + 1) * BK, avec, W, nstride, col0, tid);
        gemm_compute(As2 + cur * ASZ, Bs2 + cur * BSZ, acc, wm, wn, gid, tig);
        if (kc + 1 < KCH) {
            int nxt = (kc + 1) & 1;
            store_s(As2 + nxt * ASZ, Bs2 + nxt * BSZ, f, tid);
            __syncthreads();
        }
    }
    __syncthreads();
}

// ======================= conv GEMM (tf32 mma.sync) =======================
__global__ void __launch_bounds__(256, 2)
conv_gemm_mma(const float* __restrict__ X, int K, int KCH,
              const float* __restrict__ REL,
              const float* __restrict__ W,    // (9, K, 256)
              const float* __restrict__ bz,   // (9, 256)
              const float* __restrict__ bnp,  // (4, 256)
              float* __restrict__ Y)          // (65536, 256)
{
    extern __shared__ uint32_t dyn[];
    uint32_t* As2 = dyn;
    uint32_t* Bs2 = dyn + 2 * ASZ;
    __shared__ float s_sc[128], s_sh[128], s_bi[128];

    const int tid = threadIdx.x;
    const int lane = tid & 31, wid = tid >> 5;
    const int gid = lane >> 2, tig = lane & 3;
    const int wm = wid & 1, wn = wid >> 1;
    const int row0 = blockIdx.y * 128;
    const int col0 = blockIdx.x * 128;
    const int d = (row0 < 4096) ? 0 : (row0 < 16384) ? 1 : (row0 < 36864) ? 2
                : (row0 < 57344) ? 3 : 4;

    if (tid < 128) {
        int c = col0 + tid;
        float bias = (d == 0) ? bz[8 * 256 + c]
                              : bz[(2 * d - 2) * 256 + c] + bz[(2 * d - 1) * 256 + c];
        float gg = bnp[c], be = bnp[256 + c], mu = bnp[512 + c], va = bnp[768 + c];
        float sc = gg * rsqrtf(va + BN_EPS);
        s_sc[tid] = sc; s_sh[tid] = be - mu * sc; s_bi[tid] = bias;
    }
    __syncthreads();

    const long wsz = (long)K * 256;
    const float* A0 = X + (long)row0 * K;
    const float* W0 = W + ((d == 0) ? 8 : (2 * d - 1)) * wsz;
    const bool avec = ((K & 15) == 0);

    float acc[16][4];
#pragma unroll
    for (int i = 0; i < 16; i++)
        acc[i][0] = acc[i][1] = acc[i][2] = acc[i][3] = 0.f;

    gemm_pass(As2, Bs2, A0, K, KCH, avec, W0, 256, col0,
              acc, tid, wm, wn, gid, tig);
    if (d > 0) {
        const float* A1 = REL + (long)(row0 - 4096) * K;
        const float* W1 = W + (2 * d - 2) * wsz;
        gemm_pass(As2, Bs2, A1, K, KCH, avec, W1, 256, col0,
                  acc, tid, wm, wn, gid, tig);
    }

#pragma unroll
    for (int mt = 0; mt < 4; mt++) {
#pragma unroll
        for (int nt = 0; nt < 4; nt++) {
            int cl = wn * 32 + nt * 8 + tig * 2;
            int r = row0 + wm * 64 + mt * 16 + gid;
            float* a4 = acc[mt * 4 + nt];
            float sc0 = s_sc[cl], sc1 = s_sc[cl + 1];
            float sh0 = s_sh[cl], sh1 = s_sh[cl + 1];
            float bi0 = s_bi[cl], bi1 = s_bi[cl + 1];
            float2 v;
            v.x = fmaxf(a4[0] + bi0, 0.f) * sc0 + sh0;
            v.y = fmaxf(a4[1] + bi1, 0.f) * sc1 + sh1;
            *reinterpret_cast<float2*>(&Y[(long)r * 256 + col0 + cl]) = v;
            v.x = fmaxf(a4[2] + bi0, 0.f) * sc0 + sh0;
            v.y = fmaxf(a4[3] + bi1, 0.f) * sc1 + sh1;
            *reinterpret_cast<float2*>(&Y[(long)(r + 8) * 256 + col0 + cl]) = v;
        }
    }
}

// ======================= dense GEMM (tf32 mma.sync) =======================
__global__ void __launch_bounds__(256, 2)
dense_gemm_mma(const float* __restrict__ X,
               const float* __restrict__ W,    // (256, 512)
               const float* __restrict__ bz,   // (512,)
               const float* __restrict__ bnp,  // (4, 512)
               float* __restrict__ Y)          // (65536, 512)
{
    extern __shared__ uint32_t dyn[];
    uint32_t* As2 = dyn;
    uint32_t* Bs2 = dyn + 2 * ASZ;
    __shared__ float s_sc[128], s_sh[128], s_bi[128];

    const int tid = threadIdx.x;
    const int lane = tid & 31, wid = tid >> 5;
    const int gid = lane >> 2, tig = lane & 3;
    const int wm = wid & 1, wn = wid >> 1;
    const int row0 = blockIdx.y * 128;
    const int col0 = blockIdx.x * 128;
    const int K = 256;

    if (tid < 128) {
        int c = col0 + tid;
        float gg = bnp[c], be = bnp[512 + c], mu = bnp[1024 + c], va = bnp[1536 + c];
        float sc = gg * rsqrtf(va + BN_EPS);
        s_sc[tid] = sc; s_sh[tid] = be - mu * sc; s_bi[tid] = bz[c];
    }
    __syncthreads();

    float acc[16][4];
#pragma unroll
    for (int i = 0; i < 16; i++)
        acc[i][0] = acc[i][1] = acc[i][2] = acc[i][3] = 0.f;

    gemm_pass(As2, Bs2, X + (long)row0 * K, K, 8, true, W, 512, col0,
              acc, tid, wm, wn, gid, tig);

#pragma unroll
    for (int mt = 0; mt < 4; mt++) {
#pragma unroll
        for (int nt = 0; nt < 4; nt++) {
            int cl = wn * 32 + nt * 8 + tig * 2;
            int r = row0 + wm * 64 + mt * 16 + gid;
            float* a4 = acc[mt * 4 + nt];
            float sc0 = s_sc[cl], sc1 = s_sc[cl + 1];
            float sh0 = s_sh[cl], sh1 = s_sh[cl + 1];
            float bi0 = s_bi[cl], bi1 = s_bi[cl + 1];
            float2 v;
            v.x = fmaxf(a4[0] + bi0, 0.f) * sc0 + sh0;
            v.y = fmaxf(a4[1] + bi1, 0.f) * sc1 + sh1;
            *reinterpret_cast<float2*>(&Y[(long)r * 512 + col0 + cl]) = v;
            v.x = fmaxf(a4[2] + bi0, 0.f) * sc0 + sh0;
            v.y = fmaxf(a4[3] + bi1, 0.f) * sc1 + sh1;
            *reinterpret_cast<float2*>(&Y[(long)(r + 8) * 512 + col0 + cl]) = v;
        }
    }
}

// ======================= gather / pool =======================
__global__ void gather_sum(const float* __restrict__ X, int ldx,
                           const int* __restrict__ adj, int d, int nrows,
                           float* __restrict__ out)
{
    int idx = blockIdx.x * blockDim.x + threadIdx.x;
    int tot = nrows * ldx;
    if (idx >= tot) return;
    int i = idx / ldx;
    int c = idx - i * ldx;
    float s = 0.f;
    for (int j = 0; j < d; j++)
        s += X[(long)adj[i * d + j] * ldx + c];
    out[(long)i * ldx + c] = s;
}

__global__ void pool_max(const float* __restrict__ X,
                         const int* __restrict__ adj, int d, int nrows, int off,
                         float* __restrict__ out)
{
    int idx = blockIdx.x * blockDim.x + threadIdx.x;
    int tot = nrows * 256;
    if (idx >= tot) return;
    int i = idx >> 8;
    int c = idx & 255;
    float m = X[(long)(off + i) * 256 + c];
    for (int j = 0; j < d; j++)
        m = fmaxf(m, X[(long)adj[i * d + j] * 256 + c]);
    out[(long)(off + i) * 256 + c] = m;
}

// ======================= segment reduce (sorted, no float atomics) ==========
__global__ void zero_cnt() { g_cnt[blockIdx.x * blockDim.x + threadIdx.x] = 0; }

__global__ void hist_k(const int* __restrict__ mem) {
    int i = blockIdx.x * blockDim.x + threadIdx.x;
    if (i < 65536) atomicAdd(&g_cnt[mem[i]], 1);
}

__global__ void scan_k() {  // single block, 1024 threads
    __shared__ int s[1024];
    int t = threadIdx.x;
    s[t] = g_cnt[t];
    __syncthreads();
    // Hillis-Steele inclusive scan
    for (int ofs = 1; ofs < 1024; ofs <<= 1) {
        int v = (t >= ofs) ? s[t - ofs] : 0;
        __syncthreads();
        s[t] += v;
        __syncthreads();
    }
    int excl = s[t] - g_cnt[t];
    g_off[t] = excl;
    g_cur[t] = excl;
    if (t == 1023) g_off[1024] = s[t];
}

__global__ void scatter_k(const int* __restrict__ mem) {
    int i = blockIdx.x * blockDim.x + threadIdx.x;
    if (i >= 65536) return;
    int p = atomicAdd(&g_cur[mem[i]], 1);
    g_perm[p] = i;
}

// one block per segment; 512 threads = 512 columns; fused tanh -> fp
__global__ void __launch_bounds__(512)
seg_reduce_sorted(const float* __restrict__ H, float* __restrict__ fp)
{
    int b = blockIdx.x, c = threadIdx.x;
    int s = g_off[b], e = g_off[b + 1];
    float sum = 0.f, mx = -CUDART_INF_F;
    for (int j = s; j < e; j++) {
        int r = g_perm[j];
        float v = H[(long)r * 512 + c];
        sum += v;
        mx = fmaxf(mx, v);
    }
    fp[(long)b * 1024 + c]       = tanhf(sum);
    fp[(long)b * 1024 + 512 + c] = tanhf(mx);
}

// ======================= head =======================
__global__ void head_kernel(const float* __restrict__ fp,
                            const float* __restrict__ W,
                            const float* __restrict__ b,
                            float* __restrict__ soft,
                            float* __restrict__ logits)
{
    __shared__ float row[1024];
    __shared__ float lg[24];
    int bi = blockIdx.x;
    for (int c = threadIdx.x; c < 1024; c += blockDim.x)
        row[c] = fp[bi * 1024 + c];
    __syncthreads();
    if (threadIdx.x < 24) {
        int t = threadIdx.x;
        float acc = b[t];
        for (int k = 0; k < 1024; k++)
            acc += row[k] * W[k * 24 + t];
        lg[t] = acc;
        logits[bi * 24 + t] = acc;
    }
    __syncthreads();
    if (threadIdx.x < 12) {
        int t = threadIdx.x;
        float l0 = lg[2 * t], l1 = lg[2 * t + 1];
        float m  = fmaxf(l0, l1);
        float e0 = expf(l0 - m), e1 = expf(l1 - m);
        float inv = 1.f / (e0 + e1);
        soft[bi * 24 + 2 * t]     = e0 * inv;
        soft[bi * 24 + 2 * t + 1] = e1 * inv;
    }
}

// ======================= launch =======================
extern "C" void kernel_launch(void* const* d_in, const int* in_sizes, int n_in,
                              void* d_out, int out_size)
{
    const float* atom       = (const float*)d_in[0];
    const int*   membership = (const int*)  d_in[2];
    const int*   adj[4]     = {(const int*)d_in[4], (const int*)d_in[5],
                               (const int*)d_in[6], (const int*)d_in[7]};
    const float* gc1W = (const float*)d_in[8];
    const float* gc1b = (const float*)d_in[9];
    const float* gc2W = (const float*)d_in[10];
    const float* gc2b = (const float*)d_in[11];
    const float* bn1  = (const float*)d_in[12];
    const float* bn2  = (const float*)d_in[13];
    const float* bn3  = (const float*)d_in[14];
    const float* dW   = (const float*)d_in[15];
    const float* db   = (const float*)d_in[16];
    const float* hW   = (const float*)d_in[17];
    const float* hb   = (const float*)d_in[18];

    float *rel, *bufA, *bufB, *h;
    cudaGetSymbolAddress((void**)&rel,  g_rel);
    cudaGetSymbolAddress((void**)&bufA, g_bufA);
    cudaGetSymbolAddress((void**)&bufB, g_bufB);
    cudaGetSymbolAddress((void**)&h,    g_h);

    cudaFuncSetAttribute(conv_gemm_mma,
                         cudaFuncAttributeMaxDynamicSharedMemorySize, SMEM_GEMM);
    cudaFuncSetAttribute(dense_gemm_mma,
                         cudaFuncAttributeMaxDynamicSharedMemorySize, SMEM_GEMM);

    float* out        = (float*)d_out;
    float* out_soft   = out;
    float* out_logits = out + 1024 * 24;
    float* out_fp     = out + 2 * 1024 * 24;

    // -------- membership permutation (overlaps with layer work) --------
    zero_cnt<<<4, 256>>>();
    hist_k<<<256, 256>>>(membership);
    scan_k<<<1, 1024>>>();
    scatter_k<<<256, 256>>>(membership);

    // ---------------- layer 1 (K = 75) ----------------
    for (int d = 1; d <= 4; d++) {
        int n = SEG_SIZE[d], tot = n * 75;
        gather_sum<<<(tot + 255) / 256, 256>>>(atom, 75, adj[d - 1], d, n,
                                               rel + (long)REL_OFF[d] * 75);
    }
    conv_gemm_mma<<<dim3(2, 512), 256, SMEM_GEMM>>>(atom, 75, 3, rel, gc1W, gc1b, bn1, bufA);
    cudaMemcpyAsync(bufB, bufA, (size_t)4096 * 256 * sizeof(float),
                    cudaMemcpyDeviceToDevice);
    for (int d = 1; d <= 4; d++) {
        int n = SEG_SIZE[d], tot = n * 256;
        pool_max<<<(tot + 255) / 256, 256>>>(bufA, adj[d - 1], d, n, SEG_START[d], bufB);
    }

    // ---------------- layer 2 (K = 256) ----------------
    for (int d = 1; d <= 4; d++) {
        int n = SEG_SIZE[d], tot = n * 256;
        gather_sum<<<(tot + 255) / 256, 256>>>(bufB, 256, adj[d - 1], d, n,
                                               rel + (long)REL_OFF[d] * 256);
    }
    conv_gemm_mma<<<dim3(2, 512), 256, SMEM_GEMM>>>(bufB, 256, 8, rel, gc2W, gc2b, bn2, bufA);
    cudaMemcpyAsync(bufB, bufA, (size_t)4096 * 256 * sizeof(float),
                    cudaMemcpyDeviceToDevice);
    for (int d = 1; d <= 4; d++) {
        int n = SEG_SIZE[d], tot = n * 256;
        pool_max<<<(tot + 255) / 256, 256>>>(bufA, adj[d - 1], d, n, SEG_START[d], bufB);
    }

    // ---------------- dense + BN3 ----------------
    dense_gemm_mma<<<dim3(4, 512), 256, SMEM_GEMM>>>(bufB, dW, db, bn3, h);

    // ---------------- segment sum/max + tanh (no atomics) ----------------
    seg_reduce_sorted<<<1024, 512>>>(h, out_fp);

    // ---------------- head / softmax ----------------
    head_kernel<<<1024, 256>>>(out_fp, hW, hb, out_soft, out_logits);
}

// round 5
// speedup vs baseline: 1.0123x; 1.0123x over previous
#include <cuda_runtime.h>
#include <stdint.h>
#include <math_constants.h>

#define BN_EPS 1e-3f
#define BK 32
#define AS_STRIDE 36
#define BS_STRIDE 136

// Segment layout (static): degree-0..4
static const int SEG_START[5] = {0, 4096, 16384, 36864, 57344};
static const int SEG_SIZE[5]  = {4096, 12288, 20480, 20480, 8192};
static const int REL_OFF[5]   = {0, 0, 12288, 32768, 53248};

// -------- scratch (static device globals; no runtime allocation) --------
__device__ float g_rel [61440 * 256];
__device__ float g_bufA[65536 * 256];
__device__ float g_bufB[65536 * 256];
__device__ float g_h   [65536 * 512];
__device__ int   g_cnt [1024];
__device__ int   g_off [1025];
__device__ int   g_cur [1024];
__device__ int   g_perm[65536];

// ======================= MMA helpers =======================
__device__ __forceinline__ uint32_t f2tf(float f) {
    uint32_t r; asm("cvt.rna.tf32.f32 %0, %1;" : "=r"(r) : "f"(f)); return r;
}

__device__ __forceinline__ void mma8(float* d, const uint32_t* a, const uint32_t* b) {
    asm volatile("mma.sync.aligned.m16n8k8.row.col.f32.tf32.tf32.f32 "
        "{%0,%1,%2,%3}, {%4,%5,%6,%7}, {%8,%9}, {%0,%1,%2,%3};"
        : "+f"(d[0]), "+f"(d[1]), "+f"(d[2]), "+f"(d[3])
        : "r"(a[0]), "r"(a[1]), "r"(a[2]), "r"(a[3]), "r"(b[0]), "r"(b[1]));
}

// Load one BK-chunk of A (128 x 32, [m][k]) and B (32 x N-slice 128, [k][n]).
__device__ __forceinline__ void load_tiles(
    uint32_t* As, uint32_t* Bs,
    const float* __restrict__ A, int K, int kt, bool avec,
    const float* __restrict__ W, int nstride, int col0, int tid)
{
    {
        const int ar = tid >> 1, ac0 = (tid & 1) * 16;
        const float* Ap = A + (long)ar * K + kt + ac0;
        uint32_t* Ad = As + ar * AS_STRIDE + ac0;
        if (avec) {
#pragma unroll
            for (int q = 0; q < 4; q++) {
                float4 v = *reinterpret_cast<const float4*>(Ap + q * 4);
                Ad[q * 4 + 0] = f2tf(v.x); Ad[q * 4 + 1] = f2tf(v.y);
                Ad[q * 4 + 2] = f2tf(v.z); Ad[q * 4 + 3] = f2tf(v.w);
            }
        } else {
#pragma unroll
            for (int i = 0; i < 16; i++) {
                int k = kt + ac0 + i;
                float v = (k < K) ? Ap[i] : 0.f;
                Ad[i] = f2tf(v);
            }
        }
    }
    {
        const int kr = tid >> 3, nb0 = (tid & 7) * 16;
        const int k = kt + kr;
        uint32_t* Bd = Bs + kr * BS_STRIDE + nb0;
        if (k < K) {
            const float* Bp = W + (long)k * nstride + col0 + nb0;
#pragma unroll
            for (int q = 0; q < 4; q++) {
                float4 v = *reinterpret_cast<const float4*>(Bp + q * 4);
                Bd[q * 4 + 0] = f2tf(v.x); Bd[q * 4 + 1] = f2tf(v.y);
                Bd[q * 4 + 2] = f2tf(v.z); Bd[q * 4 + 3] = f2tf(v.w);
            }
        } else {
#pragma unroll
            for (int i = 0; i < 16; i++) Bd[i] = 0u;
        }
    }
}

__device__ __forceinline__ void gemm_compute(
    const uint32_t* As, const uint32_t* Bs,
    float acc[16][4], int wm, int wn, int gid, int tig)
{
#pragma unroll
    for (int kk = 0; kk < 4; kk++) {
        const int kb = kk * 8;
        uint32_t a[4][4], b[4][2];
#pragma unroll
        for (int mt = 0; mt < 4; mt++) {
            int r = wm * 64 + mt * 16;
            a[mt][0] = As[(r + gid) * AS_STRIDE + kb + tig];
            a[mt][1] = As[(r + gid + 8) * AS_STRIDE + kb + tig];
            a[mt][2] = As[(r + gid) * AS_STRIDE + kb + tig + 4];
            a[mt][3] = As[(r + gid + 8) * AS_STRIDE + kb + tig + 4];
        }
#pragma unroll
        for (int nt = 0; nt < 4; nt++) {
            int c = wn * 32 + nt * 8;
            b[nt][0] = Bs[(kb + tig) * BS_STRIDE + c + gid];
            b[nt][1] = Bs[(kb + tig + 4) * BS_STRIDE + c + gid];
        }
#pragma unroll
        for (int mt = 0; mt < 4; mt++)
#pragma unroll
            for (int nt = 0; nt < 4; nt++)
                mma8(acc[mt * 4 + nt], a[mt], b[nt]);
    }
}

// ======================= conv GEMM (tf32 mma.sync) =======================
__global__ void __launch_bounds__(256, 2)
conv_gemm_mma(const float* __restrict__ X, int K, int KCH,
              const float* __restrict__ REL,
              const float* __restrict__ W,    // (9, K, 256)
              const float* __restrict__ bz,   // (9, 256)
              const float* __restrict__ bnp,  // (4, 256)
              float* __restrict__ Y)          // (65536, 256)
{
    __shared__ uint32_t As[128 * AS_STRIDE];
    __shared__ uint32_t Bs[BK * BS_STRIDE];
    __shared__ float s_sc[128], s_sh[128], s_bi[128];

    const int tid = threadIdx.x;
    const int lane = tid & 31, wid = tid >> 5;
    const int gid = lane >> 2, tig = lane & 3;
    const int wm = wid & 1, wn = wid >> 1;
    const int row0 = blockIdx.y * 128;
    const int col0 = blockIdx.x * 128;
    const int d = (row0 < 4096) ? 0 : (row0 < 16384) ? 1 : (row0 < 36864) ? 2
                : (row0 < 57344) ? 3 : 4;

    if (tid < 128) {
        int c = col0 + tid;
        float bias = (d == 0) ? bz[8 * 256 + c]
                              : bz[(2 * d - 2) * 256 + c] + bz[(2 * d - 1) * 256 + c];
        float gg = bnp[c], be = bnp[256 + c], mu = bnp[512 + c], va = bnp[768 + c];
        float sc = gg * rsqrtf(va + BN_EPS);
        s_sc[tid] = sc; s_sh[tid] = be - mu * sc; s_bi[tid] = bias;
    }

    const long wsz = (long)K * 256;
    const float* A0 = X + (long)row0 * K;
    const float* W0 = W + ((d == 0) ? 8 : (2 * d - 1)) * wsz;
    const float* A1 = (d > 0) ? REL + (long)(row0 - 4096) * K : A0;
    const float* W1 = (d > 0) ? W + (2 * d - 2) * wsz : W0;
    const int npass = (d > 0) ? 2 : 1;
    const bool avec = ((K & 15) == 0);

    float acc[16][4];
#pragma unroll
    for (int i = 0; i < 16; i++)
        acc[i][0] = acc[i][1] = acc[i][2] = acc[i][3] = 0.f;

    for (int pass = 0; pass < npass; pass++) {
        const float* A = pass ? A1 : A0;
        const float* Wp = pass ? W1 : W0;
        for (int kc = 0; kc < KCH; kc++) {
            __syncthreads();
            load_tiles(As, Bs, A, K, kc * BK, avec, Wp, 256, col0, tid);
            __syncthreads();
            gemm_compute(As, Bs, acc, wm, wn, gid, tig);
        }
    }

#pragma unroll
    for (int mt = 0; mt < 4; mt++) {
#pragma unroll
        for (int nt = 0; nt < 4; nt++) {
            int cl = wn * 32 + nt * 8 + tig * 2;
            int r = row0 + wm * 64 + mt * 16 + gid;
            float* a4 = acc[mt * 4 + nt];
            float sc0 = s_sc[cl], sc1 = s_sc[cl + 1];
            float sh0 = s_sh[cl], sh1 = s_sh[cl + 1];
            float bi0 = s_bi[cl], bi1 = s_bi[cl + 1];
            float2 v;
            v.x = fmaxf(a4[0] + bi0, 0.f) * sc0 + sh0;
            v.y = fmaxf(a4[1] + bi1, 0.f) * sc1 + sh1;
            *reinterpret_cast<float2*>(&Y[(long)r * 256 + col0 + cl]) = v;
            v.x = fmaxf(a4[2] + bi0, 0.f) * sc0 + sh0;
            v.y = fmaxf(a4[3] + bi1, 0.f) * sc1 + sh1;
            *reinterpret_cast<float2*>(&Y[(long)(r + 8) * 256 + col0 + cl]) = v;
        }
    }
}

// ======================= dense GEMM (tf32 mma.sync) =======================
__global__ void __launch_bounds__(256, 2)
dense_gemm_mma(const float* __restrict__ X,
               const float* __restrict__ W,    // (256, 512)
               const float* __restrict__ bz,   // (512,)
               const float* __restrict__ bnp,  // (4, 512)
               float* __restrict__ Y)          // (65536, 512)
{
    __shared__ uint32_t As[128 * AS_STRIDE];
    __shared__ uint32_t Bs[BK * BS_STRIDE];
    __shared__ float s_sc[128], s_sh[128], s_bi[128];

    const int tid = threadIdx.x;
    const int lane = tid & 31, wid = tid >> 5;
    const int gid = lane >> 2, tig = lane & 3;
    const int wm = wid & 1, wn = wid >> 1;
    const int row0 = blockIdx.y * 128;
    const int col0 = blockIdx.x * 128;
    const int K = 256;

    if (tid < 128) {
        int c = col0 + tid;
        float gg = bnp[c], be = bnp[512 + c], mu = bnp[1024 + c], va = bnp[1536 + c];
        float sc = gg * rsqrtf(va + BN_EPS);
        s_sc[tid] = sc; s_sh[tid] = be - mu * sc; s_bi[tid] = bz[c];
    }

    float acc[16][4];
#pragma unroll
    for (int i = 0; i < 16; i++)
        acc[i][0] = acc[i][1] = acc[i][2] = acc[i][3] = 0.f;

    const float* A = X + (long)row0 * K;
    for (int kc = 0; kc < 8; kc++) {
        __syncthreads();
        load_tiles(As, Bs, A, K, kc * BK, true, W, 512, col0, tid);
        __syncthreads();
        gemm_compute(As, Bs, acc, wm, wn, gid, tig);
    }

#pragma unroll
    for (int mt = 0; mt < 4; mt++) {
#pragma unroll
        for (int nt = 0; nt < 4; nt++) {
            int cl = wn * 32 + nt * 8 + tig * 2;
            int r = row0 + wm * 64 + mt * 16 + gid;
            float* a4 = acc[mt * 4 + nt];
            float sc0 = s_sc[cl], sc1 = s_sc[cl + 1];
            float sh0 = s_sh[cl], sh1 = s_sh[cl + 1];
            float bi0 = s_bi[cl], bi1 = s_bi[cl + 1];
            float2 v;
            v.x = fmaxf(a4[0] + bi0, 0.f) * sc0 + sh0;
            v.y = fmaxf(a4[1] + bi1, 0.f) * sc1 + sh1;
            *reinterpret_cast<float2*>(&Y[(long)r * 512 + col0 + cl]) = v;
            v.x = fmaxf(a4[2] + bi0, 0.f) * sc0 + sh0;
            v.y = fmaxf(a4[3] + bi1, 0.f) * sc1 + sh1;
            *reinterpret_cast<float2*>(&Y[(long)(r + 8) * 512 + col0 + cl]) = v;
        }
    }
}

// ======================= gather / pool =======================
__global__ void gather_sum(const float* __restrict__ X, int ldx,
                           const int* __restrict__ adj, int d, int nrows,
                           float* __restrict__ out)
{
    int idx = blockIdx.x * blockDim.x + threadIdx.x;
    int tot = nrows * ldx;
    if (idx >= tot) return;
    int i = idx / ldx;
    int c = idx - i * ldx;
    float s = 0.f;
    for (int j = 0; j < d; j++)
        s += X[(long)adj[i * d + j] * ldx + c];
    out[(long)i * ldx + c] = s;
}

__global__ void pool_max(const float* __restrict__ X,
                         const int* __restrict__ adj, int d, int nrows, int off,
                         float* __restrict__ out)
{
    int idx = blockIdx.x * blockDim.x + threadIdx.x;
    int tot = nrows * 256;
    if (idx >= tot) return;
    int i = idx >> 8;
    int c = idx & 255;
    float m = X[(long)(off + i) * 256 + c];
    for (int j = 0; j < d; j++)
        m = fmaxf(m, X[(long)adj[i * d + j] * 256 + c]);
    out[(long)(off + i) * 256 + c] = m;
}

// ======================= segment reduce (sorted, no float atomics) ==========
__global__ void zero_cnt() { g_cnt[blockIdx.x * blockDim.x + threadIdx.x] = 0; }

__global__ void hist_k(const int* __restrict__ mem) {
    int i = blockIdx.x * blockDim.x + threadIdx.x;
    if (i < 65536) atomicAdd(&g_cnt[mem[i]], 1);
}

__global__ void scan_k() {  // single block, 1024 threads
    __shared__ int s[1024];
    int t = threadIdx.x;
    s[t] = g_cnt[t];
    __syncthreads();
    for (int ofs = 1; ofs < 1024; ofs <<= 1) {
        int v = (t >= ofs) ? s[t - ofs] : 0;
        __syncthreads();
        s[t] += v;
        __syncthreads();
    }
    int excl = s[t] - g_cnt[t];
    g_off[t] = excl;
    g_cur[t] = excl;
    if (t == 1023) g_off[1024] = s[t];
}

__global__ void scatter_k(const int* __restrict__ mem) {
    int i = blockIdx.x * blockDim.x + threadIdx.x;
    if (i >= 65536) return;
    int p = atomicAdd(&g_cur[mem[i]], 1);
    g_perm[p] = i;
}

// one block per segment; 256 threads x float2 = 512 cols; fused tanh -> fp
__global__ void __launch_bounds__(256)
seg_reduce_sorted(const float* __restrict__ H, float* __restrict__ fp)
{
    int b = blockIdx.x, c2 = threadIdx.x;
    int s = g_off[b], e = g_off[b + 1];
    float2 sum = make_float2(0.f, 0.f);
    float2 mx  = make_float2(-CUDART_INF_F, -CUDART_INF_F);
    for (int j = s; j < e; j++) {
        int r = g_perm[j];
        float2 v = *reinterpret_cast<const float2*>(&H[(long)r * 512 + c2 * 2]);
        sum.x += v.x; sum.y += v.y;
        mx.x = fmaxf(mx.x, v.x); mx.y = fmaxf(mx.y, v.y);
    }
    float2 o;
    o.x = tanhf(sum.x); o.y = tanhf(sum.y);
    *reinterpret_cast<float2*>(&fp[(long)b * 1024 + c2 * 2]) = o;
    o.x = tanhf(mx.x); o.y = tanhf(mx.y);
    *reinterpret_cast<float2*>(&fp[(long)b * 1024 + 512 + c2 * 2]) = o;
}

// ======================= head =======================
__global__ void head_kernel(const float* __restrict__ fp,
                            const float* __restrict__ W,
                            const float* __restrict__ b,
                            float* __restrict__ soft,
                            float* __restrict__ logits)
{
    __shared__ float row[1024];
    __shared__ float lg[24];
    int bi = blockIdx.x;
    for (int c = threadIdx.x; c < 1024; c += blockDim.x)
        row[c] = fp[bi * 1024 + c];
    __syncthreads();
    if (threadIdx.x < 24) {
        int t = threadIdx.x;
        float acc = b[t];
        for (int k = 0; k < 1024; k++)
            acc += row[k] * W[k * 24 + t];
        lg[t] = acc;
        logits[bi * 24 + t] = acc;
    }
    __syncthreads();
    if (threadIdx.x < 12) {
        int t = threadIdx.x;
        float l0 = lg[2 * t], l1 = lg[2 * t + 1];
        float m  = fmaxf(l0, l1);
        float e0 = expf(l0 - m), e1 = expf(l1 - m);
        float inv = 1.f / (e0 + e1);
        soft[bi * 24 + 2 * t]     = e0 * inv;
        soft[bi * 24 + 2 * t + 1] = e1 * inv;
    }
}

// ======================= launch =======================
extern "C" void kernel_launch(void* const* d_in, const int* in_sizes, int n_in,
                              void* d_out, int out_size)
{
    const float* atom       = (const float*)d_in[0];
    const int*   membership = (const int*)  d_in[2];
    const int*   adj[4]     = {(const int*)d_in[4], (const int*)d_in[5],
                               (const int*)d_in[6], (const int*)d_in[7]};
    const float* gc1W = (const float*)d_in[8];
    const float* gc1b = (const float*)d_in[9];
    const float* gc2W = (const float*)d_in[10];
    const float* gc2b = (const float*)d_in[11];
    const float* bn1  = (const float*)d_in[12];
    const float* bn2  = (const float*)d_in[13];
    const float* bn3  = (const float*)d_in[14];
    const float* dW   = (const float*)d_in[15];
    const float* db   = (const float*)d_in[16];
    const float* hW   = (const float*)d_in[17];
    const float* hb   = (const float*)d_in[18];

    float *rel, *bufA, *bufB, *h;
    cudaGetSymbolAddress((void**)&rel,  g_rel);
    cudaGetSymbolAddress((void**)&bufA, g_bufA);
    cudaGetSymbolAddress((void**)&bufB, g_bufB);
    cudaGetSymbolAddress((void**)&h,    g_h);

    float* out        = (float*)d_out;
    float* out_soft   = out;
    float* out_logits = out + 1024 * 24;
    float* out_fp     = out + 2 * 1024 * 24;

    // -------- membership permutation (overlaps with layer work) --------
    zero_cnt<<<4, 256>>>();
    hist_k<<<256, 256>>>(membership);
    scan_k<<<1, 1024>>>();
    scatter_k<<<256, 256>>>(membership);

    // ---------------- layer 1 (K = 75) ----------------
    for (int d = 1; d <= 4; d++) {
        int n = SEG_SIZE[d], tot = n * 75;
        gather_sum<<<(tot + 255) / 256, 256>>>(atom, 75, adj[d - 1], d, n,
                                               rel + (long)REL_OFF[d] * 75);
    }
    conv_gemm_mma<<<dim3(2, 512), 256>>>(atom, 75, 3, rel, gc1W, gc1b, bn1, bufA);
    cudaMemcpyAsync(bufB, bufA, (size_t)4096 * 256 * sizeof(float),
                    cudaMemcpyDeviceToDevice);
    for (int d = 1; d <= 4; d++) {
        int n = SEG_SIZE[d], tot = n * 256;
        pool_max<<<(tot + 255) / 256, 256>>>(bufA, adj[d - 1], d, n, SEG_START[d], bufB);
    }

    // ---------------- layer 2 (K = 256) ----------------
    for (int d = 1; d <= 4; d++) {
        int n = SEG_SIZE[d], tot = n * 256;
        gather_sum<<<(tot + 255) / 256, 256>>>(bufB, 256, adj[d - 1], d, n,
                                               rel + (long)REL_OFF[d] * 256);
    }
    conv_gemm_mma<<<dim3(2, 512), 256>>>(bufB, 256, 8, rel, gc2W, gc2b, bn2, bufA);
    cudaMemcpyAsync(bufB, bufA, (size_t)4096 * 256 * sizeof(float),
                    cudaMemcpyDeviceToDevice);
    for (int d = 1; d <= 4; d++) {
        int n = SEG_SIZE[d], tot = n * 256;
        pool_max<<<(tot + 255) / 256, 256>>>(bufA, adj[d - 1], d, n, SEG_START[d], bufB);
    }

    // ---------------- dense + BN3 ----------------
    dense_gemm_mma<<<dim3(4, 512), 256>>>(bufB, dW, db, bn3, h);

    // ---------------- segment sum/max + tanh (no atomics) ----------------
    seg_reduce_sorted<<<1024, 256>>>(h, out_fp);

    // ---------------- head / softmax ----------------
    head_kernel<<<1024, 256>>>(out_fp, hW, hb, out_soft, out_logits);
}

// round 6
// speedup vs baseline: 1.3689x; 1.3524x over previous
#include <cuda_runtime.h>
#include <stdint.h>

#define BN_EPS 1e-3f
#define BK 32
#define AS_STRIDE 36
#define BS_STRIDE 136

// Segment layout (static): degree-0..4
// atom rows:  d0 [0,4096) d1 [4096,16384) d2 [16384,36864) d3 [36864,57344) d4 [57344,65536)
// rel rows:   d1 [0,12288) d2 [12288,32768) d3 [32768,53248) d4 [53248,61440)

// -------- scratch (static device globals; no runtime allocation) --------
__device__ float    g_rel [61440 * 256];
__device__ float    g_bufA[65536 * 256];
__device__ float    g_bufB[65536 * 256];
__device__ float    g_h   [65536 * 512];
__device__ float    g_sum [1024 * 512];
__device__ unsigned g_maxu[1024 * 512];

// ======================= MMA helpers =======================
__device__ __forceinline__ uint32_t f2tf(float f) {
    uint32_t r; asm("cvt.rna.tf32.f32 %0, %1;" : "=r"(r) : "f"(f)); return r;
}

__device__ __forceinline__ void mma8(float* d, const uint32_t* a, const uint32_t* b) {
    asm volatile("mma.sync.aligned.m16n8k8.row.col.f32.tf32.tf32.f32 "
        "{%0,%1,%2,%3}, {%4,%5,%6,%7}, {%8,%9}, {%0,%1,%2,%3};"
        : "+f"(d[0]), "+f"(d[1]), "+f"(d[2]), "+f"(d[3])
        : "r"(a[0]), "r"(a[1]), "r"(a[2]), "r"(a[3]), "r"(b[0]), "r"(b[1]));
}

// Load one BK-chunk of A (128 x 32, [m][k]) and B (32 x N-slice 128, [k][n]).
__device__ __forceinline__ void load_tiles(
    uint32_t* As, uint32_t* Bs,
    const float* __restrict__ A, int K, int kt, bool avec,
    const float* __restrict__ W, int nstride, int col0, int tid)
{
    {
        const int ar = tid >> 1, ac0 = (tid & 1) * 16;
        const float* Ap = A + (long)ar * K + kt + ac0;
        uint32_t* Ad = As + ar * AS_STRIDE + ac0;
        if (avec) {
#pragma unroll
            for (int q = 0; q < 4; q++) {
                float4 v = *reinterpret_cast<const float4*>(Ap + q * 4);
                Ad[q * 4 + 0] = f2tf(v.x); Ad[q * 4 + 1] = f2tf(v.y);
                Ad[q * 4 + 2] = f2tf(v.z); Ad[q * 4 + 3] = f2tf(v.w);
            }
        } else {
#pragma unroll
            for (int i = 0; i < 16; i++) {
                int k = kt + ac0 + i;
                float v = (k < K) ? Ap[i] : 0.f;
                Ad[i] = f2tf(v);
            }
        }
    }
    {
        const int kr = tid >> 3, nb0 = (tid & 7) * 16;
        const int k = kt + kr;
        uint32_t* Bd = Bs + kr * BS_STRIDE + nb0;
        if (k < K) {
            const float* Bp = W + (long)k * nstride + col0 + nb0;
#pragma unroll
            for (int q = 0; q < 4; q++) {
                float4 v = *reinterpret_cast<const float4*>(Bp + q * 4);
                Bd[q * 4 + 0] = f2tf(v.x); Bd[q * 4 + 1] = f2tf(v.y);
                Bd[q * 4 + 2] = f2tf(v.z); Bd[q * 4 + 3] = f2tf(v.w);
            }
        } else {
#pragma unroll
            for (int i = 0; i < 16; i++) Bd[i] = 0u;
        }
    }
}

__device__ __forceinline__ void gemm_compute(
    const uint32_t* As, const uint32_t* Bs,
    float acc[16][4], int wm, int wn, int gid, int tig)
{
#pragma unroll
    for (int kk = 0; kk < 4; kk++) {
        const int kb = kk * 8;
        uint32_t a[4][4], b[4][2];
#pragma unroll
        for (int mt = 0; mt < 4; mt++) {
            int r = wm * 64 + mt * 16;
            a[mt][0] = As[(r + gid) * AS_STRIDE + kb + tig];
            a[mt][1] = As[(r + gid + 8) * AS_STRIDE + kb + tig];
            a[mt][2] = As[(r + gid) * AS_STRIDE + kb + tig + 4];
            a[mt][3] = As[(r + gid + 8) * AS_STRIDE + kb + tig + 4];
        }
#pragma unroll
        for (int nt = 0; nt < 4; nt++) {
            int c = wn * 32 + nt * 8;
            b[nt][0] = Bs[(kb + tig) * BS_STRIDE + c + gid];
            b[nt][1] = Bs[(kb + tig + 4) * BS_STRIDE + c + gid];
        }
#pragma unroll
        for (int mt = 0; mt < 4; mt++)
#pragma unroll
            for (int nt = 0; nt < 4; nt++)
                mma8(acc[mt * 4 + nt], a[mt], b[nt]);
    }
}

// ======================= conv GEMM (tf32 mma.sync) =======================
__global__ void __launch_bounds__(256, 2)
conv_gemm_mma(const float* __restrict__ X, int K, int KCH,
              const float* __restrict__ REL,
              const float* __restrict__ W,    // (9, K, 256)
              const float* __restrict__ bz,   // (9, 256)
              const float* __restrict__ bnp,  // (4, 256)
              float* __restrict__ Y)          // (65536, 256)
{
    __shared__ uint32_t As[128 * AS_STRIDE];
    __shared__ uint32_t Bs[BK * BS_STRIDE];
    __shared__ float s_sc[128], s_sh[128], s_bi[128];

    const int tid = threadIdx.x;
    const int lane = tid & 31, wid = tid >> 5;
    const int gid = lane >> 2, tig = lane & 3;
    const int wm = wid & 1, wn = wid >> 1;
    const int row0 = blockIdx.y * 128;
    const int col0 = blockIdx.x * 128;
    const int d = (row0 < 4096) ? 0 : (row0 < 16384) ? 1 : (row0 < 36864) ? 2
                : (row0 < 57344) ? 3 : 4;

    if (tid < 128) {
        int c = col0 + tid;
        float bias = (d == 0) ? bz[8 * 256 + c]
                              : bz[(2 * d - 2) * 256 + c] + bz[(2 * d - 1) * 256 + c];
        float gg = bnp[c], be = bnp[256 + c], mu = bnp[512 + c], va = bnp[768 + c];
        float sc = gg * rsqrtf(va + BN_EPS);
        s_sc[tid] = sc; s_sh[tid] = be - mu * sc; s_bi[tid] = bias;
    }

    const long wsz = (long)K * 256;
    const float* A0 = X + (long)row0 * K;
    const float* W0 = W + ((d == 0) ? 8 : (2 * d - 1)) * wsz;
    const float* A1 = (d > 0) ? REL + (long)(row0 - 4096) * K : A0;
    const float* W1 = (d > 0) ? W + (2 * d - 2) * wsz : W0;
    const int npass = (d > 0) ? 2 : 1;
    const bool avec = ((K & 15) == 0);

    float acc[16][4];
#pragma unroll
    for (int i = 0; i < 16; i++)
        acc[i][0] = acc[i][1] = acc[i][2] = acc[i][3] = 0.f;

    for (int pass = 0; pass < npass; pass++) {
        const float* A = pass ? A1 : A0;
        const float* Wp = pass ? W1 : W0;
        for (int kc = 0; kc < KCH; kc++) {
            __syncthreads();
            load_tiles(As, Bs, A, K, kc * BK, avec, Wp, 256, col0, tid);
            __syncthreads();
            gemm_compute(As, Bs, acc, wm, wn, gid, tig);
        }
    }

#pragma unroll
    for (int mt = 0; mt < 4; mt++) {
#pragma unroll
        for (int nt = 0; nt < 4; nt++) {
            int cl = wn * 32 + nt * 8 + tig * 2;
            int r = row0 + wm * 64 + mt * 16 + gid;
            float* a4 = acc[mt * 4 + nt];
            float sc0 = s_sc[cl], sc1 = s_sc[cl + 1];
            float sh0 = s_sh[cl], sh1 = s_sh[cl + 1];
            float bi0 = s_bi[cl], bi1 = s_bi[cl + 1];
            float2 v;
            v.x = fmaxf(a4[0] + bi0, 0.f) * sc0 + sh0;
            v.y = fmaxf(a4[1] + bi1, 0.f) * sc1 + sh1;
            *reinterpret_cast<float2*>(&Y[(long)r * 256 + col0 + cl]) = v;
            v.x = fmaxf(a4[2] + bi0, 0.f) * sc0 + sh0;
            v.y = fmaxf(a4[3] + bi1, 0.f) * sc1 + sh1;
            *reinterpret_cast<float2*>(&Y[(long)(r + 8) * 256 + col0 + cl]) = v;
        }
    }
}

// ======================= dense GEMM (tf32 mma.sync) =======================
__global__ void __launch_bounds__(256, 2)
dense_gemm_mma(const float* __restrict__ X,
               const float* __restrict__ W,    // (256, 512)
               const float* __restrict__ bz,   // (512,)
               const float* __restrict__ bnp,  // (4, 512)
               float* __restrict__ Y)          // (65536, 512)
{
    __shared__ uint32_t As[128 * AS_STRIDE];
    __shared__ uint32_t Bs[BK * BS_STRIDE];
    __shared__ float s_sc[128], s_sh[128], s_bi[128];

    const int tid = threadIdx.x;
    const int lane = tid & 31, wid = tid >> 5;
    const int gid = lane >> 2, tig = lane & 3;
    const int wm = wid & 1, wn = wid >> 1;
    const int row0 = blockIdx.y * 128;
    const int col0 = blockIdx.x * 128;
    const int K = 256;

    if (tid < 128) {
        int c = col0 + tid;
        float gg = bnp[c], be = bnp[512 + c], mu = bnp[1024 + c], va = bnp[1536 + c];
        float sc = gg * rsqrtf(va + BN_EPS);
        s_sc[tid] = sc; s_sh[tid] = be - mu * sc; s_bi[tid] = bz[c];
    }

    float acc[16][4];
#pragma unroll
    for (int i = 0; i < 16; i++)
        acc[i][0] = acc[i][1] = acc[i][2] = acc[i][3] = 0.f;

    const float* A = X + (long)row0 * K;
    for (int kc = 0; kc < 8; kc++) {
        __syncthreads();
        load_tiles(As, Bs, A, K, kc * BK, true, W, 512, col0, tid);
        __syncthreads();
        gemm_compute(As, Bs, acc, wm, wn, gid, tig);
    }

#pragma unroll
    for (int mt = 0; mt < 4; mt++) {
#pragma unroll
        for (int nt = 0; nt < 4; nt++) {
            int cl = wn * 32 + nt * 8 + tig * 2;
            int r = row0 + wm * 64 + mt * 16 + gid;
            float* a4 = acc[mt * 4 + nt];
            float sc0 = s_sc[cl], sc1 = s_sc[cl + 1];
            float sh0 = s_sh[cl], sh1 = s_sh[cl + 1];
            float bi0 = s_bi[cl], bi1 = s_bi[cl + 1];
            float2 v;
            v.x = fmaxf(a4[0] + bi0, 0.f) * sc0 + sh0;
            v.y = fmaxf(a4[1] + bi1, 0.f) * sc1 + sh1;
            *reinterpret_cast<float2*>(&Y[(long)r * 512 + col0 + cl]) = v;
            v.x = fmaxf(a4[2] + bi0, 0.f) * sc0 + sh0;
            v.y = fmaxf(a4[3] + bi1, 0.f) * sc1 + sh1;
            *reinterpret_cast<float2*>(&Y[(long)(r + 8) * 512 + col0 + cl]) = v;
        }
    }
}

// ======================= merged gather (all 4 degrees, one launch) ==========
// rel rows: d1 [0,12288) d2 [12288,32768) d3 [32768,53248) d4 [53248,61440)
__global__ void gather_all(const float* __restrict__ X, int ldx,
                           const int* __restrict__ a1, const int* __restrict__ a2,
                           const int* __restrict__ a3, const int* __restrict__ a4,
                           float* __restrict__ out)
{
    long idx = (long)blockIdx.x * blockDim.x + threadIdx.x;
    long tot = 61440L * ldx;
    if (idx >= tot) return;
    int i = (int)(idx / ldx);
    int c = (int)(idx - (long)i * ldx);
    const int* adj; int d, li;
    if (i < 12288)      { adj = a1; d = 1; li = i; }
    else if (i < 32768) { adj = a2; d = 2; li = i - 12288; }
    else if (i < 53248) { adj = a3; d = 3; li = i - 32768; }
    else                { adj = a4; d = 4; li = i - 53248; }
    float s = 0.f;
    for (int j = 0; j < d; j++)
        s += X[(long)adj[li * d + j] * ldx + c];
    out[(long)i * ldx + c] = s;
}

// ======================= merged pool (copy d0 + max d1..4, one launch) =======
__global__ void pool_all(const float* __restrict__ X,
                         const int* __restrict__ a1, const int* __restrict__ a2,
                         const int* __restrict__ a3, const int* __restrict__ a4,
                         float* __restrict__ out)
{
    long idx = (long)blockIdx.x * blockDim.x + threadIdx.x;
    if (idx >= 65536L * 256) return;
    int row = (int)(idx >> 8);
    int c = (int)(idx & 255);
    float m = X[idx];
    if (row >= 4096) {
        const int* adj; int d, li;
        if (row < 16384)      { adj = a1; d = 1; li = row - 4096; }
        else if (row < 36864) { adj = a2; d = 2; li = row - 16384; }
        else if (row < 57344) { adj = a3; d = 3; li = row - 36864; }
        else                  { adj = a4; d = 4; li = row - 57344; }
        for (int j = 0; j < d; j++)
            m = fmaxf(m, X[(long)adj[li * d + j] * 256 + c]);
    }
    out[idx] = m;
}

// ======================= segment reduce (atomic, proven) =======================
__device__ __forceinline__ unsigned ford(float f) {
    unsigned u = __float_as_uint(f);
    return u ^ (unsigned)(((int)u >> 31) | 0x80000000);
}
__device__ __forceinline__ float funord(unsigned v) {
    unsigned u = (v & 0x80000000u) ? (v ^ 0x80000000u) : ~v;
    return __uint_as_float(u);
}

__global__ void seg_init_sum(float* __restrict__ ssum)
{
    int idx = blockIdx.x * blockDim.x + threadIdx.x;
    if (idx < 1024 * 512) ssum[idx] = 0.f;
}

__global__ void seg_init_max(unsigned* __restrict__ smax)
{
    int idx = blockIdx.x * blockDim.x + threadIdx.x;
    if (idx < 1024 * 512) smax[idx] = 0x007FFFFFu;  // ford(-inf)
}

__global__ void seg_reduce(const float* __restrict__ H,
                           const int* __restrict__ mem,
                           float* __restrict__ ssum, unsigned* __restrict__ smax)
{
    int idx = blockIdx.x * blockDim.x + threadIdx.x;
    if (idx >= 65536 * 512) return;
    int i = idx >> 9;
    int c = idx & 511;
    float v = H[idx];
    int m = mem[i];
    atomicAdd(&ssum[m * 512 + c], v);
    atomicMax(&smax[m * 512 + c], ford(v));
}

__global__ void fp_tanh(const float* __restrict__ ssum,
                        const unsigned* __restrict__ smax,
                        float* __restrict__ fp)
{
    int idx = blockIdx.x * blockDim.x + threadIdx.x;
    if (idx >= 1024 * 1024) return;
    int b = idx >> 10;
    int c = idx & 1023;
    float v = (c < 512) ? ssum[b * 512 + c] : funord(smax[b * 512 + (c - 512)]);
    fp[idx] = tanhf(v);
}

// ======================= head =======================
__global__ void head_kernel(const float* __restrict__ fp,
                            const float* __restrict__ W,
                            const float* __restrict__ b,
                            float* __restrict__ soft,
                            float* __restrict__ logits)
{
    __shared__ float row[1024];
    __shared__ float lg[24];
    int bi = blockIdx.x;
    for (int c = threadIdx.x; c < 1024; c += blockDim.x)
        row[c] = fp[bi * 1024 + c];
    __syncthreads();
    if (threadIdx.x < 24) {
        int t = threadIdx.x;
        float acc = b[t];
        for (int k = 0; k < 1024; k++)
            acc += row[k] * W[k * 24 + t];
        lg[t] = acc;
        logits[bi * 24 + t] = acc;
    }
    __syncthreads();
    if (threadIdx.x < 12) {
        int t = threadIdx.x;
        float l0 = lg[2 * t], l1 = lg[2 * t + 1];
        float m  = fmaxf(l0, l1);
        float e0 = expf(l0 - m), e1 = expf(l1 - m);
        float inv = 1.f / (e0 + e1);
        soft[bi * 24 + 2 * t]     = e0 * inv;
        soft[bi * 24 + 2 * t + 1] = e1 * inv;
    }
}

// ======================= launch =======================
extern "C" void kernel_launch(void* const* d_in, const int* in_sizes, int n_in,
                              void* d_out, int out_size)
{
    const float* atom       = (const float*)d_in[0];
    const int*   membership = (const int*)  d_in[2];
    const int*   a1 = (const int*)d_in[4];
    const int*   a2 = (const int*)d_in[5];
    const int*   a3 = (const int*)d_in[6];
    const int*   a4 = (const int*)d_in[7];
    const float* gc1W = (const float*)d_in[8];
    const float* gc1b = (const float*)d_in[9];
    const float* gc2W = (const float*)d_in[10];
    const float* gc2b = (const float*)d_in[11];
    const float* bn1  = (const float*)d_in[12];
    const float* bn2  = (const float*)d_in[13];
    const float* bn3  = (const float*)d_in[14];
    const float* dW   = (const float*)d_in[15];
    const float* db   = (const float*)d_in[16];
    const float* hW   = (const float*)d_in[17];
    const float* hb   = (const float*)d_in[18];

    float *rel, *bufA, *bufB, *h, *ssum;
    unsigned* smax;
    cudaGetSymbolAddress((void**)&rel,  g_rel);
    cudaGetSymbolAddress((void**)&bufA, g_bufA);
    cudaGetSymbolAddress((void**)&bufB, g_bufB);
    cudaGetSymbolAddress((void**)&h,    g_h);
    cudaGetSymbolAddress((void**)&ssum, g_sum);
    cudaGetSymbolAddress((void**)&smax, g_maxu);

    float* out        = (float*)d_out;
    float* out_soft   = out;
    float* out_logits = out + 1024 * 24;
    float* out_fp     = out + 2 * 1024 * 24;

    // launch #1: merged layer-1 gather
    {
        long tot = 61440L * 75;
        gather_all<<<(int)((tot + 255) / 256), 256>>>(atom, 75, a1, a2, a3, a4, rel);
    }
    // launches #2, #3: independent fillers (segment-pool init)
    seg_init_sum<<<(1024 * 512 + 255) / 256, 256>>>(ssum);
    seg_init_max<<<(1024 * 512 + 255) / 256, 256>>>(smax);

    // launch #4: conv1 GEMM (profiled slot)
    conv_gemm_mma<<<dim3(2, 512), 256>>>(atom, 75, 3, rel, gc1W, gc1b, bn1, bufA);

    // launch #5: merged pool 1 (includes degree-0 copy)
    pool_all<<<(int)((65536L * 256 + 255) / 256), 256>>>(bufA, a1, a2, a3, a4, bufB);

    // launch #6: merged layer-2 gather
    {
        long tot = 61440L * 256;
        gather_all<<<(int)((tot + 255) / 256), 256>>>(bufB, 256, a1, a2, a3, a4, rel);
    }

    // launch #7: conv2 GEMM
    conv_gemm_mma<<<dim3(2, 512), 256>>>(bufB, 256, 8, rel, gc2W, gc2b, bn2, bufA);

    // launch #8: merged pool 2
    pool_all<<<(int)((65536L * 256 + 255) / 256), 256>>>(bufA, a1, a2, a3, a4, bufB);

    // launch #9: dense + BN3
    dense_gemm_mma<<<dim3(4, 512), 256>>>(bufB, dW, db, bn3, h);

    // launch #10: atomic segment sum/max
    seg_reduce<<<(65536 * 512 + 255) / 256, 256>>>(h, membership, ssum, smax);

    // launch #11: fp = tanh([sum | max])
    fp_tanh<<<(1024 * 1024 + 255) / 256, 256>>>(ssum, smax, out_fp);

    // launch #12: head + softmax
    head_kernel<<<1024, 256>>>(out_fp, hW, hb, out_soft, out_logits);
}

// round 7
// speedup vs baseline: 1.5781x; 1.1528x over previous
#include <cuda_runtime.h>
#include <stdint.h>

#define BN_EPS 1e-3f
#define BK 32
// A tile: 128 rows x 32 k, fp16, row stride 40 halves (=20 u32 words, 80B)
// B tile: 32 k x 128 n, fp16, row stride 136 halves (=68 words, 272B = 17*16B)
#define ASW 20
#define BSW 68

// Segment layout (static): degree-0..4
// atom rows:  d0 [0,4096) d1 [4096,16384) d2 [16384,36864) d3 [36864,57344) d4 [57344,65536)
// rel rows:   d1 [0,12288) d2 [12288,32768) d3 [32768,53248) d4 [53248,61440)

// -------- scratch (static device globals; no runtime allocation) --------
__device__ float    g_rel [61440 * 256];
__device__ float    g_bufA[65536 * 256];
__device__ float    g_bufB[65536 * 256];
__device__ float    g_h   [65536 * 512];
__device__ float    g_sum [1024 * 512];
__device__ unsigned g_maxu[1024 * 512];

// ======================= helpers =======================
__device__ __forceinline__ uint32_t smem_u32(const void* p) {
    uint32_t a;
    asm("{ .reg .u64 t; cvta.to.shared.u64 t, %1; cvt.u32.u64 %0, t; }" : "=r"(a) : "l"(p));
    return a;
}

// pack two fp32 -> f16x2 (lo in low half, hi in high half), round-to-nearest
__device__ __forceinline__ uint32_t pkf16(float lo, float hi) {
    uint32_t r; asm("cvt.rn.f16x2.f32 %0, %1, %2;" : "=r"(r) : "f"(hi), "f"(lo));
    return r;
}

__device__ __forceinline__ void ldsm_x2t(uint32_t& r0, uint32_t& r1, uint32_t addr) {
    asm volatile("ldmatrix.sync.aligned.m8n8.x2.trans.shared.b16 {%0,%1}, [%2];"
        : "=r"(r0), "=r"(r1) : "r"(addr));
}

__device__ __forceinline__ void mma16(float* d, const uint32_t* a, const uint32_t* b) {
    asm volatile("mma.sync.aligned.m16n8k16.row.col.f32.f16.f16.f32 "
        "{%0,%1,%2,%3}, {%4,%5,%6,%7}, {%8,%9}, {%0,%1,%2,%3};"
        : "+f"(d[0]), "+f"(d[1]), "+f"(d[2]), "+f"(d[3])
        : "r"(a[0]), "r"(a[1]), "r"(a[2]), "r"(a[3]), "r"(b[0]), "r"(b[1]));
}

// Load one BK-chunk: A (128 x 32 -> fp16 [m][k]) and B (32 x 128 n-slice -> fp16 [k][n]).
__device__ __forceinline__ void load_tiles_h(
    uint32_t* As, uint32_t* Bs,
    const float* __restrict__ A, int K, int kt, bool avec,
    const float* __restrict__ W, int nstride, int col0, int tid)
{
    // ---- A: row ar = tid>>1, 16 k-values at ac0 = (tid&1)*16 ----
    {
        const int ar = tid >> 1, ac0 = (tid & 1) * 16;
        const float* Ap = A + (long)ar * K + kt + ac0;
        uint32_t p[8];
        if (avec) {
#pragma unroll
            for (int q = 0; q < 4; q++) {
                float4 v = *reinterpret_cast<const float4*>(Ap + q * 4);
                p[q * 2 + 0] = pkf16(v.x, v.y);
                p[q * 2 + 1] = pkf16(v.z, v.w);
            }
        } else {
            float t[16];
#pragma unroll
            for (int i = 0; i < 16; i++) {
                int k = kt + ac0 + i;
                t[i] = (k < K) ? Ap[i] : 0.f;
            }
#pragma unroll
            for (int q = 0; q < 8; q++) p[q] = pkf16(t[2 * q], t[2 * q + 1]);
        }
        uint4* dst = reinterpret_cast<uint4*>(As + ar * ASW + (ac0 >> 1));
        dst[0] = make_uint4(p[0], p[1], p[2], p[3]);
        dst[1] = make_uint4(p[4], p[5], p[6], p[7]);
    }
    // ---- B: k-row kr = tid>>3, 16 n-values at nb0 = (tid&7)*16 ----
    {
        const int kr = tid >> 3, nb0 = (tid & 7) * 16;
        const int k = kt + kr;
        uint32_t p[8];
        if (k < K) {
            const float* Bp = W + (long)k * nstride + col0 + nb0;
#pragma unroll
            for (int q = 0; q < 4; q++) {
                float4 v = *reinterpret_cast<const float4*>(Bp + q * 4);
                p[q * 2 + 0] = pkf16(v.x, v.y);
                p[q * 2 + 1] = pkf16(v.z, v.w);
            }
        } else {
#pragma unroll
            for (int q = 0; q < 8; q++) p[q] = 0u;
        }
        uint4* dst = reinterpret_cast<uint4*>(Bs + kr * BSW + (nb0 >> 1));
        dst[0] = make_uint4(p[0], p[1], p[2], p[3]);
        dst[1] = make_uint4(p[4], p[5], p[6], p[7]);
    }
}

// compute on one chunk: 2 k16-steps, warp tile 64x32
__device__ __forceinline__ void gemm_compute_h(
    const uint32_t* As, uint32_t bs_addr,
    float acc[16][4], int wm, int wn, int gid, int tig, int lane)
{
#pragma unroll
    for (int ks = 0; ks < 2; ks++) {
        uint32_t a[4][4];
#pragma unroll
        for (int mt = 0; mt < 4; mt++) {
            int r = wm * 64 + mt * 16;
            int base = (r + gid) * ASW + ks * 8 + tig;
            a[mt][0] = As[base];
            a[mt][1] = As[base + 8 * ASW];
            a[mt][2] = As[base + 4];
            a[mt][3] = As[base + 8 * ASW + 4];
        }
        uint32_t b[4][2];
        uint32_t krow = ks * 16 + (lane & 15);
#pragma unroll
        for (int nt = 0; nt < 4; nt++) {
            int n0 = wn * 32 + nt * 8;
            ldsm_x2t(b[nt][0], b[nt][1], bs_addr + (krow * (2 * BSW) + n0) * 2);
        }
#pragma unroll
        for (int mt = 0; mt < 4; mt++)
#pragma unroll
            for (int nt = 0; nt < 4; nt++)
                mma16(acc[mt * 4 + nt], a[mt], b[nt]);
    }
}

// ======================= conv GEMM (fp16 mma.sync) =======================
__global__ void __launch_bounds__(256, 2)
conv_gemm_mma(const float* __restrict__ X, int K, int KCH,
              const float* __restrict__ REL,
              const float* __restrict__ W,    // (9, K, 256)
              const float* __restrict__ bz,   // (9, 256)
              const float* __restrict__ bnp,  // (4, 256)
              float* __restrict__ Y)          // (65536, 256)
{
    __shared__ uint32_t As[128 * ASW];
    __shared__ uint32_t Bs[BK * BSW];
    __shared__ float s_sc[128], s_sh[128], s_bi[128];

    const int tid = threadIdx.x;
    const int lane = tid & 31, wid = tid >> 5;
    const int gid = lane >> 2, tig = lane & 3;
    const int wm = wid & 1, wn = wid >> 1;
    const int row0 = blockIdx.y * 128;
    const int col0 = blockIdx.x * 128;
    const int d = (row0 < 4096) ? 0 : (row0 < 16384) ? 1 : (row0 < 36864) ? 2
                : (row0 < 57344) ? 3 : 4;
    const uint32_t bs_addr = smem_u32(Bs);

    if (tid < 128) {
        int c = col0 + tid;
        float bias = (d == 0) ? bz[8 * 256 + c]
                              : bz[(2 * d - 2) * 256 + c] + bz[(2 * d - 1) * 256 + c];
        float gg = bnp[c], be = bnp[256 + c], mu = bnp[512 + c], va = bnp[768 + c];
        float sc = gg * rsqrtf(va + BN_EPS);
        s_sc[tid] = sc; s_sh[tid] = be - mu * sc; s_bi[tid] = bias;
    }

    const long wsz = (long)K * 256;
    const float* A0 = X + (long)row0 * K;
    const float* W0 = W + ((d == 0) ? 8 : (2 * d - 1)) * wsz;
    const float* A1 = (d > 0) ? REL + (long)(row0 - 4096) * K : A0;
    const float* W1 = (d > 0) ? W + (2 * d - 2) * wsz : W0;
    const int npass = (d > 0) ? 2 : 1;
    const bool avec = ((K & 15) == 0);

    float acc[16][4];
#pragma unroll
    for (int i = 0; i < 16; i++)
        acc[i][0] = acc[i][1] = acc[i][2] = acc[i][3] = 0.f;

    for (int pass = 0; pass < npass; pass++) {
        const float* A = pass ? A1 : A0;
        const float* Wp = pass ? W1 : W0;
        for (int kc = 0; kc < KCH; kc++) {
            __syncthreads();
            load_tiles_h(As, Bs, A, K, kc * BK, avec, Wp, 256, col0, tid);
            __syncthreads();
            gemm_compute_h(As, bs_addr, acc, wm, wn, gid, tig, lane);
        }
    }

#pragma unroll
    for (int mt = 0; mt < 4; mt++) {
#pragma unroll
        for (int nt = 0; nt < 4; nt++) {
            int cl = wn * 32 + nt * 8 + tig * 2;
            int r = row0 + wm * 64 + mt * 16 + gid;
            float* a4 = acc[mt * 4 + nt];
            float sc0 = s_sc[cl], sc1 = s_sc[cl + 1];
            float sh0 = s_sh[cl], sh1 = s_sh[cl + 1];
            float bi0 = s_bi[cl], bi1 = s_bi[cl + 1];
            float2 v;
            v.x = fmaxf(a4[0] + bi0, 0.f) * sc0 + sh0;
            v.y = fmaxf(a4[1] + bi1, 0.f) * sc1 + sh1;
            *reinterpret_cast<float2*>(&Y[(long)r * 256 + col0 + cl]) = v;
            v.x = fmaxf(a4[2] + bi0, 0.f) * sc0 + sh0;
            v.y = fmaxf(a4[3] + bi1, 0.f) * sc1 + sh1;
            *reinterpret_cast<float2*>(&Y[(long)(r + 8) * 256 + col0 + cl]) = v;
        }
    }
}

// ======================= dense GEMM (fp16 mma.sync) =======================
__global__ void __launch_bounds__(256, 2)
dense_gemm_mma(const float* __restrict__ X,
               const float* __restrict__ W,    // (256, 512)
               const float* __restrict__ bz,   // (512,)
               const float* __restrict__ bnp,  // (4, 512)
               float* __restrict__ Y)          // (65536, 512)
{
    __shared__ uint32_t As[128 * ASW];
    __shared__ uint32_t Bs[BK * BSW];
    __shared__ float s_sc[128], s_sh[128], s_bi[128];

    const int tid = threadIdx.x;
    const int lane = tid & 31, wid = tid >> 5;
    const int gid = lane >> 2, tig = lane & 3;
    const int wm = wid & 1, wn = wid >> 1;
    const int row0 = blockIdx.y * 128;
    const int col0 = blockIdx.x * 128;
    const int K = 256;
    const uint32_t bs_addr = smem_u32(Bs);

    if (tid < 128) {
        int c = col0 + tid;
        float gg = bnp[c], be = bnp[512 + c], mu = bnp[1024 + c], va = bnp[1536 + c];
        float sc = gg * rsqrtf(va + BN_EPS);
        s_sc[tid] = sc; s_sh[tid] = be - mu * sc; s_bi[tid] = bz[c];
    }

    float acc[16][4];
#pragma unroll
    for (int i = 0; i < 16; i++)
        acc[i][0] = acc[i][1] = acc[i][2] = acc[i][3] = 0.f;

    const float* A = X + (long)row0 * K;
    for (int kc = 0; kc < 8; kc++) {
        __syncthreads();
        load_tiles_h(As, Bs, A, K, kc * BK, true, W, 512, col0, tid);
        __syncthreads();
        gemm_compute_h(As, bs_addr, acc, wm, wn, gid, tig, lane);
    }

#pragma unroll
    for (int mt = 0; mt < 4; mt++) {
#pragma unroll
        for (int nt = 0; nt < 4; nt++) {
            int cl = wn * 32 + nt * 8 + tig * 2;
            int r = row0 + wm * 64 + mt * 16 + gid;
            float* a4 = acc[mt * 4 + nt];
            float sc0 = s_sc[cl], sc1 = s_sc[cl + 1];
            float sh0 = s_sh[cl], sh1 = s_sh[cl + 1];
            float bi0 = s_bi[cl], bi1 = s_bi[cl + 1];
            float2 v;
            v.x = fmaxf(a4[0] + bi0, 0.f) * sc0 + sh0;
            v.y = fmaxf(a4[1] + bi1, 0.f) * sc1 + sh1;
            *reinterpret_cast<float2*>(&Y[(long)r * 512 + col0 + cl]) = v;
            v.x = fmaxf(a4[2] + bi0, 0.f) * sc0 + sh0;
            v.y = fmaxf(a4[3] + bi1, 0.f) * sc1 + sh1;
            *reinterpret_cast<float2*>(&Y[(long)(r + 8) * 512 + col0 + cl]) = v;
        }
    }
}

// ======================= merged gather (all 4 degrees, one launch) ==========
__global__ void gather_all(const float* __restrict__ X, int ldx,
                           const int* __restrict__ a1, const int* __restrict__ a2,
                           const int* __restrict__ a3, const int* __restrict__ a4,
                           float* __restrict__ out)
{
    long idx = (long)blockIdx.x * blockDim.x + threadIdx.x;
    long tot = 61440L * ldx;
    if (idx >= tot) return;
    int i = (int)(idx / ldx);
    int c = (int)(idx - (long)i * ldx);
    const int* adj; int d, li;
    if (i < 12288)      { adj = a1; d = 1; li = i; }
    else if (i < 32768) { adj = a2; d = 2; li = i - 12288; }
    else if (i < 53248) { adj = a3; d = 3; li = i - 32768; }
    else                { adj = a4; d = 4; li = i - 53248; }
    float s = 0.f;
    for (int j = 0; j < d; j++)
        s += X[(long)adj[li * d + j] * ldx + c];
    out[(long)i * ldx + c] = s;
}

// ======================= merged pool (copy d0 + max d1..4, one launch) =======
__global__ void pool_all(const float* __restrict__ X,
                         const int* __restrict__ a1, const int* __restrict__ a2,
                         const int* __restrict__ a3, const int* __restrict__ a4,
                         float* __restrict__ out)
{
    long idx = (long)blockIdx.x * blockDim.x + threadIdx.x;
    if (idx >= 65536L * 256) return;
    int row = (int)(idx >> 8);
    int c = (int)(idx & 255);
    float m = X[idx];
    if (row >= 4096) {
        const int* adj; int d, li;
        if (row < 16384)      { adj = a1; d = 1; li = row - 4096; }
        else if (row < 36864) { adj = a2; d = 2; li = row - 16384; }
        else if (row < 57344) { adj = a3; d = 3; li = row - 36864; }
        else                  { adj = a4; d = 4; li = row - 57344; }
        for (int j = 0; j < d; j++)
            m = fmaxf(m, X[(long)adj[li * d + j] * 256 + c]);
    }
    out[idx] = m;
}

// ======================= segment reduce (atomic, proven) =======================
__device__ __forceinline__ unsigned ford(float f) {
    unsigned u = __float_as_uint(f);
    return u ^ (unsigned)(((int)u >> 31) | 0x80000000);
}
__device__ __forceinline__ float funord(unsigned v) {
    unsigned u = (v & 0x80000000u) ? (v ^ 0x80000000u) : ~v;
    return __uint_as_float(u);
}

__global__ void seg_init_sum(float* __restrict__ ssum)
{
    int idx = blockIdx.x * blockDim.x + threadIdx.x;
    if (idx < 1024 * 512) ssum[idx] = 0.f;
}

__global__ void seg_init_max(unsigned* __restrict__ smax)
{
    int idx = blockIdx.x * blockDim.x + threadIdx.x;
    if (idx < 1024 * 512) smax[idx] = 0x007FFFFFu;  // ford(-inf)
}

__global__ void seg_reduce(const float* __restrict__ H,
                           const int* __restrict__ mem,
                           float* __restrict__ ssum, unsigned* __restrict__ smax)
{
    int idx = blockIdx.x * blockDim.x + threadIdx.x;
    if (idx >= 65536 * 512) return;
    int i = idx >> 9;
    int c = idx & 511;
    float v = H[idx];
    int m = mem[i];
    atomicAdd(&ssum[m * 512 + c], v);
    atomicMax(&smax[m * 512 + c], ford(v));
}

__global__ void fp_tanh(const float* __restrict__ ssum,
                        const unsigned* __restrict__ smax,
                        float* __restrict__ fp)
{
    int idx = blockIdx.x * blockDim.x + threadIdx.x;
    if (idx >= 1024 * 1024) return;
    int b = idx >> 10;
    int c = idx & 1023;
    float v = (c < 512) ? ssum[b * 512 + c] : funord(smax[b * 512 + (c - 512)]);
    fp[idx] = tanhf(v);
}

// ======================= head =======================
__global__ void head_kernel(const float* __restrict__ fp,
                            const float* __restrict__ W,
                            const float* __restrict__ b,
                            float* __restrict__ soft,
                            float* __restrict__ logits)
{
    __shared__ float row[1024];
    __shared__ float lg[24];
    int bi = blockIdx.x;
    for (int c = threadIdx.x; c < 1024; c += blockDim.x)
        row[c] = fp[bi * 1024 + c];
    __syncthreads();
    if (threadIdx.x < 24) {
        int t = threadIdx.x;
        float acc = b[t];
        for (int k = 0; k < 1024; k++)
            acc += row[k] * W[k * 24 + t];
        lg[t] = acc;
        logits[bi * 24 + t] = acc;
    }
    __syncthreads();
    if (threadIdx.x < 12) {
        int t = threadIdx.x;
        float l0 = lg[2 * t], l1 = lg[2 * t + 1];
        float m  = fmaxf(l0, l1);
        float e0 = expf(l0 - m), e1 = expf(l1 - m);
        float inv = 1.f / (e0 + e1);
        soft[bi * 24 + 2 * t]     = e0 * inv;
        soft[bi * 24 + 2 * t + 1] = e1 * inv;
    }
}

// ======================= launch =======================
extern "C" void kernel_launch(void* const* d_in, const int* in_sizes, int n_in,
                              void* d_out, int out_size)
{
    const float* atom       = (const float*)d_in[0];
    const int*   membership = (const int*)  d_in[2];
    const int*   a1 = (const int*)d_in[4];
    const int*   a2 = (const int*)d_in[5];
    const int*   a3 = (const int*)d_in[6];
    const int*   a4 = (const int*)d_in[7];
    const float* gc1W = (const float*)d_in[8];
    const float* gc1b = (const float*)d_in[9];
    const float* gc2W = (const float*)d_in[10];
    const float* gc2b = (const float*)d_in[11];
    const float* bn1  = (const float*)d_in[12];
    const float* bn2  = (const float*)d_in[13];
    const float* bn3  = (const float*)d_in[14];
    const float* dW   = (const float*)d_in[15];
    const float* db   = (const float*)d_in[16];
    const float* hW   = (const float*)d_in[17];
    const float* hb   = (const float*)d_in[18];

    float *rel, *bufA, *bufB, *h, *ssum;
    unsigned* smax;
    cudaGetSymbolAddress((void**)&rel,  g_rel);
    cudaGetSymbolAddress((void**)&bufA, g_bufA);
    cudaGetSymbolAddress((void**)&bufB, g_bufB);
    cudaGetSymbolAddress((void**)&h,    g_h);
    cudaGetSymbolAddress((void**)&ssum, g_sum);
    cudaGetSymbolAddress((void**)&smax, g_maxu);

    float* out        = (float*)d_out;
    float* out_soft   = out;
    float* out_logits = out + 1024 * 24;
    float* out_fp     = out + 2 * 1024 * 24;

    // launch #1: merged layer-1 gather
    {
        long tot = 61440L * 75;
        gather_all<<<(int)((tot + 255) / 256), 256>>>(atom, 75, a1, a2, a3, a4, rel);
    }
    // launches #2, #3: independent fillers (segment-pool init)
    seg_init_sum<<<(1024 * 512 + 255) / 256, 256>>>(ssum);
    seg_init_max<<<(1024 * 512 + 255) / 256, 256>>>(smax);

    // launch #4: conv1 GEMM (profiled slot)
    conv_gemm_mma<<<dim3(2, 512), 256>>>(atom, 75, 3, rel, gc1W, gc1b, bn1, bufA);

    // launch #5: merged pool 1 (includes degree-0 copy)
    pool_all<<<(int)((65536L * 256 + 255) / 256), 256>>>(bufA, a1, a2, a3, a4, bufB);

    // launch #6: merged layer-2 gather
    {
        long tot = 61440L * 256;
        gather_all<<<(int)((tot + 255) / 256), 256>>>(bufB, 256, a1, a2, a3, a4, rel);
    }

    // launch #7: conv2 GEMM
    conv_gemm_mma<<<dim3(2, 512), 256>>>(bufB, 256, 8, rel, gc2W, gc2b, bn2, bufA);

    // launch #8: merged pool 2
    pool_all<<<(int)((65536L * 256 + 255) / 256), 256>>>(bufA, a1, a2, a3, a4, bufB);

    // launch #9: dense + BN3
    dense_gemm_mma<<<dim3(4, 512), 256>>>(bufB, dW, db, bn3, h);

    // launch #10: atomic segment sum/max
    seg_reduce<<<(65536 * 512 + 255) / 256, 256>>>(h, membership, ssum, smax);

    // launch #11: fp = tanh([sum | max])
    fp_tanh<<<(1024 * 1024 + 255) / 256, 256>>>(ssum, smax, out_fp);

    // launch #12: head + softmax
    head_kernel<<<1024, 256>>>(out_fp, hW, hb, out_soft, out_logits);
}

// round 8
// speedup vs baseline: 2.6104x; 1.6542x over previous
#include <cuda_runtime.h>
#include <cuda_fp16.h>
#include <stdint.h>

#define BN_EPS 1e-3f
#define BK 32
// fp16 SMEM tiles: A 128 rows x 32k, row stride 40 halves (80B, conflict-free for ldmatrix)
//                  B 32 k x 128 n, row stride 136 halves (272B)
#define A_ROW_H 40
#define B_ROW_H 136
#define A_STAGE_B (128 * A_ROW_H * 2)   // 10240
#define B_STAGE_B (32 * B_ROW_H * 2)    // 8704
#define STAGE_B (A_STAGE_B + B_STAGE_B) // 18944
#define NSTAGE 3
#define SMEM_DYN (NSTAGE * STAGE_B)     // 56832

// Segment layout: atom rows d0 [0,4096) d1 [4096,16384) d2 [16384,36864) d3 [36864,57344) d4 [57344,65536)
// rel rows: d1 [0,12288) d2 [12288,32768) d3 [32768,53248) d4 [53248,61440)

// -------- scratch (static device globals) --------
__device__ __half   g_atomh[65536 * 96];      // atom padded 75->96
__device__ __half   g_relh [61440 * 256];     // layer1 uses stride 96 region, layer2 stride 256
__device__ __half   g_bufAh[65536 * 256];
__device__ __half   g_bufBh[65536 * 256];
__device__ __half   g_w1h  [9 * 96 * 256];    // K padded 75->96 (zeros)
__device__ __half   g_w2h  [9 * 256 * 256];
__device__ __half   g_wdh  [256 * 512];
__device__ float    g_h    [65536 * 512];
__device__ float    g_sum  [1024 * 512];
__device__ unsigned g_maxu [1024 * 512];

// ======================= asm helpers =======================
__device__ __forceinline__ uint32_t smem_u32(const void* p) {
    uint32_t a;
    asm("{ .reg .u64 t; cvta.to.shared.u64 t, %1; cvt.u32.u64 %0, t; }" : "=r"(a) : "l"(p));
    return a;
}
__device__ __forceinline__ uint32_t pkf16(float lo, float hi) {
    uint32_t r; asm("cvt.rn.f16x2.f32 %0, %1, %2;" : "=r"(r) : "f"(hi), "f"(lo));
    return r;
}
__device__ __forceinline__ void cp16(uint32_t dst, const void* src) {
    asm volatile("cp.async.cg.shared.global [%0], [%1], 16;" :: "r"(dst), "l"(src));
}
#define CP_COMMIT() asm volatile("cp.async.commit_group;" ::: "memory")
#define CP_WAIT1()  asm volatile("cp.async.wait_group 1;" ::: "memory")

__device__ __forceinline__ void ldsm_x4(uint32_t& r0, uint32_t& r1, uint32_t& r2, uint32_t& r3,
                                        uint32_t addr) {
    asm volatile("ldmatrix.sync.aligned.m8n8.x4.shared.b16 {%0,%1,%2,%3}, [%4];"
        : "=r"(r0), "=r"(r1), "=r"(r2), "=r"(r3) : "r"(addr));
}
__device__ __forceinline__ void ldsm_x2t(uint32_t& r0, uint32_t& r1, uint32_t addr) {
    asm volatile("ldmatrix.sync.aligned.m8n8.x2.trans.shared.b16 {%0,%1}, [%2];"
        : "=r"(r0), "=r"(r1) : "r"(addr));
}
__device__ __forceinline__ void mma16(float* d, const uint32_t* a, const uint32_t* b) {
    asm volatile("mma.sync.aligned.m16n8k16.row.col.f32.f16.f16.f32 "
        "{%0,%1,%2,%3}, {%4,%5,%6,%7}, {%8,%9}, {%0,%1,%2,%3};"
        : "+f"(d[0]), "+f"(d[1]), "+f"(d[2]), "+f"(d[3])
        : "r"(a[0]), "r"(a[1]), "r"(a[2]), "r"(a[3]), "r"(b[0]), "r"(b[1]));
}

// issue one chunk's cp.async copies into a stage (4 x 16B per thread)
__device__ __forceinline__ void issue_chunk(
    uint32_t sa, uint32_t sb,
    const __half* __restrict__ A, int lda,
    const __half* __restrict__ B, int ldb, int col0, int kt, int tid)
{
#pragma unroll
    for (int h = 0; h < 2; h++) {
        int id = tid + h * 256;                 // 512 x 16B units for A
        int row = id >> 2, u = id & 3;
        cp16(sa + (row * A_ROW_H + u * 8) * 2, A + (long)row * lda + kt + u * 8);
    }
#pragma unroll
    for (int h = 0; h < 2; h++) {
        int id = tid + h * 256;                 // 512 x 16B units for B
        int row = id >> 4, u = id & 15;
        cp16(sb + (row * B_ROW_H + u * 8) * 2, B + (long)(kt + row) * ldb + col0 + u * 8);
    }
}

// compute on one resident stage: 2 k16-steps, warp tile 64x32
__device__ __forceinline__ void compute_stage(
    uint32_t sa, uint32_t sb, float acc[16][4], int wm, int wn, int lane)
{
    const int arow = lane & 15, asel = (lane >> 4) * 8;
#pragma unroll
    for (int ks = 0; ks < 2; ks++) {
        uint32_t a[4][4];
#pragma unroll
        for (int mt = 0; mt < 4; mt++) {
            int m0 = wm * 64 + mt * 16;
            ldsm_x4(a[mt][0], a[mt][1], a[mt][2], a[mt][3],
                    sa + ((m0 + arow) * A_ROW_H + ks * 16 + asel) * 2);
        }
        uint32_t b[4][2];
        int krow = ks * 16 + (lane & 15);
#pragma unroll
        for (int nt = 0; nt < 4; nt++) {
            int n0 = wn * 32 + nt * 8;
            ldsm_x2t(b[nt][0], b[nt][1], sb + (krow * B_ROW_H + n0) * 2);
        }
#pragma unroll
        for (int mt = 0; mt < 4; mt++)
#pragma unroll
            for (int nt = 0; nt < 4; nt++)
                mma16(acc[mt * 4 + nt], a[mt], b[nt]);
    }
}

// ======================= conv GEMM (fp16, cp.async pipeline) =======================
__global__ void __launch_bounds__(256, 2)
conv_gemm_h(const __half* __restrict__ X, int lda, int KCH,
            const __half* __restrict__ REL,
            const __half* __restrict__ Wh,   // (9, lda, 256) K-padded
            const float* __restrict__ bz,    // (9, 256)
            const float* __restrict__ bnp,   // (4, 256)
            __half* __restrict__ Y)          // (65536, 256) fp16
{
    extern __shared__ char dyn[];
    const uint32_t sa0 = smem_u32(dyn);
    __shared__ float s_sc[128], s_sh[128], s_bi[128];

    const int tid = threadIdx.x;
    const int lane = tid & 31, wid = tid >> 5;
    const int gid = lane >> 2, tig = lane & 3;
    const int wm = wid & 1, wn = wid >> 1;
    const int row0 = blockIdx.y * 128;
    const int col0 = blockIdx.x * 128;
    const int d = (row0 < 4096) ? 0 : (row0 < 16384) ? 1 : (row0 < 36864) ? 2
                : (row0 < 57344) ? 3 : 4;

    if (tid < 128) {
        int c = col0 + tid;
        float bias = (d == 0) ? bz[8 * 256 + c]
                              : bz[(2 * d - 2) * 256 + c] + bz[(2 * d - 1) * 256 + c];
        float gg = bnp[c], be = bnp[256 + c], mu = bnp[512 + c], va = bnp[768 + c];
        float sc = gg * rsqrtf(va + BN_EPS);
        s_sc[tid] = sc; s_sh[tid] = be - mu * sc; s_bi[tid] = bias;
    }

    const long wsz = (long)lda * 256;
    const __half* A0 = X + (long)row0 * lda;
    const __half* W0 = Wh + ((d == 0) ? 8 : (2 * d - 1)) * wsz;
    const __half* A1 = (d > 0) ? REL + (long)(row0 - 4096) * lda : A0;
    const __half* W1 = (d > 0) ? Wh + (2 * d - 2) * wsz : W0;
    const int T = ((d > 0) ? 2 : 1) * KCH;

    float acc[16][4];
#pragma unroll
    for (int i = 0; i < 16; i++)
        acc[i][0] = acc[i][1] = acc[i][2] = acc[i][3] = 0.f;

    // prologue: chunks 0,1
#pragma unroll
    for (int c = 0; c < 2; c++) {
        int pass = (c >= KCH), kc = c - pass * KCH;
        uint32_t sbase = sa0 + (c % NSTAGE) * STAGE_B;
        issue_chunk(sbase, sbase + A_STAGE_B,
                    pass ? A1 : A0, lda, pass ? W1 : W0, 256, col0, kc * BK, tid);
        CP_COMMIT();
    }

    for (int c = 0; c < T; c++) {
        CP_WAIT1();
        __syncthreads();
        int n = c + 2;
        if (n < T) {
            int pass = (n >= KCH), kc = n - pass * KCH;
            uint32_t sbase = sa0 + (n % NSTAGE) * STAGE_B;
            issue_chunk(sbase, sbase + A_STAGE_B,
                        pass ? A1 : A0, lda, pass ? W1 : W0, 256, col0, kc * BK, tid);
        }
        CP_COMMIT();
        uint32_t sbase = sa0 + (c % NSTAGE) * STAGE_B;
        compute_stage(sbase, sbase + A_STAGE_B, acc, wm, wn, lane);
    }
    __syncthreads();

#pragma unroll
    for (int mt = 0; mt < 4; mt++) {
#pragma unroll
        for (int nt = 0; nt < 4; nt++) {
            int cl = wn * 32 + nt * 8 + tig * 2;
            int r = row0 + wm * 64 + mt * 16 + gid;
            float* a4 = acc[mt * 4 + nt];
            float sc0 = s_sc[cl], sc1 = s_sc[cl + 1];
            float sh0 = s_sh[cl], sh1 = s_sh[cl + 1];
            float bi0 = s_bi[cl], bi1 = s_bi[cl + 1];
            float x0 = fmaxf(a4[0] + bi0, 0.f) * sc0 + sh0;
            float x1 = fmaxf(a4[1] + bi1, 0.f) * sc1 + sh1;
            *reinterpret_cast<uint32_t*>(&Y[(long)r * 256 + col0 + cl]) = pkf16(x0, x1);
            x0 = fmaxf(a4[2] + bi0, 0.f) * sc0 + sh0;
            x1 = fmaxf(a4[3] + bi1, 0.f) * sc1 + sh1;
            *reinterpret_cast<uint32_t*>(&Y[(long)(r + 8) * 256 + col0 + cl]) = pkf16(x0, x1);
        }
    }
}

// ======================= dense GEMM (fp16, cp.async pipeline) =======================
__global__ void __launch_bounds__(256, 2)
dense_gemm_h(const __half* __restrict__ X,     // (65536, 256)
             const __half* __restrict__ Wh,    // (256, 512)
             const float* __restrict__ bz,     // (512,)
             const float* __restrict__ bnp,    // (4, 512)
             float* __restrict__ Y)            // (65536, 512) fp32
{
    extern __shared__ char dyn[];
    const uint32_t sa0 = smem_u32(dyn);
    __shared__ float s_sc[128], s_sh[128], s_bi[128];

    const int tid = threadIdx.x;
    const int lane = tid & 31, wid = tid >> 5;
    const int gid = lane >> 2, tig = lane & 3;
    const int wm = wid & 1, wn = wid >> 1;
    const int row0 = blockIdx.y * 128;
    const int col0 = blockIdx.x * 128;
    const int T = 8;

    if (tid < 128) {
        int c = col0 + tid;
        float gg = bnp[c], be = bnp[512 + c], mu = bnp[1024 + c], va = bnp[1536 + c];
        float sc = gg * rsqrtf(va + BN_EPS);
        s_sc[tid] = sc; s_sh[tid] = be - mu * sc; s_bi[tid] = bz[c];
    }

    const __half* A = X + (long)row0 * 256;
    float acc[16][4];
#pragma unroll
    for (int i = 0; i < 16; i++)
        acc[i][0] = acc[i][1] = acc[i][2] = acc[i][3] = 0.f;

#pragma unroll
    for (int c = 0; c < 2; c++) {
        uint32_t sbase = sa0 + c * STAGE_B;
        issue_chunk(sbase, sbase + A_STAGE_B, A, 256, Wh, 512, col0, c * BK, tid);
        CP_COMMIT();
    }
    for (int c = 0; c < T; c++) {
        CP_WAIT1();
        __syncthreads();
        int n = c + 2;
        if (n < T) {
            uint32_t sbase = sa0 + (n % NSTAGE) * STAGE_B;
            issue_chunk(sbase, sbase + A_STAGE_B, A, 256, Wh, 512, col0, n * BK, tid);
        }
        CP_COMMIT();
        uint32_t sbase = sa0 + (c % NSTAGE) * STAGE_B;
        compute_stage(sbase, sbase + A_STAGE_B, acc, wm, wn, lane);
    }
    __syncthreads();

#pragma unroll
    for (int mt = 0; mt < 4; mt++) {
#pragma unroll
        for (int nt = 0; nt < 4; nt++) {
            int cl = wn * 32 + nt * 8 + tig * 2;
            int r = row0 + wm * 64 + mt * 16 + gid;
            float* a4 = acc[mt * 4 + nt];
            float sc0 = s_sc[cl], sc1 = s_sc[cl + 1];
            float sh0 = s_sh[cl], sh1 = s_sh[cl + 1];
            float bi0 = s_bi[cl], bi1 = s_bi[cl + 1];
            float2 v;
            v.x = fmaxf(a4[0] + bi0, 0.f) * sc0 + sh0;
            v.y = fmaxf(a4[1] + bi1, 0.f) * sc1 + sh1;
            *reinterpret_cast<float2*>(&Y[(long)r * 512 + col0 + cl]) = v;
            v.x = fmaxf(a4[2] + bi0, 0.f) * sc0 + sh0;
            v.y = fmaxf(a4[3] + bi1, 0.f) * sc1 + sh1;
            *reinterpret_cast<float2*>(&Y[(long)(r + 8) * 512 + col0 + cl]) = v;
        }
    }
}

// ======================= converts =======================
__global__ void atom_to_h(const float* __restrict__ X, __half* __restrict__ O)
{
    long idx = (long)blockIdx.x * blockDim.x + threadIdx.x;
    if (idx >= 65536L * 96) return;
    int row = (int)(idx / 96), k = (int)(idx - (long)row * 96);
    O[idx] = (k < 75) ? __float2half(X[(long)row * 75 + k]) : __half(0.f);
}
__global__ void w1_to_h(const float* __restrict__ W, __half* __restrict__ O)
{
    long idx = (long)blockIdx.x * blockDim.x + threadIdx.x;
    if (idx >= 9L * 96 * 256) return;
    int n = (int)(idx & 255);
    long t = idx >> 8;
    int k = (int)(t % 96), gg = (int)(t / 96);
    O[idx] = (k < 75) ? __float2half(W[((long)gg * 75 + k) * 256 + n]) : __half(0.f);
}
__global__ void f_to_h(const float* __restrict__ W, __half* __restrict__ O, long n)
{
    long idx = (long)blockIdx.x * blockDim.x + threadIdx.x;
    if (idx < n) O[idx] = __float2half(W[idx]);
}

// ======================= gather / pool (fp16) =======================
// sums neighbor rows (half2 granularity); ld2 = row stride in half2 units
__global__ void gather_all_h(const __half2* __restrict__ X, int ld2,
                             const int* __restrict__ a1, const int* __restrict__ a2,
                             const int* __restrict__ a3, const int* __restrict__ a4,
                             __half2* __restrict__ out)
{
    long idx = (long)blockIdx.x * blockDim.x + threadIdx.x;
    long tot = 61440L * ld2;
    if (idx >= tot) return;
    int i = (int)(idx / ld2);
    int c = (int)(idx - (long)i * ld2);
    const int* adj; int d, li;
    if (i < 12288)      { adj = a1; d = 1; li = i; }
    else if (i < 32768) { adj = a2; d = 2; li = i - 12288; }
    else if (i < 53248) { adj = a3; d = 3; li = i - 32768; }
    else                { adj = a4; d = 4; li = i - 53248; }
    float2 s = make_float2(0.f, 0.f);
    for (int j = 0; j < d; j++) {
        float2 v = __half22float2(X[(long)adj[li * d + j] * ld2 + c]);
        s.x += v.x; s.y += v.y;
    }
    out[(long)i * ld2 + c] = __floats2half2_rn(s.x, s.y);
}

__global__ void pool_all_h(const __half2* __restrict__ X,
                           const int* __restrict__ a1, const int* __restrict__ a2,
                           const int* __restrict__ a3, const int* __restrict__ a4,
                           __half2* __restrict__ out)
{
    long idx = (long)blockIdx.x * blockDim.x + threadIdx.x;
    if (idx >= 65536L * 128) return;
    int row = (int)(idx >> 7);
    int c = (int)(idx & 127);
    __half2 m = X[idx];
    if (row >= 4096) {
        const int* adj; int d, li;
        if (row < 16384)      { adj = a1; d = 1; li = row - 4096; }
        else if (row < 36864) { adj = a2; d = 2; li = row - 16384; }
        else if (row < 57344) { adj = a3; d = 3; li = row - 36864; }
        else                  { adj = a4; d = 4; li = row - 57344; }
        for (int j = 0; j < d; j++)
            m = __hmax2(m, X[(long)adj[li * d + j] * 128 + c]);
    }
    out[idx] = m;
}

// ======================= segment reduce (atomic, proven) =======================
__device__ __forceinline__ unsigned ford(float f) {
    unsigned u = __float_as_uint(f);
    return u ^ (unsigned)(((int)u >> 31) | 0x80000000);
}
__device__ __forceinline__ float funord(unsigned v) {
    unsigned u = (v & 0x80000000u) ? (v ^ 0x80000000u) : ~v;
    return __uint_as_float(u);
}

__global__ void seg_init_sum(float* __restrict__ ssum)
{
    int idx = blockIdx.x * blockDim.x + threadIdx.x;
    if (idx < 1024 * 512) ssum[idx] = 0.f;
}
__global__ void seg_init_max(unsigned* __restrict__ smax)
{
    int idx = blockIdx.x * blockDim.x + threadIdx.x;
    if (idx < 1024 * 512) smax[idx] = 0x007FFFFFu;
}
__global__ void seg_reduce(const float* __restrict__ H,
                           const int* __restrict__ mem,
                           float* __restrict__ ssum, unsigned* __restrict__ smax)
{
    int idx = blockIdx.x * blockDim.x + threadIdx.x;
    if (idx >= 65536 * 512) return;
    int i = idx >> 9;
    int c = idx & 511;
    float v = H[idx];
    int m = mem[i];
    atomicAdd(&ssum[m * 512 + c], v);
    atomicMax(&smax[m * 512 + c], ford(v));
}
__global__ void fp_tanh(const float* __restrict__ ssum,
                        const unsigned* __restrict__ smax,
                        float* __restrict__ fp)
{
    int idx = blockIdx.x * blockDim.x + threadIdx.x;
    if (idx >= 1024 * 1024) return;
    int b = idx >> 10;
    int c = idx & 1023;
    float v = (c < 512) ? ssum[b * 512 + c] : funord(smax[b * 512 + (c - 512)]);
    fp[idx] = tanhf(v);
}

// ======================= head =======================
__global__ void head_kernel(const float* __restrict__ fp,
                            const float* __restrict__ W,
                            const float* __restrict__ b,
                            float* __restrict__ soft,
                            float* __restrict__ logits)
{
    __shared__ float row[1024];
    __shared__ float lg[24];
    int bi = blockIdx.x;
    for (int c = threadIdx.x; c < 1024; c += blockDim.x)
        row[c] = fp[bi * 1024 + c];
    __syncthreads();
    if (threadIdx.x < 24) {
        int t = threadIdx.x;
        float acc = b[t];
        for (int k = 0; k < 1024; k++)
            acc += row[k] * W[k * 24 + t];
        lg[t] = acc;
        logits[bi * 24 + t] = acc;
    }
    __syncthreads();
    if (threadIdx.x < 12) {
        int t = threadIdx.x;
        float l0 = lg[2 * t], l1 = lg[2 * t + 1];
        float m  = fmaxf(l0, l1);
        float e0 = expf(l0 - m), e1 = expf(l1 - m);
        float inv = 1.f / (e0 + e1);
        soft[bi * 24 + 2 * t]     = e0 * inv;
        soft[bi * 24 + 2 * t + 1] = e1 * inv;
    }
}

// ======================= launch =======================
extern "C" void kernel_launch(void* const* d_in, const int* in_sizes, int n_in,
                              void* d_out, int out_size)
{
    const float* atom       = (const float*)d_in[0];
    const int*   membership = (const int*)  d_in[2];
    const int*   a1 = (const int*)d_in[4];
    const int*   a2 = (const int*)d_in[5];
    const int*   a3 = (const int*)d_in[6];
    const int*   a4 = (const int*)d_in[7];
    const float* gc1W = (const float*)d_in[8];
    const float* gc1b = (const float*)d_in[9];
    const float* gc2W = (const float*)d_in[10];
    const float* gc2b = (const float*)d_in[11];
    const float* bn1  = (const float*)d_in[12];
    const float* bn2  = (const float*)d_in[13];
    const float* bn3  = (const float*)d_in[14];
    const float* dW   = (const float*)d_in[15];
    const float* db   = (const float*)d_in[16];
    const float* hW   = (const float*)d_in[17];
    const float* hb   = (const float*)d_in[18];

    __half *atomh, *relh, *bufAh, *bufBh, *w1h, *w2h, *wdh;
    float *h, *ssum; unsigned* smax;
    cudaGetSymbolAddress((void**)&atomh, g_atomh);
    cudaGetSymbolAddress((void**)&relh,  g_relh);
    cudaGetSymbolAddress((void**)&bufAh, g_bufAh);
    cudaGetSymbolAddress((void**)&bufBh, g_bufBh);
    cudaGetSymbolAddress((void**)&w1h,   g_w1h);
    cudaGetSymbolAddress((void**)&w2h,   g_w2h);
    cudaGetSymbolAddress((void**)&wdh,   g_wdh);
    cudaGetSymbolAddress((void**)&h,     g_h);
    cudaGetSymbolAddress((void**)&ssum,  g_sum);
    cudaGetSymbolAddress((void**)&smax,  g_maxu);

    cudaFuncSetAttribute(conv_gemm_h,  cudaFuncAttributeMaxDynamicSharedMemorySize, SMEM_DYN);
    cudaFuncSetAttribute(dense_gemm_h, cudaFuncAttributeMaxDynamicSharedMemorySize, SMEM_DYN);

    float* out        = (float*)d_out;
    float* out_soft   = out;
    float* out_logits = out + 1024 * 24;
    float* out_fp     = out + 2 * 1024 * 24;

    // converts (once per launch)
    atom_to_h<<<(int)((65536L * 96 + 255) / 256), 256>>>(atom, atomh);
    w1_to_h<<<(int)((9L * 96 * 256 + 255) / 256), 256>>>(gc1W, w1h);
    f_to_h<<<(int)((9L * 256 * 256 + 255) / 256), 256>>>(gc2W, w2h, 9L * 256 * 256);
    f_to_h<<<(int)((256L * 512 + 255) / 256), 256>>>(dW, wdh, 256L * 512);
    seg_init_sum<<<(1024 * 512 + 255) / 256, 256>>>(ssum);
    seg_init_max<<<(1024 * 512 + 255) / 256, 256>>>(smax);

    // layer 1 (padded K=96)
    gather_all_h<<<(int)((61440L * 48 + 255) / 256), 256>>>(
        (const __half2*)atomh, 48, a1, a2, a3, a4, (__half2*)relh);
    conv_gemm_h<<<dim3(2, 512), 256, SMEM_DYN>>>(atomh, 96, 3, relh, w1h, gc1b, bn1, bufAh);
    pool_all_h<<<(int)((65536L * 128 + 255) / 256), 256>>>(
        (const __half2*)bufAh, a1, a2, a3, a4, (__half2*)bufBh);

    // layer 2 (K=256)
    gather_all_h<<<(int)((61440L * 128 + 255) / 256), 256>>>(
        (const __half2*)bufBh, 128, a1, a2, a3, a4, (__half2*)relh);
    conv_gemm_h<<<dim3(2, 512), 256, SMEM_DYN>>>(bufBh, 256, 8, relh, w2h, gc2b, bn2, bufAh);
    pool_all_h<<<(int)((65536L * 128 + 255) / 256), 256>>>(
        (const __half2*)bufAh, a1, a2, a3, a4, (__half2*)bufBh);

    // dense + BN3 -> fp32 h
    dense_gemm_h<<<dim3(4, 512), 256, SMEM_DYN>>>(bufBh, wdh, db, bn3, h);

    // segment sum/max + fp + head
    seg_reduce<<<(65536 * 512 + 255) / 256, 256>>>(h, membership, ssum, smax);
    fp_tanh<<<(1024 * 1024 + 255) / 256, 256>>>(ssum, smax, out_fp);
    head_kernel<<<1024, 256>>>(out_fp, hW, hb, out_soft, out_logits);
}

// round 9
// speedup vs baseline: 2.9137x; 1.1162x over previous
#include <cuda_runtime.h>
#include <cuda_fp16.h>
#include <stdint.h>

#define BN_EPS 1e-3f
#define BK 32
#define A_ROW_H 40
#define B_ROW_H 136
#define A_STAGE_B (128 * A_ROW_H * 2)   // 10240
#define B_STAGE_B (32 * B_ROW_H * 2)    // 8704
#define STAGE_B (A_STAGE_B + B_STAGE_B) // 18944
#define NSTAGE 3
#define SMEM_DYN (NSTAGE * STAGE_B)     // 56832

// Segment layout: atom rows d0 [0,4096) d1 [4096,16384) d2 [16384,36864) d3 [36864,57344) d4 [57344,65536)
// rel rows: d1 [0,12288) d2 [12288,32768) d3 [32768,53248) d4 [53248,61440)

// -------- scratch (static device globals) --------
__device__ __half   g_atomh[65536 * 96];
__device__ __half   g_relh [61440 * 256];
__device__ __half   g_bufAh[65536 * 256];
__device__ __half   g_bufBh[65536 * 256];
__device__ __half   g_w1h  [9 * 96 * 256];
__device__ __half   g_w2h  [9 * 256 * 256];
__device__ __half   g_wdh  [256 * 512];
__device__ float    g_sum  [1024 * 512];
__device__ unsigned g_maxu [1024 * 512];

// ======================= asm helpers =======================
__device__ __forceinline__ uint32_t smem_u32(const void* p) {
    uint32_t a;
    asm("{ .reg .u64 t; cvta.to.shared.u64 t, %1; cvt.u32.u64 %0, t; }" : "=r"(a) : "l"(p));
    return a;
}
__device__ __forceinline__ uint32_t pkf16(float lo, float hi) {
    uint32_t r; asm("cvt.rn.f16x2.f32 %0, %1, %2;" : "=r"(r) : "f"(hi), "f"(lo));
    return r;
}
__device__ __forceinline__ void cp16(uint32_t dst, const void* src) {
    asm volatile("cp.async.cg.shared.global [%0], [%1], 16;" :: "r"(dst), "l"(src));
}
#define CP_COMMIT() asm volatile("cp.async.commit_group;" ::: "memory")
#define CP_WAIT1()  asm volatile("cp.async.wait_group 1;" ::: "memory")

__device__ __forceinline__ void ldsm_x4(uint32_t& r0, uint32_t& r1, uint32_t& r2, uint32_t& r3,
                                        uint32_t addr) {
    asm volatile("ldmatrix.sync.aligned.m8n8.x4.shared.b16 {%0,%1,%2,%3}, [%4];"
        : "=r"(r0), "=r"(r1), "=r"(r2), "=r"(r3) : "r"(addr));
}
__device__ __forceinline__ void ldsm_x2t(uint32_t& r0, uint32_t& r1, uint32_t addr) {
    asm volatile("ldmatrix.sync.aligned.m8n8.x2.trans.shared.b16 {%0,%1}, [%2];"
        : "=r"(r0), "=r"(r1) : "r"(addr));
}
__device__ __forceinline__ void mma16(float* d, const uint32_t* a, const uint32_t* b) {
    asm volatile("mma.sync.aligned.m16n8k16.row.col.f32.f16.f16.f32 "
        "{%0,%1,%2,%3}, {%4,%5,%6,%7}, {%8,%9}, {%0,%1,%2,%3};"
        : "+f"(d[0]), "+f"(d[1]), "+f"(d[2]), "+f"(d[3])
        : "r"(a[0]), "r"(a[1]), "r"(a[2]), "r"(a[3]), "r"(b[0]), "r"(b[1]));
}

__device__ __forceinline__ unsigned ford(float f) {
    unsigned u = __float_as_uint(f);
    return u ^ (unsigned)(((int)u >> 31) | 0x80000000);
}
__device__ __forceinline__ float funord(unsigned v) {
    unsigned u = (v & 0x80000000u) ? (v ^ 0x80000000u) : ~v;
    return __uint_as_float(u);
}

// issue one chunk's cp.async copies into a stage (4 x 16B per thread)
__device__ __forceinline__ void issue_chunk(
    uint32_t sa, uint32_t sb,
    const __half* __restrict__ A, int lda,
    const __half* __restrict__ B, int ldb, int col0, int kt, int tid)
{
#pragma unroll
    for (int h = 0; h < 2; h++) {
        int id = tid + h * 256;
        int row = id >> 2, u = id & 3;
        cp16(sa + (row * A_ROW_H + u * 8) * 2, A + (long)row * lda + kt + u * 8);
    }
#pragma unroll
    for (int h = 0; h < 2; h++) {
        int id = tid + h * 256;
        int row = id >> 4, u = id & 15;
        cp16(sb + (row * B_ROW_H + u * 8) * 2, B + (long)(kt + row) * ldb + col0 + u * 8);
    }
}

// compute on one resident stage: 2 k16-steps, warp tile 64x32
__device__ __forceinline__ void compute_stage(
    uint32_t sa, uint32_t sb, float acc[16][4], int wm, int wn, int lane)
{
    const int arow = lane & 15, asel = (lane >> 4) * 8;
#pragma unroll
    for (int ks = 0; ks < 2; ks++) {
        uint32_t a[4][4];
#pragma unroll
        for (int mt = 0; mt < 4; mt++) {
            int m0 = wm * 64 + mt * 16;
            ldsm_x4(a[mt][0], a[mt][1], a[mt][2], a[mt][3],
                    sa + ((m0 + arow) * A_ROW_H + ks * 16 + asel) * 2);
        }
        uint32_t b[4][2];
        int krow = ks * 16 + (lane & 15);
#pragma unroll
        for (int nt = 0; nt < 4; nt++) {
            int n0 = wn * 32 + nt * 8;
            ldsm_x2t(b[nt][0], b[nt][1], sb + (krow * B_ROW_H + n0) * 2);
        }
#pragma unroll
        for (int mt = 0; mt < 4; mt++)
#pragma unroll
            for (int nt = 0; nt < 4; nt++)
                mma16(acc[mt * 4 + nt], a[mt], b[nt]);
    }
}

// ======================= conv GEMM (fp16, cp.async pipeline) =======================
__global__ void __launch_bounds__(256, 2)
conv_gemm_h(const __half* __restrict__ X, int lda, int KCH,
            const __half* __restrict__ REL,
            const __half* __restrict__ Wh,
            const float* __restrict__ bz,
            const float* __restrict__ bnp,
            __half* __restrict__ Y)
{
    extern __shared__ char dyn[];
    const uint32_t sa0 = smem_u32(dyn);
    __shared__ float s_sc[128], s_sh[128], s_bi[128];

    const int tid = threadIdx.x;
    const int lane = tid & 31, wid = tid >> 5;
    const int gid = lane >> 2, tig = lane & 3;
    const int wm = wid & 1, wn = wid >> 1;
    const int row0 = blockIdx.y * 128;
    const int col0 = blockIdx.x * 128;
    const int d = (row0 < 4096) ? 0 : (row0 < 16384) ? 1 : (row0 < 36864) ? 2
                : (row0 < 57344) ? 3 : 4;

    if (tid < 128) {
        int c = col0 + tid;
        float bias = (d == 0) ? bz[8 * 256 + c]
                              : bz[(2 * d - 2) * 256 + c] + bz[(2 * d - 1) * 256 + c];
        float gg = bnp[c], be = bnp[256 + c], mu = bnp[512 + c], va = bnp[768 + c];
        float sc = gg * rsqrtf(va + BN_EPS);
        s_sc[tid] = sc; s_sh[tid] = be - mu * sc; s_bi[tid] = bias;
    }

    const long wsz = (long)lda * 256;
    const __half* A0 = X + (long)row0 * lda;
    const __half* W0 = Wh + ((d == 0) ? 8 : (2 * d - 1)) * wsz;
    const __half* A1 = (d > 0) ? REL + (long)(row0 - 4096) * lda : A0;
    const __half* W1 = (d > 0) ? Wh + (2 * d - 2) * wsz : W0;
    const int T = ((d > 0) ? 2 : 1) * KCH;

    float acc[16][4];
#pragma unroll
    for (int i = 0; i < 16; i++)
        acc[i][0] = acc[i][1] = acc[i][2] = acc[i][3] = 0.f;

#pragma unroll
    for (int c = 0; c < 2; c++) {
        int pass = (c >= KCH), kc = c - pass * KCH;
        uint32_t sbase = sa0 + (c % NSTAGE) * STAGE_B;
        issue_chunk(sbase, sbase + A_STAGE_B,
                    pass ? A1 : A0, lda, pass ? W1 : W0, 256, col0, kc * BK, tid);
        CP_COMMIT();
    }

    for (int c = 0; c < T; c++) {
        CP_WAIT1();
        __syncthreads();
        int n = c + 2;
        if (n < T) {
            int pass = (n >= KCH), kc = n - pass * KCH;
            uint32_t sbase = sa0 + (n % NSTAGE) * STAGE_B;
            issue_chunk(sbase, sbase + A_STAGE_B,
                        pass ? A1 : A0, lda, pass ? W1 : W0, 256, col0, kc * BK, tid);
        }
        CP_COMMIT();
        uint32_t sbase = sa0 + (c % NSTAGE) * STAGE_B;
        compute_stage(sbase, sbase + A_STAGE_B, acc, wm, wn, lane);
    }
    __syncthreads();

#pragma unroll
    for (int mt = 0; mt < 4; mt++) {
#pragma unroll
        for (int nt = 0; nt < 4; nt++) {
            int cl = wn * 32 + nt * 8 + tig * 2;
            int r = row0 + wm * 64 + mt * 16 + gid;
            float* a4 = acc[mt * 4 + nt];
            float sc0 = s_sc[cl], sc1 = s_sc[cl + 1];
            float sh0 = s_sh[cl], sh1 = s_sh[cl + 1];
            float bi0 = s_bi[cl], bi1 = s_bi[cl + 1];
            float x0 = fmaxf(a4[0] + bi0, 0.f) * sc0 + sh0;
            float x1 = fmaxf(a4[1] + bi1, 0.f) * sc1 + sh1;
            *reinterpret_cast<uint32_t*>(&Y[(long)r * 256 + col0 + cl]) = pkf16(x0, x1);
            x0 = fmaxf(a4[2] + bi0, 0.f) * sc0 + sh0;
            x1 = fmaxf(a4[3] + bi1, 0.f) * sc1 + sh1;
            *reinterpret_cast<uint32_t*>(&Y[(long)(r + 8) * 256 + col0 + cl]) = pkf16(x0, x1);
        }
    }
}

// ======================= dense GEMM + fused segment reduce =======================
__global__ void __launch_bounds__(256, 2)
dense_gemm_h(const __half* __restrict__ X,     // (65536, 256)
             const __half* __restrict__ Wh,    // (256, 512)
             const float* __restrict__ bz,
             const float* __restrict__ bnp,
             const int* __restrict__ mem,      // (65536,)
             float* __restrict__ ssum,         // (1024, 512)
             unsigned* __restrict__ smax)      // (1024, 512)
{
    extern __shared__ char dyn[];
    const uint32_t sa0 = smem_u32(dyn);
    __shared__ float s_sc[128], s_sh[128], s_bi[128];

    const int tid = threadIdx.x;
    const int lane = tid & 31, wid = tid >> 5;
    const int gid = lane >> 2, tig = lane & 3;
    const int wm = wid & 1, wn = wid >> 1;
    const int row0 = blockIdx.y * 128;
    const int col0 = blockIdx.x * 128;
    const int T = 8;

    if (tid < 128) {
        int c = col0 + tid;
        float gg = bnp[c], be = bnp[512 + c], mu = bnp[1024 + c], va = bnp[1536 + c];
        float sc = gg * rsqrtf(va + BN_EPS);
        s_sc[tid] = sc; s_sh[tid] = be - mu * sc; s_bi[tid] = bz[c];
    }

    const __half* A = X + (long)row0 * 256;
    float acc[16][4];
#pragma unroll
    for (int i = 0; i < 16; i++)
        acc[i][0] = acc[i][1] = acc[i][2] = acc[i][3] = 0.f;

#pragma unroll
    for (int c = 0; c < 2; c++) {
        uint32_t sbase = sa0 + c * STAGE_B;
        issue_chunk(sbase, sbase + A_STAGE_B, A, 256, Wh, 512, col0, c * BK, tid);
        CP_COMMIT();
    }
    for (int c = 0; c < T; c++) {
        CP_WAIT1();
        __syncthreads();
        int n = c + 2;
        if (n < T) {
            uint32_t sbase = sa0 + (n % NSTAGE) * STAGE_B;
            issue_chunk(sbase, sbase + A_STAGE_B, A, 256, Wh, 512, col0, n * BK, tid);
        }
        CP_COMMIT();
        uint32_t sbase = sa0 + (c % NSTAGE) * STAGE_B;
        compute_stage(sbase, sbase + A_STAGE_B, acc, wm, wn, lane);
    }
    __syncthreads();

    // fused epilogue: BN3(relu(.)) then atomic segment sum/max — h never hits DRAM
#pragma unroll
    for (int mt = 0; mt < 4; mt++) {
        int r = row0 + wm * 64 + mt * 16 + gid;
        int m0 = mem[r] * 512, m1 = mem[r + 8] * 512;
#pragma unroll
        for (int nt = 0; nt < 4; nt++) {
            int cl = wn * 32 + nt * 8 + tig * 2;
            int gc = col0 + cl;
            float* a4 = acc[mt * 4 + nt];
            float sc0 = s_sc[cl], sc1 = s_sc[cl + 1];
            float sh0 = s_sh[cl], sh1 = s_sh[cl + 1];
            float bi0 = s_bi[cl], bi1 = s_bi[cl + 1];
            float x00 = fmaxf(a4[0] + bi0, 0.f) * sc0 + sh0;
            float x01 = fmaxf(a4[1] + bi1, 0.f) * sc1 + sh1;
            float x10 = fmaxf(a4[2] + bi0, 0.f) * sc0 + sh0;
            float x11 = fmaxf(a4[3] + bi1, 0.f) * sc1 + sh1;
            atomicAdd(&ssum[m0 + gc],     x00);
            atomicAdd(&ssum[m0 + gc + 1], x01);
            atomicAdd(&ssum[m1 + gc],     x10);
            atomicAdd(&ssum[m1 + gc + 1], x11);
            atomicMax(&smax[m0 + gc],     ford(x00));
            atomicMax(&smax[m0 + gc + 1], ford(x01));
            atomicMax(&smax[m1 + gc],     ford(x10));
            atomicMax(&smax[m1 + gc + 1], ford(x11));
        }
    }
}

// ======================= merged converts (one launch) =======================
// ranges: [0, 65536*96) atom pad | [.., +9*96*256) w1 pad | [.., +9*256*256) w2 | [.., +256*512) wd
#define CV_ATOM (65536L * 96)
#define CV_W1   (9L * 96 * 256)
#define CV_W2   (9L * 256 * 256)
#define CV_WD   (256L * 512)
__global__ void convert_all(const float* __restrict__ atomf,
                            const float* __restrict__ w1f,
                            const float* __restrict__ w2f,
                            const float* __restrict__ wdf,
                            __half* __restrict__ atomh, __half* __restrict__ w1h,
                            __half* __restrict__ w2h,   __half* __restrict__ wdh)
{
    long idx = (long)blockIdx.x * blockDim.x + threadIdx.x;
    if (idx < CV_ATOM) {
        int row = (int)(idx / 96), k = (int)(idx - (long)row * 96);
        atomh[idx] = (k < 75) ? __float2half(atomf[(long)row * 75 + k]) : __half(0.f);
        return;
    }
    idx -= CV_ATOM;
    if (idx < CV_W1) {
        int n = (int)(idx & 255);
        long t = idx >> 8;
        int k = (int)(t % 96), gg = (int)(t / 96);
        w1h[idx] = (k < 75) ? __float2half(w1f[((long)gg * 75 + k) * 256 + n]) : __half(0.f);
        return;
    }
    idx -= CV_W1;
    if (idx < CV_W2) { w2h[idx] = __float2half(w2f[idx]); return; }
    idx -= CV_W2;
    if (idx < CV_WD) { wdh[idx] = __float2half(wdf[idx]); }
}

// ======================= gather / pool (fp16) =======================
__global__ void gather_all_h(const __half2* __restrict__ X, int ld2,
                             const int* __restrict__ a1, const int* __restrict__ a2,
                             const int* __restrict__ a3, const int* __restrict__ a4,
                             __half2* __restrict__ out)
{
    long idx = (long)blockIdx.x * blockDim.x + threadIdx.x;
    long tot = 61440L * ld2;
    if (idx >= tot) return;
    int i = (int)(idx / ld2);
    int c = (int)(idx - (long)i * ld2);
    const int* adj; int d, li;
    if (i < 12288)      { adj = a1; d = 1; li = i; }
    else if (i < 32768) { adj = a2; d = 2; li = i - 12288; }
    else if (i < 53248) { adj = a3; d = 3; li = i - 32768; }
    else                { adj = a4; d = 4; li = i - 53248; }
    float2 s = make_float2(0.f, 0.f);
    for (int j = 0; j < d; j++) {
        float2 v = __half22float2(X[(long)adj[li * d + j] * ld2 + c]);
        s.x += v.x; s.y += v.y;
    }
    out[(long)i * ld2 + c] = __floats2half2_rn(s.x, s.y);
}

__global__ void pool_all_h(const __half2* __restrict__ X,
                           const int* __restrict__ a1, const int* __restrict__ a2,
                           const int* __restrict__ a3, const int* __restrict__ a4,
                           __half2* __restrict__ out)
{
    long idx = (long)blockIdx.x * blockDim.x + threadIdx.x;
    if (idx >= 65536L * 128) return;
    int row = (int)(idx >> 7);
    int c = (int)(idx & 127);
    __half2 m = X[idx];
    if (row >= 4096) {
        const int* adj; int d, li;
        if (row < 16384)      { adj = a1; d = 1; li = row - 4096; }
        else if (row < 36864) { adj = a2; d = 2; li = row - 16384; }
        else if (row < 57344) { adj = a3; d = 3; li = row - 36864; }
        else                  { adj = a4; d = 4; li = row - 57344; }
        for (int j = 0; j < d; j++)
            m = __hmax2(m, X[(long)adj[li * d + j] * 128 + c]);
    }
    out[idx] = m;
}

// ======================= seg init / fp / head =======================
__global__ void seg_init_sum(float* __restrict__ ssum)
{
    int idx = blockIdx.x * blockDim.x + threadIdx.x;
    if (idx < 1024 * 512) ssum[idx] = 0.f;
}
__global__ void seg_init_max(unsigned* __restrict__ smax)
{
    int idx = blockIdx.x * blockDim.x + threadIdx.x;
    if (idx < 1024 * 512) smax[idx] = 0x007FFFFFu;
}
__global__ void fp_tanh(const float* __restrict__ ssum,
                        const unsigned* __restrict__ smax,
                        float* __restrict__ fp)
{
    int idx = blockIdx.x * blockDim.x + threadIdx.x;
    if (idx >= 1024 * 1024) return;
    int b = idx >> 10;
    int c = idx & 1023;
    float v = (c < 512) ? ssum[b * 512 + c] : funord(smax[b * 512 + (c - 512)]);
    fp[idx] = tanhf(v);
}

__global__ void head_kernel(const float* __restrict__ fp,
                            const float* __restrict__ W,
                            const float* __restrict__ b,
                            float* __restrict__ soft,
                            float* __restrict__ logits)
{
    __shared__ float row[1024];
    __shared__ float lg[24];
    int bi = blockIdx.x;
    for (int c = threadIdx.x; c < 1024; c += blockDim.x)
        row[c] = fp[bi * 1024 + c];
    __syncthreads();
    if (threadIdx.x < 24) {
        int t = threadIdx.x;
        float acc = b[t];
        for (int k = 0; k < 1024; k++)
            acc += row[k] * W[k * 24 + t];
        lg[t] = acc;
        logits[bi * 24 + t] = acc;
    }
    __syncthreads();
    if (threadIdx.x < 12) {
        int t = threadIdx.x;
        float l0 = lg[2 * t], l1 = lg[2 * t + 1];
        float m  = fmaxf(l0, l1);
        float e0 = expf(l0 - m), e1 = expf(l1 - m);
        float inv = 1.f / (e0 + e1);
        soft[bi * 24 + 2 * t]     = e0 * inv;
        soft[bi * 24 + 2 * t + 1] = e1 * inv;
    }
}

// ======================= launch =======================
extern "C" void kernel_launch(void* const* d_in, const int* in_sizes, int n_in,
                              void* d_out, int out_size)
{
    const float* atom       = (const float*)d_in[0];
    const int*   membership = (const int*)  d_in[2];
    const int*   a1 = (const int*)d_in[4];
    const int*   a2 = (const int*)d_in[5];
    const int*   a3 = (const int*)d_in[6];
    const int*   a4 = (const int*)d_in[7];
    const float* gc1W = (const float*)d_in[8];
    const float* gc1b = (const float*)d_in[9];
    const float* gc2W = (const float*)d_in[10];
    const float* gc2b = (const float*)d_in[11];
    const float* bn1  = (const float*)d_in[12];
    const float* bn2  = (const float*)d_in[13];
    const float* bn3  = (const float*)d_in[14];
    const float* dW   = (const float*)d_in[15];
    const float* db   = (const float*)d_in[16];
    const float* hW   = (const float*)d_in[17];
    const float* hb   = (const float*)d_in[18];

    __half *atomh, *relh, *bufAh, *bufBh, *w1h, *w2h, *wdh;
    float *ssum; unsigned* smax;
    cudaGetSymbolAddress((void**)&atomh, g_atomh);
    cudaGetSymbolAddress((void**)&relh,  g_relh);
    cudaGetSymbolAddress((void**)&bufAh, g_bufAh);
    cudaGetSymbolAddress((void**)&bufBh, g_bufBh);
    cudaGetSymbolAddress((void**)&w1h,   g_w1h);
    cudaGetSymbolAddress((void**)&w2h,   g_w2h);
    cudaGetSymbolAddress((void**)&wdh,   g_wdh);
    cudaGetSymbolAddress((void**)&ssum,  g_sum);
    cudaGetSymbolAddress((void**)&smax,  g_maxu);

    cudaFuncSetAttribute(conv_gemm_h,  cudaFuncAttributeMaxDynamicSharedMemorySize, SMEM_DYN);
    cudaFuncSetAttribute(dense_gemm_h, cudaFuncAttributeMaxDynamicSharedMemorySize, SMEM_DYN);

    float* out        = (float*)d_out;
    float* out_soft   = out;
    float* out_logits = out + 1024 * 24;
    float* out_fp     = out + 2 * 1024 * 24;

    // converts + seg init
    {
        long tot = CV_ATOM + CV_W1 + CV_W2 + CV_WD;
        convert_all<<<(int)((tot + 255) / 256), 256>>>(
            atom, gc1W, gc2W, dW, atomh, w1h, w2h, wdh);
    }
    seg_init_sum<<<(1024 * 512 + 255) / 256, 256>>>(ssum);
    seg_init_max<<<(1024 * 512 + 255) / 256, 256>>>(smax);

    // layer 1 (padded K=96)
    gather_all_h<<<(int)((61440L * 48 + 255) / 256), 256>>>(
        (const __half2*)atomh, 48, a1, a2, a3, a4, (__half2*)relh);
    conv_gemm_h<<<dim3(2, 512), 256, SMEM_DYN>>>(atomh, 96, 3, relh, w1h, gc1b, bn1, bufAh);
    pool_all_h<<<(int)((65536L * 128 + 255) / 256), 256>>>(
        (const __half2*)bufAh, a1, a2, a3, a4, (__half2*)bufBh);

    // layer 2 (K=256)
    gather_all_h<<<(int)((61440L * 128 + 255) / 256), 256>>>(
        (const __half2*)bufBh, 128, a1, a2, a3, a4, (__half2*)relh);
    conv_gemm_h<<<dim3(2, 512), 256, SMEM_DYN>>>(bufBh, 256, 8, relh, w2h, gc2b, bn2, bufAh);
    pool_all_h<<<(int)((65536L * 128 + 255) / 256), 256>>>(
        (const __half2*)bufAh, a1, a2, a3, a4, (__half2*)bufBh);

    // dense + BN3 + fused segment sum/max (no h materialization)
    dense_gemm_h<<<dim3(4, 512), 256, SMEM_DYN>>>(bufBh, wdh, db, bn3,
                                                  membership, ssum, smax);

    // fp = tanh([sum | max]) ; head
    fp_tanh<<<(1024 * 1024 + 255) / 256, 256>>>(ssum, smax, out_fp);
    head_kernel<<<1024, 256>>>(out_fp, hW, hb, out_soft, out_logits);
}

// round 10
// speedup vs baseline: 3.2489x; 1.1150x over previous
#include <cuda_runtime.h>
#include <cuda_fp16.h>
#include <stdint.h>

#define BN_EPS 1e-3f
#define BK 32
#define A_ROW_H 40
#define B_ROW_H 264
#define A_STAGE_B (128 * A_ROW_H * 2)   // 10240
#define B_STAGE_B (32 * B_ROW_H * 2)    // 16896
#define STAGE_B (A_STAGE_B + B_STAGE_B) // 27136
#define NSTAGE 3
#define SMEM_DYN (NSTAGE * STAGE_B)     // 81408

// Segment layout: atom rows d0 [0,4096) d1 [4096,16384) d2 [16384,36864) d3 [36864,57344) d4 [57344,65536)
// rel rows: d1 [0,12288) d2 [12288,32768) d3 [32768,53248) d4 [53248,61440)

// -------- scratch (static device globals) --------
__device__ __half   g_atomh[65536 * 96];
__device__ __half   g_relh [61440 * 256];
__device__ __half   g_bufAh[65536 * 256];
__device__ __half   g_bufBh[65536 * 256];
__device__ __half   g_w1h  [9 * 96 * 256];
__device__ __half   g_w2h  [9 * 256 * 256];
__device__ __half   g_wdh  [256 * 512];
__device__ float    g_sum  [1024 * 512];
__device__ unsigned g_maxu [1024 * 512];

// ======================= asm helpers =======================
__device__ __forceinline__ uint32_t smem_u32(const void* p) {
    uint32_t a;
    asm("{ .reg .u64 t; cvta.to.shared.u64 t, %1; cvt.u32.u64 %0, t; }" : "=r"(a) : "l"(p));
    return a;
}
__device__ __forceinline__ uint32_t pkf16(float lo, float hi) {
    uint32_t r; asm("cvt.rn.f16x2.f32 %0, %1, %2;" : "=r"(r) : "f"(hi), "f"(lo));
    return r;
}
__device__ __forceinline__ void cp16(uint32_t dst, const void* src) {
    asm volatile("cp.async.cg.shared.global [%0], [%1], 16;" :: "r"(dst), "l"(src));
}
#define CP_COMMIT() asm volatile("cp.async.commit_group;" ::: "memory")
#define CP_WAIT1()  asm volatile("cp.async.wait_group 1;" ::: "memory")

__device__ __forceinline__ void ldsm_x4(uint32_t& r0, uint32_t& r1, uint32_t& r2, uint32_t& r3,
                                        uint32_t addr) {
    asm volatile("ldmatrix.sync.aligned.m8n8.x4.shared.b16 {%0,%1,%2,%3}, [%4];"
        : "=r"(r0), "=r"(r1), "=r"(r2), "=r"(r3) : "r"(addr));
}
__device__ __forceinline__ void ldsm_x2t(uint32_t& r0, uint32_t& r1, uint32_t addr) {
    asm volatile("ldmatrix.sync.aligned.m8n8.x2.trans.shared.b16 {%0,%1}, [%2];"
        : "=r"(r0), "=r"(r1) : "r"(addr));
}
__device__ __forceinline__ void mma16(float* d, const uint32_t* a, const uint32_t* b) {
    asm volatile("mma.sync.aligned.m16n8k16.row.col.f32.f16.f16.f32 "
        "{%0,%1,%2,%3}, {%4,%5,%6,%7}, {%8,%9}, {%0,%1,%2,%3};"
        : "+f"(d[0]), "+f"(d[1]), "+f"(d[2]), "+f"(d[3])
        : "r"(a[0]), "r"(a[1]), "r"(a[2]), "r"(a[3]), "r"(b[0]), "r"(b[1]));
}

__device__ __forceinline__ unsigned ford(float f) {
    unsigned u = __float_as_uint(f);
    return u ^ (unsigned)(((int)u >> 31) | 0x80000000);
}
__device__ __forceinline__ float funord(unsigned v) {
    unsigned u = (v & 0x80000000u) ? (v ^ 0x80000000u) : ~v;
    return __uint_as_float(u);
}

// issue one chunk's cp.async copies (512 threads): A 1x16B, B 2x16B per thread
__device__ __forceinline__ void issue_chunk(
    uint32_t sa, uint32_t sb,
    const __half* __restrict__ A, int lda,
    const __half* __restrict__ B, int ldb, int col0, int kt, int tid)
{
    {
        int row = tid >> 2, u = tid & 3;
        cp16(sa + (row * A_ROW_H + u * 8) * 2, A + (long)row * lda + kt + u * 8);
    }
#pragma unroll
    for (int h = 0; h < 2; h++) {
        int id = tid + h * 512;
        int row = id >> 5, u = id & 31;
        cp16(sb + (row * B_ROW_H + u * 8) * 2, B + (long)(kt + row) * ldb + col0 + u * 8);
    }
}

// compute on one resident stage: 2 k16-steps, warp tile 64x32, 16 warps (2m x 8n)
__device__ __forceinline__ void compute_stage(
    uint32_t sa, uint32_t sb, float acc[16][4], int wm, int wn, int lane)
{
    const int arow = lane & 15, asel = (lane >> 4) * 8;
#pragma unroll
    for (int ks = 0; ks < 2; ks++) {
        uint32_t a[4][4];
#pragma unroll
        for (int mt = 0; mt < 4; mt++) {
            int m0 = wm * 64 + mt * 16;
            ldsm_x4(a[mt][0], a[mt][1], a[mt][2], a[mt][3],
                    sa + ((m0 + arow) * A_ROW_H + ks * 16 + asel) * 2);
        }
        uint32_t b[4][2];
        int krow = ks * 16 + (lane & 15);
#pragma unroll
        for (int nt = 0; nt < 4; nt++) {
            int n0 = wn * 32 + nt * 8;
            ldsm_x2t(b[nt][0], b[nt][1], sb + (krow * B_ROW_H + n0) * 2);
        }
#pragma unroll
        for (int mt = 0; mt < 4; mt++)
#pragma unroll
            for (int nt = 0; nt < 4; nt++)
                mma16(acc[mt * 4 + nt], a[mt], b[nt]);
    }
}

// ======================= conv GEMM (fp16, 128x256 CTA tile) =======================
__global__ void __launch_bounds__(512, 1)
conv_gemm_h(const __half* __restrict__ X, int lda, int KCH,
            const __half* __restrict__ REL,
            const __half* __restrict__ Wh,
            const float* __restrict__ bz,
            const float* __restrict__ bnp,
            __half* __restrict__ Y)
{
    extern __shared__ char dyn[];
    const uint32_t sa0 = smem_u32(dyn);
    __shared__ float s_sc[256], s_sh[256], s_bi[256];

    const int tid = threadIdx.x;
    const int lane = tid & 31, wid = tid >> 5;
    const int gid = lane >> 2, tig = lane & 3;
    const int wm = wid & 1, wn = wid >> 1;
    const int row0 = blockIdx.x * 128;
    const int d = (row0 < 4096) ? 0 : (row0 < 16384) ? 1 : (row0 < 36864) ? 2
                : (row0 < 57344) ? 3 : 4;

    if (tid < 256) {
        int c = tid;
        float bias = (d == 0) ? bz[8 * 256 + c]
                              : bz[(2 * d - 2) * 256 + c] + bz[(2 * d - 1) * 256 + c];
        float gg = bnp[c], be = bnp[256 + c], mu = bnp[512 + c], va = bnp[768 + c];
        float sc = gg * rsqrtf(va + BN_EPS);
        s_sc[c] = sc; s_sh[c] = be - mu * sc; s_bi[c] = bias;
    }

    const long wsz = (long)lda * 256;
    const __half* A0 = X + (long)row0 * lda;
    const __half* W0 = Wh + ((d == 0) ? 8 : (2 * d - 1)) * wsz;
    const __half* A1 = (d > 0) ? REL + (long)(row0 - 4096) * lda : A0;
    const __half* W1 = (d > 0) ? Wh + (2 * d - 2) * wsz : W0;
    const int T = ((d > 0) ? 2 : 1) * KCH;

    float acc[16][4];
#pragma unroll
    for (int i = 0; i < 16; i++)
        acc[i][0] = acc[i][1] = acc[i][2] = acc[i][3] = 0.f;

#pragma unroll
    for (int c = 0; c < 2; c++) {
        int pass = (c >= KCH), kc = c - pass * KCH;
        uint32_t sbase = sa0 + (c % NSTAGE) * STAGE_B;
        issue_chunk(sbase, sbase + A_STAGE_B,
                    pass ? A1 : A0, lda, pass ? W1 : W0, 256, 0, kc * BK, tid);
        CP_COMMIT();
    }

    for (int c = 0; c < T; c++) {
        CP_WAIT1();
        __syncthreads();
        int n = c + 2;
        if (n < T) {
            int pass = (n >= KCH), kc = n - pass * KCH;
            uint32_t sbase = sa0 + (n % NSTAGE) * STAGE_B;
            issue_chunk(sbase, sbase + A_STAGE_B,
                        pass ? A1 : A0, lda, pass ? W1 : W0, 256, 0, kc * BK, tid);
        }
        CP_COMMIT();
        uint32_t sbase = sa0 + (c % NSTAGE) * STAGE_B;
        compute_stage(sbase, sbase + A_STAGE_B, acc, wm, wn, lane);
    }
    __syncthreads();

#pragma unroll
    for (int mt = 0; mt < 4; mt++) {
#pragma unroll
        for (int nt = 0; nt < 4; nt++) {
            int cl = wn * 32 + nt * 8 + tig * 2;
            int r = row0 + wm * 64 + mt * 16 + gid;
            float* a4 = acc[mt * 4 + nt];
            float sc0 = s_sc[cl], sc1 = s_sc[cl + 1];
            float sh0 = s_sh[cl], sh1 = s_sh[cl + 1];
            float bi0 = s_bi[cl], bi1 = s_bi[cl + 1];
            float x0 = fmaxf(a4[0] + bi0, 0.f) * sc0 + sh0;
            float x1 = fmaxf(a4[1] + bi1, 0.f) * sc1 + sh1;
            *reinterpret_cast<uint32_t*>(&Y[(long)r * 256 + cl]) = pkf16(x0, x1);
            x0 = fmaxf(a4[2] + bi0, 0.f) * sc0 + sh0;
            x1 = fmaxf(a4[3] + bi1, 0.f) * sc1 + sh1;
            *reinterpret_cast<uint32_t*>(&Y[(long)(r + 8) * 256 + cl]) = pkf16(x0, x1);
        }
    }
}

// ======================= dense GEMM + fused segment reduce =======================
__global__ void __launch_bounds__(512, 1)
dense_gemm_h(const __half* __restrict__ X,     // (65536, 256)
             const __half* __restrict__ Wh,    // (256, 512)
             const float* __restrict__ bz,
             const float* __restrict__ bnp,
             const int* __restrict__ mem,
             float* __restrict__ ssum,
             unsigned* __restrict__ smax)
{
    extern __shared__ char dyn[];
    const uint32_t sa0 = smem_u32(dyn);
    __shared__ float s_sc[256], s_sh[256], s_bi[256];

    const int tid = threadIdx.x;
    const int lane = tid & 31, wid = tid >> 5;
    const int gid = lane >> 2, tig = lane & 3;
    const int wm = wid & 1, wn = wid >> 1;
    const int row0 = blockIdx.y * 128;
    const int col0 = blockIdx.x * 256;
    const int T = 8;

    if (tid < 256) {
        int c = col0 + tid;
        float gg = bnp[c], be = bnp[512 + c], mu = bnp[1024 + c], va = bnp[1536 + c];
        float sc = gg * rsqrtf(va + BN_EPS);
        s_sc[tid] = sc; s_sh[tid] = be - mu * sc; s_bi[tid] = bz[c];
    }

    const __half* A = X + (long)row0 * 256;
    float acc[16][4];
#pragma unroll
    for (int i = 0; i < 16; i++)
        acc[i][0] = acc[i][1] = acc[i][2] = acc[i][3] = 0.f;

#pragma unroll
    for (int c = 0; c < 2; c++) {
        uint32_t sbase = sa0 + c * STAGE_B;
        issue_chunk(sbase, sbase + A_STAGE_B, A, 256, Wh, 512, col0, c * BK, tid);
        CP_COMMIT();
    }
    for (int c = 0; c < T; c++) {
        CP_WAIT1();
        __syncthreads();
        int n = c + 2;
        if (n < T) {
            uint32_t sbase = sa0 + (n % NSTAGE) * STAGE_B;
            issue_chunk(sbase, sbase + A_STAGE_B, A, 256, Wh, 512, col0, n * BK, tid);
        }
        CP_COMMIT();
        uint32_t sbase = sa0 + (c % NSTAGE) * STAGE_B;
        compute_stage(sbase, sbase + A_STAGE_B, acc, wm, wn, lane);
    }
    __syncthreads();

    // fused epilogue: BN3(relu(.)) + atomic segment sum/max
#pragma unroll
    for (int mt = 0; mt < 4; mt++) {
        int r = row0 + wm * 64 + mt * 16 + gid;
        int m0 = mem[r] * 512, m1 = mem[r + 8] * 512;
#pragma unroll
        for (int nt = 0; nt < 4; nt++) {
            int cl = wn * 32 + nt * 8 + tig * 2;
            int gc = col0 + cl;
            float* a4 = acc[mt * 4 + nt];
            float sc0 = s_sc[cl], sc1 = s_sc[cl + 1];
            float sh0 = s_sh[cl], sh1 = s_sh[cl + 1];
            float bi0 = s_bi[cl], bi1 = s_bi[cl + 1];
            float x00 = fmaxf(a4[0] + bi0, 0.f) * sc0 + sh0;
            float x01 = fmaxf(a4[1] + bi1, 0.f) * sc1 + sh1;
            float x10 = fmaxf(a4[2] + bi0, 0.f) * sc0 + sh0;
            float x11 = fmaxf(a4[3] + bi1, 0.f) * sc1 + sh1;
            atomicAdd(&ssum[m0 + gc],     x00);
            atomicAdd(&ssum[m0 + gc + 1], x01);
            atomicAdd(&ssum[m1 + gc],     x10);
            atomicAdd(&ssum[m1 + gc + 1], x11);
            atomicMax(&smax[m0 + gc],     ford(x00));
            atomicMax(&smax[m0 + gc + 1], ford(x01));
            atomicMax(&smax[m1 + gc],     ford(x10));
            atomicMax(&smax[m1 + gc + 1], ford(x11));
        }
    }
}

// ======================= merged converts =======================
#define CV_ATOM (65536L * 96)
#define CV_W1   (9L * 96 * 256)
#define CV_W2   (9L * 256 * 256)
#define CV_WD   (256L * 512)
__global__ void convert_all(const float* __restrict__ atomf,
                            const float* __restrict__ w1f,
                            const float* __restrict__ w2f,
                            const float* __restrict__ wdf,
                            __half* __restrict__ atomh, __half* __restrict__ w1h,
                            __half* __restrict__ w2h,   __half* __restrict__ wdh)
{
    long idx = (long)blockIdx.x * blockDim.x + threadIdx.x;
    if (idx < CV_ATOM) {
        int row = (int)(idx / 96), k = (int)(idx - (long)row * 96);
        atomh[idx] = (k < 75) ? __float2half(atomf[(long)row * 75 + k]) : __half(0.f);
        return;
    }
    idx -= CV_ATOM;
    if (idx < CV_W1) {
        int n = (int)(idx & 255);
        long t = idx >> 8;
        int k = (int)(t % 96), gg = (int)(t / 96);
        w1h[idx] = (k < 75) ? __float2half(w1f[((long)gg * 75 + k) * 256 + n]) : __half(0.f);
        return;
    }
    idx -= CV_W1;
    if (idx < CV_W2) { w2h[idx] = __float2half(w2f[idx]); return; }
    idx -= CV_W2;
    if (idx < CV_WD) { wdh[idx] = __float2half(wdf[idx]); }
}

// ======================= gather / pool (uint4 = 8 halves per thread) =========
__device__ __forceinline__ void acc8(float2 s[4], uint4 v) {
    s[0].x += __low2float(*(__half2*)&v.x);  s[0].y += __high2float(*(__half2*)&v.x);
    s[1].x += __low2float(*(__half2*)&v.y);  s[1].y += __high2float(*(__half2*)&v.y);
    s[2].x += __low2float(*(__half2*)&v.z);  s[2].y += __high2float(*(__half2*)&v.z);
    s[3].x += __low2float(*(__half2*)&v.w);  s[3].y += __high2float(*(__half2*)&v.w);
}

__global__ void gather_all_h(const __half* __restrict__ X, int ld, int chunks,
                             const int* __restrict__ a1, const int* __restrict__ a2,
                             const int* __restrict__ a3, const int* __restrict__ a4,
                             __half* __restrict__ out)
{
    long idx = (long)blockIdx.x * blockDim.x + threadIdx.x;
    long tot = 61440L * chunks;
    if (idx >= tot) return;
    int i = (int)(idx / chunks);
    int c = (int)(idx - (long)i * chunks) * 8;
    const int* adj; int d, li;
    if (i < 12288)      { adj = a1; d = 1; li = i; }
    else if (i < 32768) { adj = a2; d = 2; li = i - 12288; }
    else if (i < 53248) { adj = a3; d = 3; li = i - 32768; }
    else                { adj = a4; d = 4; li = i - 53248; }
    float2 s[4];
    s[0] = s[1] = s[2] = s[3] = make_float2(0.f, 0.f);
    for (int j = 0; j < d; j++) {
        uint4 v = *reinterpret_cast<const uint4*>(X + (long)adj[li * d + j] * ld + c);
        acc8(s, v);
    }
    uint4 o;
    o.x = pkf16(s[0].x, s[0].y); o.y = pkf16(s[1].x, s[1].y);
    o.z = pkf16(s[2].x, s[2].y); o.w = pkf16(s[3].x, s[3].y);
    *reinterpret_cast<uint4*>(out + (long)i * ld + c) = o;
}

__device__ __forceinline__ void max8(uint4& m, uint4 v) {
    *(__half2*)&m.x = __hmax2(*(__half2*)&m.x, *(__half2*)&v.x);
    *(__half2*)&m.y = __hmax2(*(__half2*)&m.y, *(__half2*)&v.y);
    *(__half2*)&m.z = __hmax2(*(__half2*)&m.z, *(__half2*)&v.z);
    *(__half2*)&m.w = __hmax2(*(__half2*)&m.w, *(__half2*)&v.w);
}

__global__ void pool_all_h(const uint4* __restrict__ X,   // (65536, 32) of 8-half
                           const int* __restrict__ a1, const int* __restrict__ a2,
                           const int* __restrict__ a3, const int* __restrict__ a4,
                           uint4* __restrict__ out)
{
    long idx = (long)blockIdx.x * blockDim.x + threadIdx.x;
    if (idx >= 65536L * 32) return;
    int row = (int)(idx >> 5);
    int c = (int)(idx & 31);
    uint4 m = X[idx];
    if (row >= 4096) {
        const int* adj; int d, li;
        if (row < 16384)      { adj = a1; d = 1; li = row - 4096; }
        else if (row < 36864) { adj = a2; d = 2; li = row - 16384; }
        else if (row < 57344) { adj = a3; d = 3; li = row - 36864; }
        else                  { adj = a4; d = 4; li = row - 57344; }
        for (int j = 0; j < d; j++)
            max8(m, X[(long)adj[li * d + j] * 32 + c]);
    }
    out[idx] = m;
}

// ======================= seg init / fp / head =======================
__global__ void seg_init_sum(float* __restrict__ ssum)
{
    int idx = blockIdx.x * blockDim.x + threadIdx.x;
    if (idx < 1024 * 512) ssum[idx] = 0.f;
}
__global__ void seg_init_max(unsigned* __restrict__ smax)
{
    int idx = blockIdx.x * blockDim.x + threadIdx.x;
    if (idx < 1024 * 512) smax[idx] = 0x007FFFFFu;
}
__global__ void fp_tanh(const float* __restrict__ ssum,
                        const unsigned* __restrict__ smax,
                        float* __restrict__ fp)
{
    int idx = blockIdx.x * blockDim.x + threadIdx.x;
    if (idx >= 1024 * 1024) return;
    int b = idx >> 10;
    int c = idx & 1023;
    float v = (c < 512) ? ssum[b * 512 + c] : funord(smax[b * 512 + (c - 512)]);
    fp[idx] = tanhf(v);
}

__global__ void head_kernel(const float* __restrict__ fp,
                            const float* __restrict__ W,
                            const float* __restrict__ b,
                            float* __restrict__ soft,
                            float* __restrict__ logits)
{
    __shared__ float row[1024];
    __shared__ float lg[24];
    int bi = blockIdx.x;
    for (int c = threadIdx.x; c < 1024; c += blockDim.x)
        row[c] = fp[bi * 1024 + c];
    __syncthreads();
    if (threadIdx.x < 24) {
        int t = threadIdx.x;
        float acc = b[t];
        for (int k = 0; k < 1024; k++)
            acc += row[k] * W[k * 24 + t];
        lg[t] = acc;
        logits[bi * 24 + t] = acc;
    }
    __syncthreads();
    if (threadIdx.x < 12) {
        int t = threadIdx.x;
        float l0 = lg[2 * t], l1 = lg[2 * t + 1];
        float m  = fmaxf(l0, l1);
        float e0 = expf(l0 - m), e1 = expf(l1 - m);
        float inv = 1.f / (e0 + e1);
        soft[bi * 24 + 2 * t]     = e0 * inv;
        soft[bi * 24 + 2 * t + 1] = e1 * inv;
    }
}

// ======================= launch =======================
extern "C" void kernel_launch(void* const* d_in, const int* in_sizes, int n_in,
                              void* d_out, int out_size)
{
    const float* atom       = (const float*)d_in[0];
    const int*   membership = (const int*)  d_in[2];
    const int*   a1 = (const int*)d_in[4];
    const int*   a2 = (const int*)d_in[5];
    const int*   a3 = (const int*)d_in[6];
    const int*   a4 = (const int*)d_in[7];
    const float* gc1W = (const float*)d_in[8];
    const float* gc1b = (const float*)d_in[9];
    const float* gc2W = (const float*)d_in[10];
    const float* gc2b = (const float*)d_in[11];
    const float* bn1  = (const float*)d_in[12];
    const float* bn2  = (const float*)d_in[13];
    const float* bn3  = (const float*)d_in[14];
    const float* dW   = (const float*)d_in[15];
    const float* db   = (const float*)d_in[16];
    const float* hW   = (const float*)d_in[17];
    const float* hb   = (const float*)d_in[18];

    __half *atomh, *relh, *bufAh, *bufBh, *w1h, *w2h, *wdh;
    float *ssum; unsigned* smax;
    cudaGetSymbolAddress((void**)&atomh, g_atomh);
    cudaGetSymbolAddress((void**)&relh,  g_relh);
    cudaGetSymbolAddress((void**)&bufAh, g_bufAh);
    cudaGetSymbolAddress((void**)&bufBh, g_bufBh);
    cudaGetSymbolAddress((void**)&w1h,   g_w1h);
    cudaGetSymbolAddress((void**)&w2h,   g_w2h);
    cudaGetSymbolAddress((void**)&wdh,   g_wdh);
    cudaGetSymbolAddress((void**)&ssum,  g_sum);
    cudaGetSymbolAddress((void**)&smax,  g_maxu);

    cudaFuncSetAttribute(conv_gemm_h,  cudaFuncAttributeMaxDynamicSharedMemorySize, SMEM_DYN);
    cudaFuncSetAttribute(dense_gemm_h, cudaFuncAttributeMaxDynamicSharedMemorySize, SMEM_DYN);

    float* out        = (float*)d_out;
    float* out_soft   = out;
    float* out_logits = out + 1024 * 24;
    float* out_fp     = out + 2 * 1024 * 24;

    // converts + seg init
    {
        long tot = CV_ATOM + CV_W1 + CV_W2 + CV_WD;
        convert_all<<<(int)((tot + 255) / 256), 256>>>(
            atom, gc1W, gc2W, dW, atomh, w1h, w2h, wdh);
    }
    seg_init_sum<<<(1024 * 512 + 255) / 256, 256>>>(ssum);
    seg_init_max<<<(1024 * 512 + 255) / 256, 256>>>(smax);

    // layer 1 (padded K=96; 12 chunks of 8 halves per row)
    gather_all_h<<<(int)((61440L * 12 + 255) / 256), 256>>>(
        atomh, 96, 12, a1, a2, a3, a4, relh);
    conv_gemm_h<<<512, 512, SMEM_DYN>>>(atomh, 96, 3, relh, w1h, gc1b, bn1, bufAh);
    pool_all_h<<<(int)((65536L * 32 + 255) / 256), 256>>>(
        (const uint4*)bufAh, a1, a2, a3, a4, (uint4*)bufBh);

    // layer 2 (K=256; 32 chunks per row)
    gather_all_h<<<(int)((61440L * 32 + 255) / 256), 256>>>(
        bufBh, 256, 32, a1, a2, a3, a4, relh);
    conv_gemm_h<<<512, 512, SMEM_DYN>>>(bufBh, 256, 8, relh, w2h, gc2b, bn2, bufAh);
    pool_all_h<<<(int)((65536L * 32 + 255) / 256), 256>>>(
        (const uint4*)bufAh, a1, a2, a3, a4, (uint4*)bufBh);

    // dense + BN3 + fused segment sum/max
    dense_gemm_h<<<dim3(2, 512), 512, SMEM_DYN>>>(bufBh, wdh, db, bn3,
                                                  membership, ssum, smax);

    // fp = tanh([sum | max]) ; head
    fp_tanh<<<(1024 * 1024 + 255) / 256, 256>>>(ssum, smax, out_fp);
    head_kernel<<<1024, 256>>>(out_fp, hW, hb, out_soft, out_logits);
}

// round 11
// speedup vs baseline: 3.3649x; 1.0357x over previous
#include <cuda_runtime.h>
#include <cuda_fp16.h>
#include <stdint.h>

#define BN_EPS 1e-3f
#define NSTAGE 3

// Segment layout: atom rows d0 [0,4096) d1 [4096,16384) d2 [16384,36864) d3 [36864,57344) d4 [57344,65536)
// rel rows: d1 [0,12288) d2 [12288,32768) d3 [32768,53248) d4 [53248,61440)

// -------- scratch (static device globals) --------
__device__ __half   g_atomh[65536 * 96];
__device__ __half   g_relh [61440 * 256];
__device__ __half   g_bufAh[65536 * 256];
__device__ __half   g_bufBh[65536 * 256];
__device__ __half   g_w1h  [9 * 96 * 256];
__device__ __half   g_w2h  [9 * 256 * 256];
__device__ __half   g_wdh  [256 * 512];
__device__ float    g_sum  [1024 * 512];
__device__ unsigned g_maxu [1024 * 512];

// ======================= asm helpers =======================
__device__ __forceinline__ uint32_t smem_u32(const void* p) {
    uint32_t a;
    asm("{ .reg .u64 t; cvta.to.shared.u64 t, %1; cvt.u32.u64 %0, t; }" : "=r"(a) : "l"(p));
    return a;
}
__device__ __forceinline__ uint32_t pkf16(float lo, float hi) {
    uint32_t r; asm("cvt.rn.f16x2.f32 %0, %1, %2;" : "=r"(r) : "f"(hi), "f"(lo));
    return r;
}
__device__ __forceinline__ void cp16(uint32_t dst, const void* src) {
    asm volatile("cp.async.cg.shared.global [%0], [%1], 16;" :: "r"(dst), "l"(src));
}
#define CP_COMMIT() asm volatile("cp.async.commit_group;" ::: "memory")
#define CP_WAIT1()  asm volatile("cp.async.wait_group 1;" ::: "memory")

__device__ __forceinline__ void ldsm_x4(uint32_t& r0, uint32_t& r1, uint32_t& r2, uint32_t& r3,
                                        uint32_t addr) {
    asm volatile("ldmatrix.sync.aligned.m8n8.x4.shared.b16 {%0,%1,%2,%3}, [%4];"
        : "=r"(r0), "=r"(r1), "=r"(r2), "=r"(r3) : "r"(addr));
}
__device__ __forceinline__ void ldsm_x2t(uint32_t& r0, uint32_t& r1, uint32_t addr) {
    asm volatile("ldmatrix.sync.aligned.m8n8.x2.trans.shared.b16 {%0,%1}, [%2];"
        : "=r"(r0), "=r"(r1) : "r"(addr));
}
__device__ __forceinline__ void mma16(float* d, const uint32_t* a, const uint32_t* b) {
    asm volatile("mma.sync.aligned.m16n8k16.row.col.f32.f16.f16.f32 "
        "{%0,%1,%2,%3}, {%4,%5,%6,%7}, {%8,%9}, {%0,%1,%2,%3};"
        : "+f"(d[0]), "+f"(d[1]), "+f"(d[2]), "+f"(d[3])
        : "r"(a[0]), "r"(a[1]), "r"(a[2]), "r"(a[3]), "r"(b[0]), "r"(b[1]));
}

__device__ __forceinline__ unsigned ford(float f) {
    unsigned u = __float_as_uint(f);
    return u ^ (unsigned)(((int)u >> 31) | 0x80000000);
}
__device__ __forceinline__ float funord(unsigned v) {
    unsigned u = (v & 0x80000000u) ? (v ^ 0x80000000u) : ~v;
    return __uint_as_float(u);
}

// ======================= templated GEMM pieces =======================
// BKC = K elements per chunk (32 or 64). A tile 128 x BKC (row stride BKC+8 halves),
// B tile BKC x 256 (row stride 264 halves).
template<int BKC> struct GP {
    static constexpr int ARH  = BKC + 8;
    static constexpr int ASTG = 128 * ARH * 2;
    static constexpr int BSTG = BKC * 264 * 2;
    static constexpr int STG  = ASTG + BSTG;
    static constexpr int SMEM = NSTAGE * STG;
};

template<int BKC>
__device__ __forceinline__ void issue_chunk(
    uint32_t sa, uint32_t sb,
    const __half* __restrict__ A, int lda,
    const __half* __restrict__ B, int ldb, int col0, int kt, int tid)
{
    constexpr int AU  = BKC / 8;           // 16B units per A row
    constexpr int APT = 128 * AU / 512;    // 1 or 2 per thread
#pragma unroll
    for (int h = 0; h < APT; h++) {
        int id = tid + h * 512;
        int row = id / AU, u = id % AU;
        cp16(sa + (row * GP<BKC>::ARH + u * 8) * 2, A + (long)row * lda + kt + u * 8);
    }
    constexpr int BPT = BKC * 32 / 512;    // 2 or 4 per thread
#pragma unroll
    for (int h = 0; h < BPT; h++) {
        int id = tid + h * 512;
        int row = id >> 5, u = id & 31;
        cp16(sb + (row * 264 + u * 8) * 2, B + (long)(kt + row) * ldb + col0 + u * 8);
    }
}

template<int BKC>
__device__ __forceinline__ void compute_stage(
    uint32_t sa, uint32_t sb, float acc[16][4], int wm, int wn, int lane)
{
    const int arow = lane & 15, asel = (lane >> 4) * 8;
#pragma unroll
    for (int ks = 0; ks < BKC / 16; ks++) {
        uint32_t a[4][4];
#pragma unroll
        for (int mt = 0; mt < 4; mt++) {
            int m0 = wm * 64 + mt * 16;
            ldsm_x4(a[mt][0], a[mt][1], a[mt][2], a[mt][3],
                    sa + ((m0 + arow) * GP<BKC>::ARH + ks * 16 + asel) * 2);
        }
        uint32_t b[4][2];
        int krow = ks * 16 + (lane & 15);
#pragma unroll
        for (int nt = 0; nt < 4; nt++) {
            int n0 = wn * 32 + nt * 8;
            ldsm_x2t(b[nt][0], b[nt][1], sb + (krow * 264 + n0) * 2);
        }
#pragma unroll
        for (int mt = 0; mt < 4; mt++)
#pragma unroll
            for (int nt = 0; nt < 4; nt++)
                mma16(acc[mt * 4 + nt], a[mt], b[nt]);
    }
}

// ======================= conv GEMM (fp16, 128x256 CTA, templated BKC) ==========
template<int BKC>
__global__ void __launch_bounds__(512, 1)
conv_gemm_t(const __half* __restrict__ X, int lda, int KCH,
            const __half* __restrict__ REL,
            const __half* __restrict__ Wh,
            const float* __restrict__ bz,
            const float* __restrict__ bnp,
            __half* __restrict__ Y)
{
    extern __shared__ char dyn[];
    const uint32_t sa0 = smem_u32(dyn);
    __shared__ float s_sc[256], s_sh[256], s_bi[256];

    const int tid = threadIdx.x;
    const int lane = tid & 31, wid = tid >> 5;
    const int gid = lane >> 2, tig = lane & 3;
    const int wm = wid & 1, wn = wid >> 1;
    const int row0 = blockIdx.x * 128;
    const int d = (row0 < 4096) ? 0 : (row0 < 16384) ? 1 : (row0 < 36864) ? 2
                : (row0 < 57344) ? 3 : 4;

    if (tid < 256) {
        int c = tid;
        float bias = (d == 0) ? bz[8 * 256 + c]
                              : bz[(2 * d - 2) * 256 + c] + bz[(2 * d - 1) * 256 + c];
        float gg = bnp[c], be = bnp[256 + c], mu = bnp[512 + c], va = bnp[768 + c];
        float sc = gg * rsqrtf(va + BN_EPS);
        s_sc[c] = sc; s_sh[c] = be - mu * sc; s_bi[c] = bias;
    }

    const long wsz = (long)lda * 256;
    const __half* A0 = X + (long)row0 * lda;
    const __half* W0 = Wh + ((d == 0) ? 8 : (2 * d - 1)) * wsz;
    const __half* A1 = (d > 0) ? REL + (long)(row0 - 4096) * lda : A0;
    const __half* W1 = (d > 0) ? Wh + (2 * d - 2) * wsz : W0;
    const int T = ((d > 0) ? 2 : 1) * KCH;

    float acc[16][4];
#pragma unroll
    for (int i = 0; i < 16; i++)
        acc[i][0] = acc[i][1] = acc[i][2] = acc[i][3] = 0.f;

#pragma unroll
    for (int c = 0; c < 2; c++) {
        int pass = (c >= KCH), kc = c - pass * KCH;
        uint32_t sbase = sa0 + (c % NSTAGE) * GP<BKC>::STG;
        issue_chunk<BKC>(sbase, sbase + GP<BKC>::ASTG,
                         pass ? A1 : A0, lda, pass ? W1 : W0, 256, 0, kc * BKC, tid);
        CP_COMMIT();
    }

    for (int c = 0; c < T; c++) {
        CP_WAIT1();
        __syncthreads();
        int n = c + 2;
        if (n < T) {
            int pass = (n >= KCH), kc = n - pass * KCH;
            uint32_t sbase = sa0 + (n % NSTAGE) * GP<BKC>::STG;
            issue_chunk<BKC>(sbase, sbase + GP<BKC>::ASTG,
                             pass ? A1 : A0, lda, pass ? W1 : W0, 256, 0, kc * BKC, tid);
        }
        CP_COMMIT();
        uint32_t sbase = sa0 + (c % NSTAGE) * GP<BKC>::STG;
        compute_stage<BKC>(sbase, sbase + GP<BKC>::ASTG, acc, wm, wn, lane);
    }
    __syncthreads();

#pragma unroll
    for (int mt = 0; mt < 4; mt++) {
#pragma unroll
        for (int nt = 0; nt < 4; nt++) {
            int cl = wn * 32 + nt * 8 + tig * 2;
            int r = row0 + wm * 64 + mt * 16 + gid;
            float* a4 = acc[mt * 4 + nt];
            float sc0 = s_sc[cl], sc1 = s_sc[cl + 1];
            float sh0 = s_sh[cl], sh1 = s_sh[cl + 1];
            float bi0 = s_bi[cl], bi1 = s_bi[cl + 1];
            float x0 = fmaxf(a4[0] + bi0, 0.f) * sc0 + sh0;
            float x1 = fmaxf(a4[1] + bi1, 0.f) * sc1 + sh1;
            *reinterpret_cast<uint32_t*>(&Y[(long)r * 256 + cl]) = pkf16(x0, x1);
            x0 = fmaxf(a4[2] + bi0, 0.f) * sc0 + sh0;
            x1 = fmaxf(a4[3] + bi1, 0.f) * sc1 + sh1;
            *reinterpret_cast<uint32_t*>(&Y[(long)(r + 8) * 256 + cl]) = pkf16(x0, x1);
        }
    }
}

// ======================= dense GEMM + fused segment reduce (BKC=64) ==========
__global__ void __launch_bounds__(512, 1)
dense_gemm_h(const __half* __restrict__ X,     // (65536, 256)
             const __half* __restrict__ Wh,    // (256, 512)
             const float* __restrict__ bz,
             const float* __restrict__ bnp,
             const int* __restrict__ mem,
             float* __restrict__ ssum,
             unsigned* __restrict__ smax)
{
    constexpr int BKC = 64;
    extern __shared__ char dyn[];
    const uint32_t sa0 = smem_u32(dyn);
    __shared__ float s_sc[256], s_sh[256], s_bi[256];

    const int tid = threadIdx.x;
    const int lane = tid & 31, wid = tid >> 5;
    const int gid = lane >> 2, tig = lane & 3;
    const int wm = wid & 1, wn = wid >> 1;
    const int row0 = blockIdx.y * 128;
    const int col0 = blockIdx.x * 256;
    const int T = 4;

    if (tid < 256) {
        int c = col0 + tid;
        float gg = bnp[c], be = bnp[512 + c], mu = bnp[1024 + c], va = bnp[1536 + c];
        float sc = gg * rsqrtf(va + BN_EPS);
        s_sc[tid] = sc; s_sh[tid] = be - mu * sc; s_bi[tid] = bz[c];
    }

    const __half* A = X + (long)row0 * 256;
    float acc[16][4];
#pragma unroll
    for (int i = 0; i < 16; i++)
        acc[i][0] = acc[i][1] = acc[i][2] = acc[i][3] = 0.f;

#pragma unroll
    for (int c = 0; c < 2; c++) {
        uint32_t sbase = sa0 + c * GP<BKC>::STG;
        issue_chunk<BKC>(sbase, sbase + GP<BKC>::ASTG, A, 256, Wh, 512, col0, c * BKC, tid);
        CP_COMMIT();
    }
    for (int c = 0; c < T; c++) {
        CP_WAIT1();
        __syncthreads();
        int n = c + 2;
        if (n < T) {
            uint32_t sbase = sa0 + (n % NSTAGE) * GP<BKC>::STG;
            issue_chunk<BKC>(sbase, sbase + GP<BKC>::ASTG, A, 256, Wh, 512, col0, n * BKC, tid);
        }
        CP_COMMIT();
        uint32_t sbase = sa0 + (c % NSTAGE) * GP<BKC>::STG;
        compute_stage<BKC>(sbase, sbase + GP<BKC>::ASTG, acc, wm, wn, lane);
    }
    __syncthreads();

    // fused epilogue: BN3(relu(.)) + atomic segment sum/max
#pragma unroll
    for (int mt = 0; mt < 4; mt++) {
        int r = row0 + wm * 64 + mt * 16 + gid;
        int m0 = mem[r] * 512, m1 = mem[r + 8] * 512;
#pragma unroll
        for (int nt = 0; nt < 4; nt++) {
            int cl = wn * 32 + nt * 8 + tig * 2;
            int gc = col0 + cl;
            float* a4 = acc[mt * 4 + nt];
            float sc0 = s_sc[cl], sc1 = s_sc[cl + 1];
            float sh0 = s_sh[cl], sh1 = s_sh[cl + 1];
            float bi0 = s_bi[cl], bi1 = s_bi[cl + 1];
            float x00 = fmaxf(a4[0] + bi0, 0.f) * sc0 + sh0;
            float x01 = fmaxf(a4[1] + bi1, 0.f) * sc1 + sh1;
            float x10 = fmaxf(a4[2] + bi0, 0.f) * sc0 + sh0;
            float x11 = fmaxf(a4[3] + bi1, 0.f) * sc1 + sh1;
            atomicAdd(&ssum[m0 + gc],     x00);
            atomicAdd(&ssum[m0 + gc + 1], x01);
            atomicAdd(&ssum[m1 + gc],     x10);
            atomicAdd(&ssum[m1 + gc + 1], x11);
            atomicMax(&smax[m0 + gc],     ford(x00));
            atomicMax(&smax[m0 + gc + 1], ford(x01));
            atomicMax(&smax[m1 + gc],     ford(x10));
            atomicMax(&smax[m1 + gc + 1], ford(x11));
        }
    }
}

// ======================= merged converts =======================
#define CV_ATOM (65536L * 96)
#define CV_W1   (9L * 96 * 256)
#define CV_W2   (9L * 256 * 256)
#define CV_WD   (256L * 512)
__global__ void convert_all(const float* __restrict__ atomf,
                            const float* __restrict__ w1f,
                            const float* __restrict__ w2f,
                            const float* __restrict__ wdf,
                            __half* __restrict__ atomh, __half* __restrict__ w1h,
                            __half* __restrict__ w2h,   __half* __restrict__ wdh)
{
    long idx = (long)blockIdx.x * blockDim.x + threadIdx.x;
    if (idx < CV_ATOM) {
        int row = (int)(idx / 96), k = (int)(idx - (long)row * 96);
        atomh[idx] = (k < 75) ? __float2half(atomf[(long)row * 75 + k]) : __half(0.f);
        return;
    }
    idx -= CV_ATOM;
    if (idx < CV_W1) {
        int n = (int)(idx & 255);
        long t = idx >> 8;
        int k = (int)(t % 96), gg = (int)(t / 96);
        w1h[idx] = (k < 75) ? __float2half(w1f[((long)gg * 75 + k) * 256 + n]) : __half(0.f);
        return;
    }
    idx -= CV_W1;
    if (idx < CV_W2) { w2h[idx] = __float2half(w2f[idx]); return; }
    idx -= CV_W2;
    if (idx < CV_WD) { wdh[idx] = __float2half(wdf[idx]); }
}

// ======================= gather / pool (uint4; templated chunk count) =========
__device__ __forceinline__ void acc8(float2 s[4], uint4 v) {
    s[0].x += __low2float(*(__half2*)&v.x);  s[0].y += __high2float(*(__half2*)&v.x);
    s[1].x += __low2float(*(__half2*)&v.y);  s[1].y += __high2float(*(__half2*)&v.y);
    s[2].x += __low2float(*(__half2*)&v.z);  s[2].y += __high2float(*(__half2*)&v.z);
    s[3].x += __low2float(*(__half2*)&v.w);  s[3].y += __high2float(*(__half2*)&v.w);
}

template<int CH>
__global__ void gather_all_h(const __half* __restrict__ X,
                             const int* __restrict__ a1, const int* __restrict__ a2,
                             const int* __restrict__ a3, const int* __restrict__ a4,
                             __half* __restrict__ out)
{
    constexpr int LD = CH * 8;
    long idx = (long)blockIdx.x * blockDim.x + threadIdx.x;
    if (idx >= 61440L * CH) return;
    int i = (int)(idx / CH);
    int c = (int)(idx - (long)i * CH) * 8;
    const int* adj; int d, li;
    if (i < 12288)      { adj = a1; d = 1; li = i; }
    else if (i < 32768) { adj = a2; d = 2; li = i - 12288; }
    else if (i < 53248) { adj = a3; d = 3; li = i - 32768; }
    else                { adj = a4; d = 4; li = i - 53248; }
    float2 s[4];
    s[0] = s[1] = s[2] = s[3] = make_float2(0.f, 0.f);
    for (int j = 0; j < d; j++) {
        uint4 v = *reinterpret_cast<const uint4*>(X + (long)adj[li * d + j] * LD + c);
        acc8(s, v);
    }
    uint4 o;
    o.x = pkf16(s[0].x, s[0].y); o.y = pkf16(s[1].x, s[1].y);
    o.z = pkf16(s[2].x, s[2].y); o.w = pkf16(s[3].x, s[3].y);
    *reinterpret_cast<uint4*>(out + (long)i * LD + c) = o;
}

__device__ __forceinline__ void max8(uint4& m, uint4 v) {
    *(__half2*)&m.x = __hmax2(*(__half2*)&m.x, *(__half2*)&v.x);
    *(__half2*)&m.y = __hmax2(*(__half2*)&m.y, *(__half2*)&v.y);
    *(__half2*)&m.z = __hmax2(*(__half2*)&m.z, *(__half2*)&v.z);
    *(__half2*)&m.w = __hmax2(*(__half2*)&m.w, *(__half2*)&v.w);
}

__global__ void pool_all_h(const uint4* __restrict__ X,   // (65536, 32) of 8-half
                           const int* __restrict__ a1, const int* __restrict__ a2,
                           const int* __restrict__ a3, const int* __restrict__ a4,
                           uint4* __restrict__ out)
{
    long idx = (long)blockIdx.x * blockDim.x + threadIdx.x;
    if (idx >= 65536L * 32) return;
    int row = (int)(idx >> 5);
    int c = (int)(idx & 31);
    uint4 m = X[idx];
    if (row >= 4096) {
        const int* adj; int d, li;
        if (row < 16384)      { adj = a1; d = 1; li = row - 4096; }
        else if (row < 36864) { adj = a2; d = 2; li = row - 16384; }
        else if (row < 57344) { adj = a3; d = 3; li = row - 36864; }
        else                  { adj = a4; d = 4; li = row - 57344; }
        for (int j = 0; j < d; j++)
            max8(m, X[(long)adj[li * d + j] * 32 + c]);
    }
    out[idx] = m;
}

// ======================= seg init / head(+tanh) =======================
__global__ void seg_init(float* __restrict__ ssum, unsigned* __restrict__ smax)
{
    int idx = blockIdx.x * blockDim.x + threadIdx.x;
    if (idx < 1024 * 512) { ssum[idx] = 0.f; smax[idx] = 0x007FFFFFu; }
}

__global__ void head_kernel(const float* __restrict__ ssum,
                            const unsigned* __restrict__ smax,
                            const float* __restrict__ W,
                            const float* __restrict__ b,
                            float* __restrict__ soft,
                            float* __restrict__ logits,
                            float* __restrict__ out_fp)
{
    __shared__ float row[1024];
    __shared__ float lg[24];
    int bi = blockIdx.x;
    for (int c = threadIdx.x; c < 1024; c += blockDim.x) {
        float v = (c < 512) ? ssum[bi * 512 + c] : funord(smax[bi * 512 + (c - 512)]);
        float t = tanhf(v);
        row[c] = t;
        out_fp[bi * 1024 + c] = t;
    }
    __syncthreads();
    if (threadIdx.x < 24) {
        int t = threadIdx.x;
        float acc = b[t];
        for (int k = 0; k < 1024; k++)
            acc += row[k] * W[k * 24 + t];
        lg[t] = acc;
        logits[bi * 24 + t] = acc;
    }
    __syncthreads();
    if (threadIdx.x < 12) {
        int t = threadIdx.x;
        float l0 = lg[2 * t], l1 = lg[2 * t + 1];
        float m  = fmaxf(l0, l1);
        float e0 = expf(l0 - m), e1 = expf(l1 - m);
        float inv = 1.f / (e0 + e1);
        soft[bi * 24 + 2 * t]     = e0 * inv;
        soft[bi * 24 + 2 * t + 1] = e1 * inv;
    }
}

// ======================= launch =======================
extern "C" void kernel_launch(void* const* d_in, const int* in_sizes, int n_in,
                              void* d_out, int out_size)
{
    const float* atom       = (const float*)d_in[0];
    const int*   membership = (const int*)  d_in[2];
    const int*   a1 = (const int*)d_in[4];
    const int*   a2 = (const int*)d_in[5];
    const int*   a3 = (const int*)d_in[6];
    const int*   a4 = (const int*)d_in[7];
    const float* gc1W = (const float*)d_in[8];
    const float* gc1b = (const float*)d_in[9];
    const float* gc2W = (const float*)d_in[10];
    const float* gc2b = (const float*)d_in[11];
    const float* bn1  = (const float*)d_in[12];
    const float* bn2  = (const float*)d_in[13];
    const float* bn3  = (const float*)d_in[14];
    const float* dW   = (const float*)d_in[15];
    const float* db   = (const float*)d_in[16];
    const float* hW   = (const float*)d_in[17];
    const float* hb   = (const float*)d_in[18];

    __half *atomh, *relh, *bufAh, *bufBh, *w1h, *w2h, *wdh;
    float *ssum; unsigned* smax;
    cudaGetSymbolAddress((void**)&atomh, g_atomh);
    cudaGetSymbolAddress((void**)&relh,  g_relh);
    cudaGetSymbolAddress((void**)&bufAh, g_bufAh);
    cudaGetSymbolAddress((void**)&bufBh, g_bufBh);
    cudaGetSymbolAddress((void**)&w1h,   g_w1h);
    cudaGetSymbolAddress((void**)&w2h,   g_w2h);
    cudaGetSymbolAddress((void**)&wdh,   g_wdh);
    cudaGetSymbolAddress((void**)&ssum,  g_sum);
    cudaGetSymbolAddress((void**)&smax,  g_maxu);

    cudaFuncSetAttribute(conv_gemm_t<32>, cudaFuncAttributeMaxDynamicSharedMemorySize,
                         GP<32>::SMEM);
    cudaFuncSetAttribute(conv_gemm_t<64>, cudaFuncAttributeMaxDynamicSharedMemorySize,
                         GP<64>::SMEM);
    cudaFuncSetAttribute(dense_gemm_h,    cudaFuncAttributeMaxDynamicSharedMemorySize,
                         GP<64>::SMEM);

    float* out        = (float*)d_out;
    float* out_soft   = out;
    float* out_logits = out + 1024 * 24;
    float* out_fp     = out + 2 * 1024 * 24;

    // converts + seg init
    {
        long tot = CV_ATOM + CV_W1 + CV_W2 + CV_WD;
        convert_all<<<(int)((tot + 255) / 256), 256>>>(
            atom, gc1W, gc2W, dW, atomh, w1h, w2h, wdh);
    }
    seg_init<<<(1024 * 512 + 255) / 256, 256>>>(ssum, smax);

    // layer 1 (padded K=96; BKC=32, 3 chunks/pass; gather 12 chunks/row)
    gather_all_h<12><<<(int)((61440L * 12 + 255) / 256), 256>>>(
        atomh, a1, a2, a3, a4, relh);
    conv_gemm_t<32><<<512, 512, GP<32>::SMEM>>>(atomh, 96, 3, relh, w1h, gc1b, bn1, bufAh);
    pool_all_h<<<(int)((65536L * 32 + 255) / 256), 256>>>(
        (const uint4*)bufAh, a1, a2, a3, a4, (uint4*)bufBh);

    // layer 2 (K=256; BKC=64, 4 chunks/pass; gather 32 chunks/row)
    gather_all_h<32><<<(int)((61440L * 32 + 255) / 256), 256>>>(
        bufBh, a1, a2, a3, a4, relh);
    conv_gemm_t<64><<<512, 512, GP<64>::SMEM>>>(bufBh, 256, 4, relh, w2h, gc2b, bn2, bufAh);
    pool_all_h<<<(int)((65536L * 32 + 255) / 256), 256>>>(
        (const uint4*)bufAh, a1, a2, a3, a4, (uint4*)bufBh);

    // dense + BN3 + fused segment sum/max (BKC=64)
    dense_gemm_h<<<dim3(2, 512), 512, GP<64>::SMEM>>>(bufBh, wdh, db, bn3,
                                                      membership, ssum, smax);

    // head (+tanh fp write)
    head_kernel<<<1024, 256>>>(ssum, smax, hW, hb, out_soft, out_logits, out_fp);
}

// round 12
// speedup vs baseline: 3.4643x; 1.0295x over previous
#include <cuda_runtime.h>
#include <cuda_fp16.h>
#include <stdint.h>

#define BN_EPS 1e-3f

// Segment layout: atom rows d0 [0,4096) d1 [4096,16384) d2 [16384,36864) d3 [36864,57344) d4 [57344,65536)
// rel rows: d1 [0,12288) d2 [12288,32768) d3 [32768,53248) d4 [53248,61440)

// -------- scratch (static device globals) --------
__device__ __half   g_atomh[65536 * 80];
__device__ __half   g_relh [61440 * 256];
__device__ __half   g_bufAh[65536 * 256];
__device__ __half   g_bufBh[65536 * 256];
__device__ __half   g_w1h  [9 * 80 * 256];
__device__ __half   g_w2h  [9 * 256 * 256];
__device__ __half   g_wdh  [256 * 512];
__device__ float    g_sum  [1024 * 512];
__device__ unsigned g_maxu [1024 * 512];

// ======================= asm helpers =======================
__device__ __forceinline__ uint32_t smem_u32(const void* p) {
    uint32_t a;
    asm("{ .reg .u64 t; cvta.to.shared.u64 t, %1; cvt.u32.u64 %0, t; }" : "=r"(a) : "l"(p));
    return a;
}
__device__ __forceinline__ uint32_t pkf16(float lo, float hi) {
    uint32_t r; asm("cvt.rn.f16x2.f32 %0, %1, %2;" : "=r"(r) : "f"(hi), "f"(lo));
    return r;
}
__device__ __forceinline__ void cp16(uint32_t dst, const void* src) {
    asm volatile("cp.async.cg.shared.global [%0], [%1], 16;" :: "r"(dst), "l"(src));
}
#define CP_COMMIT() asm volatile("cp.async.commit_group;" ::: "memory")
template<int N>
__device__ __forceinline__ void cp_wait() {
    asm volatile("cp.async.wait_group %0;" :: "n"(N) : "memory");
}

__device__ __forceinline__ void ldsm_x4(uint32_t& r0, uint32_t& r1, uint32_t& r2, uint32_t& r3,
                                        uint32_t addr) {
    asm volatile("ldmatrix.sync.aligned.m8n8.x4.shared.b16 {%0,%1,%2,%3}, [%4];"
        : "=r"(r0), "=r"(r1), "=r"(r2), "=r"(r3) : "r"(addr));
}
__device__ __forceinline__ void ldsm_x2t(uint32_t& r0, uint32_t& r1, uint32_t addr) {
    asm volatile("ldmatrix.sync.aligned.m8n8.x2.trans.shared.b16 {%0,%1}, [%2];"
        : "=r"(r0), "=r"(r1) : "r"(addr));
}
__device__ __forceinline__ void mma16(float* d, const uint32_t* a, const uint32_t* b) {
    asm volatile("mma.sync.aligned.m16n8k16.row.col.f32.f16.f16.f32 "
        "{%0,%1,%2,%3}, {%4,%5,%6,%7}, {%8,%9}, {%0,%1,%2,%3};"
        : "+f"(d[0]), "+f"(d[1]), "+f"(d[2]), "+f"(d[3])
        : "r"(a[0]), "r"(a[1]), "r"(a[2]), "r"(a[3]), "r"(b[0]), "r"(b[1]));
}

__device__ __forceinline__ unsigned ford(float f) {
    unsigned u = __float_as_uint(f);
    return u ^ (unsigned)(((int)u >> 31) | 0x80000000);
}
__device__ __forceinline__ float funord(unsigned v) {
    unsigned u = (v & 0x80000000u) ? (v ^ 0x80000000u) : ~v;
    return __uint_as_float(u);
}

// ======================= templated GEMM pieces =======================
// BKC in {32, 64, 80}. A tile 128 x BKC (row stride BKC+8 halves),
// B tile BKC x 256 (row stride 264 halves).
template<int BKC> struct GP {
    static constexpr int ARH  = BKC + 8;
    static constexpr int ASTG = 128 * ARH * 2;
    static constexpr int BSTG = BKC * 264 * 2;
    static constexpr int STG  = ASTG + BSTG;
    static constexpr int NST  = (BKC == 80) ? 3 : 4;
    static constexpr int SMEM = NST * STG;
};

template<int BKC>
__device__ __forceinline__ void issue_chunk(
    uint32_t sa, uint32_t sb,
    const __half* __restrict__ A, int lda,
    const __half* __restrict__ B, int ldb, int col0, int kt, int tid)
{
    constexpr int AU   = BKC / 8;                 // 16B units per A row
    constexpr int ATOT = 128 * AU;
    constexpr int APT  = (ATOT + 511) / 512;
#pragma unroll
    for (int h = 0; h < APT; h++) {
        int id = tid + h * 512;
        if (ATOT % 512 == 0 || id < ATOT) {
            int row = id / AU, u = id % AU;
            cp16(sa + (row * GP<BKC>::ARH + u * 8) * 2, A + (long)row * lda + kt + u * 8);
        }
    }
    constexpr int BPT = BKC * 32 / 512;
#pragma unroll
    for (int h = 0; h < BPT; h++) {
        int id = tid + h * 512;
        int row = id >> 5, u = id & 31;
        cp16(sb + (row * 264 + u * 8) * 2, B + (long)(kt + row) * ldb + col0 + u * 8);
    }
}

template<int BKC>
__device__ __forceinline__ void compute_stage(
    uint32_t sa, uint32_t sb, float acc[16][4], int wm, int wn, int lane)
{
    const int arow = lane & 15, asel = (lane >> 4) * 8;
#pragma unroll
    for (int ks = 0; ks < BKC / 16; ks++) {
        uint32_t a[4][4];
#pragma unroll
        for (int mt = 0; mt < 4; mt++) {
            int m0 = wm * 64 + mt * 16;
            ldsm_x4(a[mt][0], a[mt][1], a[mt][2], a[mt][3],
                    sa + ((m0 + arow) * GP<BKC>::ARH + ks * 16 + asel) * 2);
        }
        uint32_t b[4][2];
        int krow = ks * 16 + (lane & 15);
#pragma unroll
        for (int nt = 0; nt < 4; nt++) {
            int n0 = wn * 32 + nt * 8;
            ldsm_x2t(b[nt][0], b[nt][1], sb + (krow * 264 + n0) * 2);
        }
#pragma unroll
        for (int mt = 0; mt < 4; mt++)
#pragma unroll
            for (int nt = 0; nt < 4; nt++)
                mma16(acc[mt * 4 + nt], a[mt], b[nt]);
    }
}

// ======================= conv GEMM (fp16, 128x256 CTA, templated BKC) ==========
template<int BKC>
__global__ void __launch_bounds__(512, 1)
conv_gemm_t(const __half* __restrict__ X, int lda, int KCH,
            const __half* __restrict__ REL,
            const __half* __restrict__ Wh,
            const float* __restrict__ bz,
            const float* __restrict__ bnp,
            __half* __restrict__ Y)
{
    constexpr int NST = GP<BKC>::NST;
    extern __shared__ char dyn[];
    const uint32_t sa0 = smem_u32(dyn);
    __shared__ float s_sc[256], s_sh[256], s_bi[256];

    const int tid = threadIdx.x;
    const int lane = tid & 31, wid = tid >> 5;
    const int gid = lane >> 2, tig = lane & 3;
    const int wm = wid & 1, wn = wid >> 1;
    const int row0 = blockIdx.x * 128;
    const int d = (row0 < 4096) ? 0 : (row0 < 16384) ? 1 : (row0 < 36864) ? 2
                : (row0 < 57344) ? 3 : 4;

    if (tid < 256) {
        int c = tid;
        float bias = (d == 0) ? bz[8 * 256 + c]
                              : bz[(2 * d - 2) * 256 + c] + bz[(2 * d - 1) * 256 + c];
        float gg = bnp[c], be = bnp[256 + c], mu = bnp[512 + c], va = bnp[768 + c];
        float sc = gg * rsqrtf(va + BN_EPS);
        s_sc[c] = sc; s_sh[c] = be - mu * sc; s_bi[c] = bias;
    }

    const long wsz = (long)lda * 256;
    const __half* A0 = X + (long)row0 * lda;
    const __half* W0 = Wh + ((d == 0) ? 8 : (2 * d - 1)) * wsz;
    const __half* A1 = (d > 0) ? REL + (long)(row0 - 4096) * lda : A0;
    const __half* W1 = (d > 0) ? Wh + (2 * d - 2) * wsz : W0;
    const int T = ((d > 0) ? 2 : 1) * KCH;

    float acc[16][4];
#pragma unroll
    for (int i = 0; i < 16; i++)
        acc[i][0] = acc[i][1] = acc[i][2] = acc[i][3] = 0.f;

    // prologue: NST-1 groups (empty beyond T; groups complete in commit order)
#pragma unroll
    for (int c = 0; c < NST - 1; c++) {
        if (c < T) {
            int pass = (c >= KCH), kc = c - pass * KCH;
            uint32_t sbase = sa0 + (c % NST) * GP<BKC>::STG;
            issue_chunk<BKC>(sbase, sbase + GP<BKC>::ASTG,
                             pass ? A1 : A0, lda, pass ? W1 : W0, 256, 0, kc * BKC, tid);
        }
        CP_COMMIT();
    }

    for (int c = 0; c < T; c++) {
        cp_wait<NST - 2>();
        __syncthreads();
        int n = c + NST - 1;
        if (n < T) {
            int pass = (n >= KCH), kc = n - pass * KCH;
            uint32_t sbase = sa0 + (n % NST) * GP<BKC>::STG;
            issue_chunk<BKC>(sbase, sbase + GP<BKC>::ASTG,
                             pass ? A1 : A0, lda, pass ? W1 : W0, 256, 0, kc * BKC, tid);
        }
        CP_COMMIT();
        uint32_t sbase = sa0 + (c % NST) * GP<BKC>::STG;
        compute_stage<BKC>(sbase, sbase + GP<BKC>::ASTG, acc, wm, wn, lane);
    }
    __syncthreads();

#pragma unroll
    for (int mt = 0; mt < 4; mt++) {
#pragma unroll
        for (int nt = 0; nt < 4; nt++) {
            int cl = wn * 32 + nt * 8 + tig * 2;
            int r = row0 + wm * 64 + mt * 16 + gid;
            float* a4 = acc[mt * 4 + nt];
            float sc0 = s_sc[cl], sc1 = s_sc[cl + 1];
            float sh0 = s_sh[cl], sh1 = s_sh[cl + 1];
            float bi0 = s_bi[cl], bi1 = s_bi[cl + 1];
            float x0 = fmaxf(a4[0] + bi0, 0.f) * sc0 + sh0;
            float x1 = fmaxf(a4[1] + bi1, 0.f) * sc1 + sh1;
            *reinterpret_cast<uint32_t*>(&Y[(long)r * 256 + cl]) = pkf16(x0, x1);
            x0 = fmaxf(a4[2] + bi0, 0.f) * sc0 + sh0;
            x1 = fmaxf(a4[3] + bi1, 0.f) * sc1 + sh1;
            *reinterpret_cast<uint32_t*>(&Y[(long)(r + 8) * 256 + cl]) = pkf16(x0, x1);
        }
    }
}

// ======================= dense GEMM + fused segment reduce (BKC=64) ==========
__global__ void __launch_bounds__(512, 1)
dense_gemm_h(const __half* __restrict__ X,     // (65536, 256)
             const __half* __restrict__ Wh,    // (256, 512)
             const float* __restrict__ bz,
             const float* __restrict__ bnp,
             const int* __restrict__ mem,
             float* __restrict__ ssum,
             unsigned* __restrict__ smax)
{
    constexpr int BKC = 64;
    constexpr int NST = GP<BKC>::NST;
    extern __shared__ char dyn[];
    const uint32_t sa0 = smem_u32(dyn);
    __shared__ float s_sc[256], s_sh[256], s_bi[256];

    const int tid = threadIdx.x;
    const int lane = tid & 31, wid = tid >> 5;
    const int gid = lane >> 2, tig = lane & 3;
    const int wm = wid & 1, wn = wid >> 1;
    const int row0 = blockIdx.y * 128;
    const int col0 = blockIdx.x * 256;
    const int T = 4;

    if (tid < 256) {
        int c = col0 + tid;
        float gg = bnp[c], be = bnp[512 + c], mu = bnp[1024 + c], va = bnp[1536 + c];
        float sc = gg * rsqrtf(va + BN_EPS);
        s_sc[tid] = sc; s_sh[tid] = be - mu * sc; s_bi[tid] = bz[c];
    }

    const __half* A = X + (long)row0 * 256;
    float acc[16][4];
#pragma unroll
    for (int i = 0; i < 16; i++)
        acc[i][0] = acc[i][1] = acc[i][2] = acc[i][3] = 0.f;

#pragma unroll
    for (int c = 0; c < NST - 1; c++) {
        if (c < T) {
            uint32_t sbase = sa0 + (c % NST) * GP<BKC>::STG;
            issue_chunk<BKC>(sbase, sbase + GP<BKC>::ASTG, A, 256, Wh, 512, col0,
                             c * BKC, tid);
        }
        CP_COMMIT();
    }
    for (int c = 0; c < T; c++) {
        cp_wait<NST - 2>();
        __syncthreads();
        int n = c + NST - 1;
        if (n < T) {
            uint32_t sbase = sa0 + (n % NST) * GP<BKC>::STG;
            issue_chunk<BKC>(sbase, sbase + GP<BKC>::ASTG, A, 256, Wh, 512, col0,
                             n * BKC, tid);
        }
        CP_COMMIT();
        uint32_t sbase = sa0 + (c % NST) * GP<BKC>::STG;
        compute_stage<BKC>(sbase, sbase + GP<BKC>::ASTG, acc, wm, wn, lane);
    }
    __syncthreads();

    // fused epilogue: BN3(relu(.)) + atomic segment sum/max
#pragma unroll
    for (int mt = 0; mt < 4; mt++) {
        int r = row0 + wm * 64 + mt * 16 + gid;
        int m0 = mem[r] * 512, m1 = mem[r + 8] * 512;
#pragma unroll
        for (int nt = 0; nt < 4; nt++) {
            int cl = wn * 32 + nt * 8 + tig * 2;
            int gc = col0 + cl;
            float* a4 = acc[mt * 4 + nt];
            float sc0 = s_sc[cl], sc1 = s_sc[cl + 1];
            float sh0 = s_sh[cl], sh1 = s_sh[cl + 1];
            float bi0 = s_bi[cl], bi1 = s_bi[cl + 1];
            float x00 = fmaxf(a4[0] + bi0, 0.f) * sc0 + sh0;
            float x01 = fmaxf(a4[1] + bi1, 0.f) * sc1 + sh1;
            float x10 = fmaxf(a4[2] + bi0, 0.f) * sc0 + sh0;
            float x11 = fmaxf(a4[3] + bi1, 0.f) * sc1 + sh1;
            atomicAdd(&ssum[m0 + gc],     x00);
            atomicAdd(&ssum[m0 + gc + 1], x01);
            atomicAdd(&ssum[m1 + gc],     x10);
            atomicAdd(&ssum[m1 + gc + 1], x11);
            atomicMax(&smax[m0 + gc],     ford(x00));
            atomicMax(&smax[m0 + gc + 1], ford(x01));
            atomicMax(&smax[m1 + gc],     ford(x10));
            atomicMax(&smax[m1 + gc + 1], ford(x11));
        }
    }
}

// ======================= merged converts + seg init =======================
#define CV_ATOM (65536L * 80)
#define CV_W1   (9L * 80 * 256)
#define CV_W2   (9L * 256 * 256)
#define CV_WD   (256L * 512)
#define CV_SEG  (1024L * 512)
__global__ void convert_all(const float* __restrict__ atomf,
                            const float* __restrict__ w1f,
                            const float* __restrict__ w2f,
                            const float* __restrict__ wdf,
                            __half* __restrict__ atomh, __half* __restrict__ w1h,
                            __half* __restrict__ w2h,   __half* __restrict__ wdh,
                            float* __restrict__ ssum,   unsigned* __restrict__ smax)
{
    long idx = (long)blockIdx.x * blockDim.x + threadIdx.x;
    if (idx < CV_ATOM) {
        int row = (int)(idx / 80), k = (int)(idx - (long)row * 80);
        atomh[idx] = (k < 75) ? __float2half(atomf[(long)row * 75 + k]) : __half(0.f);
        return;
    }
    idx -= CV_ATOM;
    if (idx < CV_W1) {
        int n = (int)(idx & 255);
        long t = idx >> 8;
        int k = (int)(t % 80), gg = (int)(t / 80);
        w1h[idx] = (k < 75) ? __float2half(w1f[((long)gg * 75 + k) * 256 + n]) : __half(0.f);
        return;
    }
    idx -= CV_W1;
    if (idx < CV_W2) { w2h[idx] = __float2half(w2f[idx]); return; }
    idx -= CV_W2;
    if (idx < CV_WD) { wdh[idx] = __float2half(wdf[idx]); return; }
    idx -= CV_WD;
    if (idx < CV_SEG) { ssum[idx] = 0.f; smax[idx] = 0x007FFFFFu; }
}

// ======================= gather / pool =======================
__device__ __forceinline__ void acc8(float2 s[4], uint4 v) {
    s[0].x += __low2float(*(__half2*)&v.x);  s[0].y += __high2float(*(__half2*)&v.x);
    s[1].x += __low2float(*(__half2*)&v.y);  s[1].y += __high2float(*(__half2*)&v.y);
    s[2].x += __low2float(*(__half2*)&v.z);  s[2].y += __high2float(*(__half2*)&v.z);
    s[3].x += __low2float(*(__half2*)&v.w);  s[3].y += __high2float(*(__half2*)&v.w);
}

template<int CH>
__global__ void gather_all_h(const __half* __restrict__ X,
                             const int* __restrict__ a1, const int* __restrict__ a2,
                             const int* __restrict__ a3, const int* __restrict__ a4,
                             __half* __restrict__ out)
{
    constexpr int LD = CH * 8;
    long idx = (long)blockIdx.x * blockDim.x + threadIdx.x;
    if (idx >= 61440L * CH) return;
    int i = (int)(idx / CH);
    int c = (int)(idx - (long)i * CH) * 8;
    const int* adj; int d, li;
    if (i < 12288)      { adj = a1; d = 1; li = i; }
    else if (i < 32768) { adj = a2; d = 2; li = i - 12288; }
    else if (i < 53248) { adj = a3; d = 3; li = i - 32768; }
    else                { adj = a4; d = 4; li = i - 53248; }
    float2 s[4];
    s[0] = s[1] = s[2] = s[3] = make_float2(0.f, 0.f);
    for (int j = 0; j < d; j++) {
        uint4 v = *reinterpret_cast<const uint4*>(X + (long)adj[li * d + j] * LD + c);
        acc8(s, v);
    }
    uint4 o;
    o.x = pkf16(s[0].x, s[0].y); o.y = pkf16(s[1].x, s[1].y);
    o.z = pkf16(s[2].x, s[2].y); o.w = pkf16(s[3].x, s[3].y);
    *reinterpret_cast<uint4*>(out + (long)i * LD + c) = o;
}

__device__ __forceinline__ void max8(uint4& m, uint4 v) {
    *(__half2*)&m.x = __hmax2(*(__half2*)&m.x, *(__half2*)&v.x);
    *(__half2*)&m.y = __hmax2(*(__half2*)&m.y, *(__half2*)&v.y);
    *(__half2*)&m.z = __hmax2(*(__half2*)&m.z, *(__half2*)&v.z);
    *(__half2*)&m.w = __hmax2(*(__half2*)&m.w, *(__half2*)&v.w);
}

// 32 halves (2 x uint4) per thread
__global__ void pool_all_h(const uint4* __restrict__ X,   // (65536, 32) of 8-half
                           const int* __restrict__ a1, const int* __restrict__ a2,
                           const int* __restrict__ a3, const int* __restrict__ a4,
                           uint4* __restrict__ out)
{
    long idx = (long)blockIdx.x * blockDim.x + threadIdx.x;
    if (idx >= 65536L * 16) return;
    int row = (int)(idx >> 4);
    int c = (int)(idx & 15) * 2;
    long base = (long)row * 32 + c;
    uint4 m0 = X[base], m1 = X[base + 1];
    if (row >= 4096) {
        const int* adj; int d, li;
        if (row < 16384)      { adj = a1; d = 1; li = row - 4096; }
        else if (row < 36864) { adj = a2; d = 2; li = row - 16384; }
        else if (row < 57344) { adj = a3; d = 3; li = row - 36864; }
        else                  { adj = a4; d = 4; li = row - 57344; }
        for (int j = 0; j < d; j++) {
            long nb = (long)adj[li * d + j] * 32 + c;
            max8(m0, X[nb]);
            max8(m1, X[nb + 1]);
        }
    }
    out[base] = m0;
    out[base + 1] = m1;
}

// ======================= head (+tanh fp write) =======================
__global__ void head_kernel(const float* __restrict__ ssum,
                            const unsigned* __restrict__ smax,
                            const float* __restrict__ W,
                            const float* __restrict__ b,
                            float* __restrict__ soft,
                            float* __restrict__ logits,
                            float* __restrict__ out_fp)
{
    __shared__ float row[1024];
    __shared__ float lg[24];
    int bi = blockIdx.x;
    for (int c = threadIdx.x; c < 1024; c += blockDim.x) {
        float v = (c < 512) ? ssum[bi * 512 + c] : funord(smax[bi * 512 + (c - 512)]);
        float t = tanhf(v);
        row[c] = t;
        out_fp[bi * 1024 + c] = t;
    }
    __syncthreads();
    if (threadIdx.x < 24) {
        int t = threadIdx.x;
        float acc = b[t];
        for (int k = 0; k < 1024; k++)
            acc += row[k] * W[k * 24 + t];
        lg[t] = acc;
        logits[bi * 24 + t] = acc;
    }
    __syncthreads();
    if (threadIdx.x < 12) {
        int t = threadIdx.x;
        float l0 = lg[2 * t], l1 = lg[2 * t + 1];
        float m  = fmaxf(l0, l1);
        float e0 = expf(l0 - m), e1 = expf(l1 - m);
        float inv = 1.f / (e0 + e1);
        soft[bi * 24 + 2 * t]     = e0 * inv;
        soft[bi * 24 + 2 * t + 1] = e1 * inv;
    }
}

// ======================= launch =======================
extern "C" void kernel_launch(void* const* d_in, const int* in_sizes, int n_in,
                              void* d_out, int out_size)
{
    const float* atom       = (const float*)d_in[0];
    const int*   membership = (const int*)  d_in[2];
    const int*   a1 = (const int*)d_in[4];
    const int*   a2 = (const int*)d_in[5];
    const int*   a3 = (const int*)d_in[6];
    const int*   a4 = (const int*)d_in[7];
    const float* gc1W = (const float*)d_in[8];
    const float* gc1b = (const float*)d_in[9];
    const float* gc2W = (const float*)d_in[10];
    const float* gc2b = (const float*)d_in[11];
    const float* bn1  = (const float*)d_in[12];
    const float* bn2  = (const float*)d_in[13];
    const float* bn3  = (const float*)d_in[14];
    const float* dW   = (const float*)d_in[15];
    const float* db   = (const float*)d_in[16];
    const float* hW   = (const float*)d_in[17];
    const float* hb   = (const float*)d_in[18];

    __half *atomh, *relh, *bufAh, *bufBh, *w1h, *w2h, *wdh;
    float *ssum; unsigned* smax;
    cudaGetSymbolAddress((void**)&atomh, g_atomh);
    cudaGetSymbolAddress((void**)&relh,  g_relh);
    cudaGetSymbolAddress((void**)&bufAh, g_bufAh);
    cudaGetSymbolAddress((void**)&bufBh, g_bufBh);
    cudaGetSymbolAddress((void**)&w1h,   g_w1h);
    cudaGetSymbolAddress((void**)&w2h,   g_w2h);
    cudaGetSymbolAddress((void**)&wdh,   g_wdh);
    cudaGetSymbolAddress((void**)&ssum,  g_sum);
    cudaGetSymbolAddress((void**)&smax,  g_maxu);

    cudaFuncSetAttribute(conv_gemm_t<80>, cudaFuncAttributeMaxDynamicSharedMemorySize,
                         GP<80>::SMEM);
    cudaFuncSetAttribute(conv_gemm_t<64>, cudaFuncAttributeMaxDynamicSharedMemorySize,
                         GP<64>::SMEM);
    cudaFuncSetAttribute(dense_gemm_h,    cudaFuncAttributeMaxDynamicSharedMemorySize,
                         GP<64>::SMEM);

    float* out        = (float*)d_out;
    float* out_soft   = out;
    float* out_logits = out + 1024 * 24;
    float* out_fp     = out + 2 * 1024 * 24;

    // converts + seg init (one launch)
    {
        long tot = CV_ATOM + CV_W1 + CV_W2 + CV_WD + CV_SEG;
        convert_all<<<(int)((tot + 255) / 256), 256>>>(
            atom, gc1W, gc2W, dW, atomh, w1h, w2h, wdh, ssum, smax);
    }

    // layer 1 (padded K=80; BKC=80, 1 chunk/pass; gather 10 chunks/row)
    gather_all_h<10><<<(int)((61440L * 10 + 255) / 256), 256>>>(
        atomh, a1, a2, a3, a4, relh);
    conv_gemm_t<80><<<512, 512, GP<80>::SMEM>>>(atomh, 80, 1, relh, w1h, gc1b, bn1, bufAh);
    pool_all_h<<<(int)((65536L * 16 + 255) / 256), 256>>>(
        (const uint4*)bufAh, a1, a2, a3, a4, (uint4*)bufBh);

    // layer 2 (K=256; BKC=64, 4 chunks/pass; gather 32 chunks/row)
    gather_all_h<32><<<(int)((61440L * 32 + 255) / 256), 256>>>(
        bufBh, a1, a2, a3, a4, relh);
    conv_gemm_t<64><<<512, 512, GP<64>::SMEM>>>(bufBh, 256, 4, relh, w2h, gc2b, bn2, bufAh);
    pool_all_h<<<(int)((65536L * 16 + 255) / 256), 256>>>(
        (const uint4*)bufAh, a1, a2, a3, a4, (uint4*)bufBh);

    // dense + BN3 + fused segment sum/max (BKC=64)
    dense_gemm_h<<<dim3(2, 512), 512, GP<64>::SMEM>>>(bufBh, wdh, db, bn3,
                                                      membership, ssum, smax);

    // head (+tanh fp write)
    head_kernel<<<1024, 256>>>(ssum, smax, hW, hb, out_soft, out_logits, out_fp);
}

// round 13
// speedup vs baseline: 3.6950x; 1.0666x over previous
#include <cuda_runtime.h>
#include <cuda_fp16.h>
#include <stdint.h>

#define BN_EPS 1e-3f

// Segment layout: atom rows d0 [0,4096) d1 [4096,16384) d2 [16384,36864) d3 [36864,57344) d4 [57344,65536)
// rel rows: d1 [0,12288) d2 [12288,32768) d3 [32768,53248) d4 [53248,61440)

// -------- scratch (static device globals) --------
__device__ __half   g_atomh[65536 * 80];
__device__ __half   g_relh [61440 * 256];
__device__ __half   g_bufAh[65536 * 256];
__device__ __half   g_bufBh[65536 * 256];
__device__ __half   g_w1h  [9 * 80 * 256];
__device__ __half   g_w2h  [9 * 256 * 256];
__device__ __half   g_wdh  [256 * 512];
__device__ float    g_sum  [1024 * 512];
__device__ unsigned g_maxu [1024 * 512];

// ======================= asm helpers =======================
__device__ __forceinline__ uint32_t smem_u32(const void* p) {
    uint32_t a;
    asm("{ .reg .u64 t; cvta.to.shared.u64 t, %1; cvt.u32.u64 %0, t; }" : "=r"(a) : "l"(p));
    return a;
}
__device__ __forceinline__ uint32_t pkf16(float lo, float hi) {
    uint32_t r; asm("cvt.rn.f16x2.f32 %0, %1, %2;" : "=r"(r) : "f"(hi), "f"(lo));
    return r;
}
__device__ __forceinline__ void cp16(uint32_t dst, const void* src) {
    asm volatile("cp.async.cg.shared.global [%0], [%1], 16;" :: "r"(dst), "l"(src));
}
#define CP_COMMIT() asm volatile("cp.async.commit_group;" ::: "memory")
template<int N>
__device__ __forceinline__ void cp_wait() {
    asm volatile("cp.async.wait_group %0;" :: "n"(N) : "memory");
}

__device__ __forceinline__ void ldsm_x4(uint32_t& r0, uint32_t& r1, uint32_t& r2, uint32_t& r3,
                                        uint32_t addr) {
    asm volatile("ldmatrix.sync.aligned.m8n8.x4.shared.b16 {%0,%1,%2,%3}, [%4];"
        : "=r"(r0), "=r"(r1), "=r"(r2), "=r"(r3) : "r"(addr));
}
__device__ __forceinline__ void ldsm_x2t(uint32_t& r0, uint32_t& r1, uint32_t addr) {
    asm volatile("ldmatrix.sync.aligned.m8n8.x2.trans.shared.b16 {%0,%1}, [%2];"
        : "=r"(r0), "=r"(r1) : "r"(addr));
}
__device__ __forceinline__ void mma16(float* d, const uint32_t* a, const uint32_t* b) {
    asm volatile("mma.sync.aligned.m16n8k16.row.col.f32.f16.f16.f32 "
        "{%0,%1,%2,%3}, {%4,%5,%6,%7}, {%8,%9}, {%0,%1,%2,%3};"
        : "+f"(d[0]), "+f"(d[1]), "+f"(d[2]), "+f"(d[3])
        : "r"(a[0]), "r"(a[1]), "r"(a[2]), "r"(a[3]), "r"(b[0]), "r"(b[1]));
}

__device__ __forceinline__ unsigned ford(float f) {
    unsigned u = __float_as_uint(f);
    return u ^ (unsigned)(((int)u >> 31) | 0x80000000);
}
__device__ __forceinline__ float funord(unsigned v) {
    unsigned u = (v & 0x80000000u) ? (v ^ 0x80000000u) : ~v;
    return __uint_as_float(u);
}

// ======================= GEMM pieces: 256 threads, 128x128 tile =======================
// A tile 128 x BKC (row stride BKC+8 halves), B tile BKC x 128 (row stride 136 halves).
template<int BKC> struct GP {
    static constexpr int ARH  = BKC + 8;
    static constexpr int ASTG = 128 * ARH * 2;
    static constexpr int BSTG = BKC * 136 * 2;
    static constexpr int STG  = ASTG + BSTG;
    static constexpr int NST  = (BKC == 80) ? 2 : 3;
    static constexpr int SMEM = NST * STG;
};

template<int BKC>
__device__ __forceinline__ void issue_chunk(
    uint32_t sa, uint32_t sb,
    const __half* __restrict__ A, int lda,
    const __half* __restrict__ B, int ldb, int col0, int kt, int tid)
{
    constexpr int AU   = BKC / 8;            // 16B units per A row (8 or 10)
    constexpr int ATOT = 128 * AU;
    constexpr int APT  = ATOT / 256;         // 4 or 5 per thread
#pragma unroll
    for (int h = 0; h < APT; h++) {
        int id = tid + h * 256;
        int row = id / AU, u = id % AU;
        cp16(sa + (row * GP<BKC>::ARH + u * 8) * 2, A + (long)row * lda + kt + u * 8);
    }
    constexpr int BPT = BKC * 16 / 256;      // 4 or 5 per thread
#pragma unroll
    for (int h = 0; h < BPT; h++) {
        int id = tid + h * 256;
        int row = id >> 4, u = id & 15;
        cp16(sb + (row * 136 + u * 8) * 2, B + (long)(kt + row) * ldb + col0 + u * 8);
    }
}

template<int BKC>
__device__ __forceinline__ void compute_stage(
    uint32_t sa, uint32_t sb, float acc[16][4], int wm, int wn, int lane)
{
    const int arow = lane & 15, asel = (lane >> 4) * 8;
#pragma unroll
    for (int ks = 0; ks < BKC / 16; ks++) {
        uint32_t a[4][4];
#pragma unroll
        for (int mt = 0; mt < 4; mt++) {
            int m0 = wm * 64 + mt * 16;
            ldsm_x4(a[mt][0], a[mt][1], a[mt][2], a[mt][3],
                    sa + ((m0 + arow) * GP<BKC>::ARH + ks * 16 + asel) * 2);
        }
        uint32_t b[4][2];
        int krow = ks * 16 + (lane & 15);
#pragma unroll
        for (int nt = 0; nt < 4; nt++) {
            int n0 = wn * 32 + nt * 8;
            ldsm_x2t(b[nt][0], b[nt][1], sb + (krow * 136 + n0) * 2);
        }
#pragma unroll
        for (int mt = 0; mt < 4; mt++)
#pragma unroll
            for (int nt = 0; nt < 4; nt++)
                mma16(acc[mt * 4 + nt], a[mt], b[nt]);
    }
}

// ======================= conv GEMM (fp16, 128x128 CTA, 2 CTAs/SM) ==========
template<int BKC>
__global__ void __launch_bounds__(256, 2)
conv_gemm_t(const __half* __restrict__ X, int lda, int KCH,
            const __half* __restrict__ REL,
            const __half* __restrict__ Wh,
            const float* __restrict__ bz,
            const float* __restrict__ bnp,
            __half* __restrict__ Y)
{
    constexpr int NST = GP<BKC>::NST;
    extern __shared__ char dyn[];
    const uint32_t sa0 = smem_u32(dyn);
    __shared__ float s_sc[128], s_sh[128], s_bi[128];

    const int tid = threadIdx.x;
    const int lane = tid & 31, wid = tid >> 5;
    const int gid = lane >> 2, tig = lane & 3;
    const int wm = wid & 1, wn = wid >> 1;
    const int row0 = blockIdx.y * 128;
    const int col0 = blockIdx.x * 128;
    const int d = (row0 < 4096) ? 0 : (row0 < 16384) ? 1 : (row0 < 36864) ? 2
                : (row0 < 57344) ? 3 : 4;

    if (tid < 128) {
        int c = col0 + tid;
        float bias = (d == 0) ? bz[8 * 256 + c]
                              : bz[(2 * d - 2) * 256 + c] + bz[(2 * d - 1) * 256 + c];
        float gg = bnp[c], be = bnp[256 + c], mu = bnp[512 + c], va = bnp[768 + c];
        float sc = gg * rsqrtf(va + BN_EPS);
        s_sc[tid] = sc; s_sh[tid] = be - mu * sc; s_bi[tid] = bias;
    }

    const long wsz = (long)lda * 256;
    const __half* A0 = X + (long)row0 * lda;
    const __half* W0 = Wh + ((d == 0) ? 8 : (2 * d - 1)) * wsz;
    const __half* A1 = (d > 0) ? REL + (long)(row0 - 4096) * lda : A0;
    const __half* W1 = (d > 0) ? Wh + (2 * d - 2) * wsz : W0;
    const int T = ((d > 0) ? 2 : 1) * KCH;

    float acc[16][4];
#pragma unroll
    for (int i = 0; i < 16; i++)
        acc[i][0] = acc[i][1] = acc[i][2] = acc[i][3] = 0.f;

#pragma unroll
    for (int c = 0; c < NST - 1; c++) {
        if (c < T) {
            int pass = (c >= KCH), kc = c - pass * KCH;
            uint32_t sbase = sa0 + (c % NST) * GP<BKC>::STG;
            issue_chunk<BKC>(sbase, sbase + GP<BKC>::ASTG,
                             pass ? A1 : A0, lda, pass ? W1 : W0, 256, col0, kc * BKC, tid);
        }
        CP_COMMIT();
    }

    for (int c = 0; c < T; c++) {
        cp_wait<NST - 2>();
        __syncthreads();
        int n = c + NST - 1;
        if (n < T) {
            int pass = (n >= KCH), kc = n - pass * KCH;
            uint32_t sbase = sa0 + (n % NST) * GP<BKC>::STG;
            issue_chunk<BKC>(sbase, sbase + GP<BKC>::ASTG,
                             pass ? A1 : A0, lda, pass ? W1 : W0, 256, col0, kc * BKC, tid);
        }
        CP_COMMIT();
        uint32_t sbase = sa0 + (c % NST) * GP<BKC>::STG;
        compute_stage<BKC>(sbase, sbase + GP<BKC>::ASTG, acc, wm, wn, lane);
    }
    __syncthreads();

#pragma unroll
    for (int mt = 0; mt < 4; mt++) {
#pragma unroll
        for (int nt = 0; nt < 4; nt++) {
            int cl = wn * 32 + nt * 8 + tig * 2;
            int r = row0 + wm * 64 + mt * 16 + gid;
            float* a4 = acc[mt * 4 + nt];
            float sc0 = s_sc[cl], sc1 = s_sc[cl + 1];
            float sh0 = s_sh[cl], sh1 = s_sh[cl + 1];
            float bi0 = s_bi[cl], bi1 = s_bi[cl + 1];
            float x0 = fmaxf(a4[0] + bi0, 0.f) * sc0 + sh0;
            float x1 = fmaxf(a4[1] + bi1, 0.f) * sc1 + sh1;
            *reinterpret_cast<uint32_t*>(&Y[(long)r * 256 + col0 + cl]) = pkf16(x0, x1);
            x0 = fmaxf(a4[2] + bi0, 0.f) * sc0 + sh0;
            x1 = fmaxf(a4[3] + bi1, 0.f) * sc1 + sh1;
            *reinterpret_cast<uint32_t*>(&Y[(long)(r + 8) * 256 + col0 + cl]) = pkf16(x0, x1);
        }
    }
}

// ======================= dense GEMM + fused segment reduce (BKC=64) ==========
__global__ void __launch_bounds__(256, 2)
dense_gemm_h(const __half* __restrict__ X,     // (65536, 256)
             const __half* __restrict__ Wh,    // (256, 512)
             const float* __restrict__ bz,
             const float* __restrict__ bnp,
             const int* __restrict__ mem,
             float* __restrict__ ssum,
             unsigned* __restrict__ smax)
{
    constexpr int BKC = 64;
    constexpr int NST = GP<BKC>::NST;
    extern __shared__ char dyn[];
    const uint32_t sa0 = smem_u32(dyn);
    __shared__ float s_sc[128], s_sh[128], s_bi[128];

    const int tid = threadIdx.x;
    const int lane = tid & 31, wid = tid >> 5;
    const int gid = lane >> 2, tig = lane & 3;
    const int wm = wid & 1, wn = wid >> 1;
    const int row0 = blockIdx.y * 128;
    const int col0 = blockIdx.x * 128;
    const int T = 4;

    if (tid < 128) {
        int c = col0 + tid;
        float gg = bnp[c], be = bnp[512 + c], mu = bnp[1024 + c], va = bnp[1536 + c];
        float sc = gg * rsqrtf(va + BN_EPS);
        s_sc[tid] = sc; s_sh[tid] = be - mu * sc; s_bi[tid] = bz[c];
    }

    const __half* A = X + (long)row0 * 256;
    float acc[16][4];
#pragma unroll
    for (int i = 0; i < 16; i++)
        acc[i][0] = acc[i][1] = acc[i][2] = acc[i][3] = 0.f;

#pragma unroll
    for (int c = 0; c < NST - 1; c++) {
        if (c < T) {
            uint32_t sbase = sa0 + (c % NST) * GP<BKC>::STG;
            issue_chunk<BKC>(sbase, sbase + GP<BKC>::ASTG, A, 256, Wh, 512, col0,
                             c * BKC, tid);
        }
        CP_COMMIT();
    }
    for (int c = 0; c < T; c++) {
        cp_wait<NST - 2>();
        __syncthreads();
        int n = c + NST - 1;
        if (n < T) {
            uint32_t sbase = sa0 + (n % NST) * GP<BKC>::STG;
            issue_chunk<BKC>(sbase, sbase + GP<BKC>::ASTG, A, 256, Wh, 512, col0,
                             n * BKC, tid);
        }
        CP_COMMIT();
        uint32_t sbase = sa0 + (c % NST) * GP<BKC>::STG;
        compute_stage<BKC>(sbase, sbase + GP<BKC>::ASTG, acc, wm, wn, lane);
    }
    __syncthreads();

    // fused epilogue: BN3(relu(.)) + atomic segment sum/max
#pragma unroll
    for (int mt = 0; mt < 4; mt++) {
        int r = row0 + wm * 64 + mt * 16 + gid;
        int m0 = mem[r] * 512, m1 = mem[r + 8] * 512;
#pragma unroll
        for (int nt = 0; nt < 4; nt++) {
            int cl = wn * 32 + nt * 8 + tig * 2;
            int gc = col0 + cl;
            float* a4 = acc[mt * 4 + nt];
            float sc0 = s_sc[cl], sc1 = s_sc[cl + 1];
            float sh0 = s_sh[cl], sh1 = s_sh[cl + 1];
            float bi0 = s_bi[cl], bi1 = s_bi[cl + 1];
            float x00 = fmaxf(a4[0] + bi0, 0.f) * sc0 + sh0;
            float x01 = fmaxf(a4[1] + bi1, 0.f) * sc1 + sh1;
            float x10 = fmaxf(a4[2] + bi0, 0.f) * sc0 + sh0;
            float x11 = fmaxf(a4[3] + bi1, 0.f) * sc1 + sh1;
            atomicAdd(&ssum[m0 + gc],     x00);
            atomicAdd(&ssum[m0 + gc + 1], x01);
            atomicAdd(&ssum[m1 + gc],     x10);
            atomicAdd(&ssum[m1 + gc + 1], x11);
            atomicMax(&smax[m0 + gc],     ford(x00));
            atomicMax(&smax[m0 + gc + 1], ford(x01));
            atomicMax(&smax[m1 + gc],     ford(x10));
            atomicMax(&smax[m1 + gc + 1], ford(x11));
        }
    }
}

// ======================= merged converts + seg init =======================
#define CV_ATOM (65536L * 80)
#define CV_W1   (9L * 80 * 256)
#define CV_W2   (9L * 256 * 256)
#define CV_WD   (256L * 512)
#define CV_SEG  (1024L * 512)
__global__ void convert_all(const float* __restrict__ atomf,
                            const float* __restrict__ w1f,
                            const float* __restrict__ w2f,
                            const float* __restrict__ wdf,
                            __half* __restrict__ atomh, __half* __restrict__ w1h,
                            __half* __restrict__ w2h,   __half* __restrict__ wdh,
                            float* __restrict__ ssum,   unsigned* __restrict__ smax)
{
    long idx = (long)blockIdx.x * blockDim.x + threadIdx.x;
    if (idx < CV_ATOM) {
        int row = (int)(idx / 80), k = (int)(idx - (long)row * 80);
        atomh[idx] = (k < 75) ? __float2half(atomf[(long)row * 75 + k]) : __half(0.f);
        return;
    }
    idx -= CV_ATOM;
    if (idx < CV_W1) {
        int n = (int)(idx & 255);
        long t = idx >> 8;
        int k = (int)(t % 80), gg = (int)(t / 80);
        w1h[idx] = (k < 75) ? __float2half(w1f[((long)gg * 75 + k) * 256 + n]) : __half(0.f);
        return;
    }
    idx -= CV_W1;
    if (idx < CV_W2) { w2h[idx] = __float2half(w2f[idx]); return; }
    idx -= CV_W2;
    if (idx < CV_WD) { wdh[idx] = __float2half(wdf[idx]); return; }
    idx -= CV_WD;
    if (idx < CV_SEG) { ssum[idx] = 0.f; smax[idx] = 0x007FFFFFu; }
}

// ======================= gather / pool =======================
__device__ __forceinline__ void acc8(float2 s[4], uint4 v) {
    s[0].x += __low2float(*(__half2*)&v.x);  s[0].y += __high2float(*(__half2*)&v.x);
    s[1].x += __low2float(*(__half2*)&v.y);  s[1].y += __high2float(*(__half2*)&v.y);
    s[2].x += __low2float(*(__half2*)&v.z);  s[2].y += __high2float(*(__half2*)&v.z);
    s[3].x += __low2float(*(__half2*)&v.w);  s[3].y += __high2float(*(__half2*)&v.w);
}

template<int CH>
__global__ void gather_all_h(const __half* __restrict__ X,
                             const int* __restrict__ a1, const int* __restrict__ a2,
                             const int* __restrict__ a3, const int* __restrict__ a4,
                             __half* __restrict__ out)
{
    constexpr int LD = CH * 8;
    long idx = (long)blockIdx.x * blockDim.x + threadIdx.x;
    if (idx >= 61440L * CH) return;
    int i = (int)(idx / CH);
    int c = (int)(idx - (long)i * CH) * 8;
    const int* adj; int d, li;
    if (i < 12288)      { adj = a1; d = 1; li = i; }
    else if (i < 32768) { adj = a2; d = 2; li = i - 12288; }
    else if (i < 53248) { adj = a3; d = 3; li = i - 32768; }
    else                { adj = a4; d = 4; li = i - 53248; }
    float2 s[4];
    s[0] = s[1] = s[2] = s[3] = make_float2(0.f, 0.f);
    for (int j = 0; j < d; j++) {
        uint4 v = *reinterpret_cast<const uint4*>(X + (long)adj[li * d + j] * LD + c);
        acc8(s, v);
    }
    uint4 o;
    o.x = pkf16(s[0].x, s[0].y); o.y = pkf16(s[1].x, s[1].y);
    o.z = pkf16(s[2].x, s[2].y); o.w = pkf16(s[3].x, s[3].y);
    *reinterpret_cast<uint4*>(out + (long)i * LD + c) = o;
}

__device__ __forceinline__ void max8(uint4& m, uint4 v) {
    *(__half2*)&m.x = __hmax2(*(__half2*)&m.x, *(__half2*)&v.x);
    *(__half2*)&m.y = __hmax2(*(__half2*)&m.y, *(__half2*)&v.y);
    *(__half2*)&m.z = __hmax2(*(__half2*)&m.z, *(__half2*)&v.z);
    *(__half2*)&m.w = __hmax2(*(__half2*)&m.w, *(__half2*)&v.w);
}

// 64 halves (4 x uint4) per thread; 8 threads per 256-col row
__global__ void __launch_bounds__(512)
pool_all_h(const uint4* __restrict__ X,   // (65536, 32) of 8-half
           const int* __restrict__ a1, const int* __restrict__ a2,
           const int* __restrict__ a3, const int* __restrict__ a4,
           uint4* __restrict__ out)
{
    long idx = (long)blockIdx.x * blockDim.x + threadIdx.x;
    if (idx >= 65536L * 8) return;
    int row = (int)(idx >> 3);
    int c = (int)(idx & 7) * 4;
    long base = (long)row * 32 + c;
    uint4 m0 = X[base], m1 = X[base + 1], m2 = X[base + 2], m3 = X[base + 3];
    if (row >= 4096) {
        const int* adj; int d, li;
        if (row < 16384)      { adj = a1; d = 1; li = row - 4096; }
        else if (row < 36864) { adj = a2; d = 2; li = row - 16384; }
        else if (row < 57344) { adj = a3; d = 3; li = row - 36864; }
        else                  { adj = a4; d = 4; li = row - 57344; }
        for (int j = 0; j < d; j++) {
            long nb = (long)adj[li * d + j] * 32 + c;
            max8(m0, X[nb]);     max8(m1, X[nb + 1]);
            max8(m2, X[nb + 2]); max8(m3, X[nb + 3]);
        }
    }
    out[base] = m0; out[base + 1] = m1; out[base + 2] = m2; out[base + 3] = m3;
}

// ======================= head (+tanh fp write, warp-parallel GEMV) ===========
__global__ void head_kernel(const float* __restrict__ ssum,
                            const unsigned* __restrict__ smax,
                            const float* __restrict__ W,
                            const float* __restrict__ b,
                            float* __restrict__ soft,
                            float* __restrict__ logits,
                            float* __restrict__ out_fp)
{
    __shared__ float row[1024];
    __shared__ float lg[24];
    int bi = blockIdx.x;
    int tid = threadIdx.x, w = tid >> 5, lane = tid & 31;
    for (int c = tid; c < 1024; c += blockDim.x) {
        float v = (c < 512) ? ssum[bi * 512 + c] : funord(smax[bi * 512 + (c - 512)]);
        float t = tanhf(v);
        row[c] = t;
        out_fp[bi * 1024 + c] = t;
    }
    __syncthreads();
    // 8 warps cover 24 outputs; lane-strided k + shfl reduce
    for (int o = w; o < 24; o += 8) {
        float acc = 0.f;
        for (int k = lane; k < 1024; k += 32)
            acc += row[k] * W[k * 24 + o];
#pragma unroll
        for (int s = 16; s; s >>= 1)
            acc += __shfl_xor_sync(0xFFFFFFFFu, acc, s);
        if (lane == 0) lg[o] = acc + b[o];
    }
    __syncthreads();
    if (tid < 24) logits[bi * 24 + tid] = lg[tid];
    if (tid < 12) {
        float l0 = lg[2 * tid], l1 = lg[2 * tid + 1];
        float m  = fmaxf(l0, l1);
        float e0 = expf(l0 - m), e1 = expf(l1 - m);
        float inv = 1.f / (e0 + e1);
        soft[bi * 24 + 2 * tid]     = e0 * inv;
        soft[bi * 24 + 2 * tid + 1] = e1 * inv;
    }
}

// ======================= launch =======================
extern "C" void kernel_launch(void* const* d_in, const int* in_sizes, int n_in,
                              void* d_out, int out_size)
{
    const float* atom       = (const float*)d_in[0];
    const int*   membership = (const int*)  d_in[2];
    const int*   a1 = (const int*)d_in[4];
    const int*   a2 = (const int*)d_in[5];
    const int*   a3 = (const int*)d_in[6];
    const int*   a4 = (const int*)d_in[7];
    const float* gc1W = (const float*)d_in[8];
    const float* gc1b = (const float*)d_in[9];
    const float* gc2W = (const float*)d_in[10];
    const float* gc2b = (const float*)d_in[11];
    const float* bn1  = (const float*)d_in[12];
    const float* bn2  = (const float*)d_in[13];
    const float* bn3  = (const float*)d_in[14];
    const float* dW   = (const float*)d_in[15];
    const float* db   = (const float*)d_in[16];
    const float* hW   = (const float*)d_in[17];
    const float* hb   = (const float*)d_in[18];

    __half *atomh, *relh, *bufAh, *bufBh, *w1h, *w2h, *wdh;
    float *ssum; unsigned* smax;
    cudaGetSymbolAddress((void**)&atomh, g_atomh);
    cudaGetSymbolAddress((void**)&relh,  g_relh);
    cudaGetSymbolAddress((void**)&bufAh, g_bufAh);
    cudaGetSymbolAddress((void**)&bufBh, g_bufBh);
    cudaGetSymbolAddress((void**)&w1h,   g_w1h);
    cudaGetSymbolAddress((void**)&w2h,   g_w2h);
    cudaGetSymbolAddress((void**)&wdh,   g_wdh);
    cudaGetSymbolAddress((void**)&ssum,  g_sum);
    cudaGetSymbolAddress((void**)&smax,  g_maxu);

    cudaFuncSetAttribute(conv_gemm_t<80>, cudaFuncAttributeMaxDynamicSharedMemorySize,
                         GP<80>::SMEM);
    cudaFuncSetAttribute(conv_gemm_t<64>, cudaFuncAttributeMaxDynamicSharedMemorySize,
                         GP<64>::SMEM);
    cudaFuncSetAttribute(dense_gemm_h,    cudaFuncAttributeMaxDynamicSharedMemorySize,
                         GP<64>::SMEM);

    float* out        = (float*)d_out;
    float* out_soft   = out;
    float* out_logits = out + 1024 * 24;
    float* out_fp     = out + 2 * 1024 * 24;

    // converts + seg init (one launch)
    {
        long tot = CV_ATOM + CV_W1 + CV_W2 + CV_WD + CV_SEG;
        convert_all<<<(int)((tot + 255) / 256), 256>>>(
            atom, gc1W, gc2W, dW, atomh, w1h, w2h, wdh, ssum, smax);
    }

    // layer 1 (padded K=80; BKC=80, 1 chunk/pass)
    gather_all_h<10><<<(int)((61440L * 10 + 255) / 256), 256>>>(
        atomh, a1, a2, a3, a4, relh);
    conv_gemm_t<80><<<dim3(2, 512), 256, GP<80>::SMEM>>>(
        atomh, 80, 1, relh, w1h, gc1b, bn1, bufAh);
    pool_all_h<<<(int)((65536L * 8 + 511) / 512), 512>>>(
        (const uint4*)bufAh, a1, a2, a3, a4, (uint4*)bufBh);

    // layer 2 (K=256; BKC=64, 4 chunks/pass)
    gather_all_h<32><<<(int)((61440L * 32 + 255) / 256), 256>>>(
        bufBh, a1, a2, a3, a4, relh);
    conv_gemm_t<64><<<dim3(2, 512), 256, GP<64>::SMEM>>>(
        bufBh, 256, 4, relh, w2h, gc2b, bn2, bufAh);
    pool_all_h<<<(int)((65536L * 8 + 511) / 512), 512>>>(
        (const uint4*)bufAh, a1, a2, a3, a4, (uint4*)bufBh);

    // dense + BN3 + fused segment sum/max (BKC=64)
    dense_gemm_h<<<dim3(4, 512), 256, GP<64>::SMEM>>>(bufBh, wdh, db, bn3,
                                                      membership, ssum, smax);

    // head (+tanh fp write)
    head_kernel<<<1024, 256>>>(ssum, smax, hW, hb, out_soft, out_logits, out_fp);
}

// round 14
// speedup vs baseline: 3.9062x; 1.0572x over previous
#include <cuda_runtime.h>
#include <cuda_fp16.h>
#include <stdint.h>

#define BN_EPS 1e-3f

// Segment layout: atom rows d0 [0,4096) d1 [4096,16384) d2 [16384,36864) d3 [36864,57344) d4 [57344,65536)
// rel rows: d1 [0,12288) d2 [12288,32768) d3 [32768,53248) d4 [53248,61440)

// -------- scratch (static device globals) --------
__device__ __half   g_atomh[65536 * 80];
__device__ __half   g_relh [61440 * 256];
__device__ __half   g_bufAh[65536 * 256];
__device__ __half   g_bufBh[65536 * 256];
__device__ __half   g_w1h  [9 * 80 * 256];
__device__ __half   g_w2h  [9 * 256 * 256];
__device__ __half   g_wdh  [256 * 512];
__device__ float    g_sum  [1024 * 512];
__device__ unsigned g_maxu [1024 * 512];

// ======================= asm helpers =======================
__device__ __forceinline__ uint32_t smem_u32(const void* p) {
    uint32_t a;
    asm("{ .reg .u64 t; cvta.to.shared.u64 t, %1; cvt.u32.u64 %0, t; }" : "=r"(a) : "l"(p));
    return a;
}
__device__ __forceinline__ uint32_t pkf16(float lo, float hi) {
    uint32_t r; asm("cvt.rn.f16x2.f32 %0, %1, %2;" : "=r"(r) : "f"(hi), "f"(lo));
    return r;
}
__device__ __forceinline__ void cp16(uint32_t dst, const void* src) {
    asm volatile("cp.async.cg.shared.global [%0], [%1], 16;" :: "r"(dst), "l"(src));
}
#define CP_COMMIT() asm volatile("cp.async.commit_group;" ::: "memory")
template<int N>
__device__ __forceinline__ void cp_wait() {
    asm volatile("cp.async.wait_group %0;" :: "n"(N) : "memory");
}

__device__ __forceinline__ void ldsm_x4(uint32_t& r0, uint32_t& r1, uint32_t& r2, uint32_t& r3,
                                        uint32_t addr) {
    asm volatile("ldmatrix.sync.aligned.m8n8.x4.shared.b16 {%0,%1,%2,%3}, [%4];"
        : "=r"(r0), "=r"(r1), "=r"(r2), "=r"(r3) : "r"(addr));
}
__device__ __forceinline__ void ldsm_x2t(uint32_t& r0, uint32_t& r1, uint32_t addr) {
    asm volatile("ldmatrix.sync.aligned.m8n8.x2.trans.shared.b16 {%0,%1}, [%2];"
        : "=r"(r0), "=r"(r1) : "r"(addr));
}
__device__ __forceinline__ void mma16(float* d, const uint32_t* a, const uint32_t* b) {
    asm volatile("mma.sync.aligned.m16n8k16.row.col.f32.f16.f16.f32 "
        "{%0,%1,%2,%3}, {%4,%5,%6,%7}, {%8,%9}, {%0,%1,%2,%3};"
        : "+f"(d[0]), "+f"(d[1]), "+f"(d[2]), "+f"(d[3])
        : "r"(a[0]), "r"(a[1]), "r"(a[2]), "r"(a[3]), "r"(b[0]), "r"(b[1]));
}

__device__ __forceinline__ unsigned ford(float f) {
    unsigned u = __float_as_uint(f);
    return u ^ (unsigned)(((int)u >> 31) | 0x80000000);
}
__device__ __forceinline__ float funord(unsigned v) {
    unsigned u = (v & 0x80000000u) ? (v ^ 0x80000000u) : ~v;
    return __uint_as_float(u);
}

// ======================= GEMM pieces: 256 threads, 128x128 tile =======================
// A tile 128 x BKC (row stride BKC+8 halves), B tile BKC x 128 (row stride 136 halves).
template<int BKC> struct GP {
    static constexpr int ARH  = BKC + 8;
    static constexpr int ASTG = 128 * ARH * 2;
    static constexpr int BSTG = BKC * 136 * 2;
    static constexpr int STG  = ASTG + BSTG;
    static constexpr int NST  = (BKC == 80) ? 2 : 3;
    static constexpr int SMEM = NST * STG;
};

template<int BKC>
__device__ __forceinline__ void issue_chunk(
    uint32_t sa, uint32_t sb,
    const __half* __restrict__ A, int lda,
    const __half* __restrict__ B, int ldb, int col0, int kt, int tid)
{
    constexpr int AU   = BKC / 8;            // 16B units per A row (8 or 10)
    constexpr int ATOT = 128 * AU;
    constexpr int APT  = ATOT / 256;         // 4 or 5 per thread
#pragma unroll
    for (int h = 0; h < APT; h++) {
        int id = tid + h * 256;
        int row = id / AU, u = id % AU;
        cp16(sa + (row * GP<BKC>::ARH + u * 8) * 2, A + (long)row * lda + kt + u * 8);
    }
    constexpr int BPT = BKC * 16 / 256;      // 4 or 5 per thread
#pragma unroll
    for (int h = 0; h < BPT; h++) {
        int id = tid + h * 256;
        int row = id >> 4, u = id & 15;
        cp16(sb + (row * 136 + u * 8) * 2, B + (long)(kt + row) * ldb + col0 + u * 8);
    }
}

template<int BKC>
__device__ __forceinline__ void compute_stage(
    uint32_t sa, uint32_t sb, float acc[16][4], int wm, int wn, int lane)
{
    const int arow = lane & 15, asel = (lane >> 4) * 8;
#pragma unroll
    for (int ks = 0; ks < BKC / 16; ks++) {
        uint32_t a[4][4];
#pragma unroll
        for (int mt = 0; mt < 4; mt++) {
            int m0 = wm * 64 + mt * 16;
            ldsm_x4(a[mt][0], a[mt][1], a[mt][2], a[mt][3],
                    sa + ((m0 + arow) * GP<BKC>::ARH + ks * 16 + asel) * 2);
        }
        uint32_t b[4][2];
        int krow = ks * 16 + (lane & 15);
#pragma unroll
        for (int nt = 0; nt < 4; nt++) {
            int n0 = wn * 32 + nt * 8;
            ldsm_x2t(b[nt][0], b[nt][1], sb + (krow * 136 + n0) * 2);
        }
#pragma unroll
        for (int mt = 0; mt < 4; mt++)
#pragma unroll
            for (int nt = 0; nt < 4; nt++)
                mma16(acc[mt * 4 + nt], a[mt], b[nt]);
    }
}

// ======================= conv GEMM (fp16, 128x128 CTA, 2 CTAs/SM) ==========
template<int BKC>
__global__ void __launch_bounds__(256, 2)
conv_gemm_t(const __half* __restrict__ X, int lda, int KCH,
            const __half* __restrict__ REL,
            const __half* __restrict__ Wh,
            const float* __restrict__ bz,
            const float* __restrict__ bnp,
            __half* __restrict__ Y)
{
    constexpr int NST = GP<BKC>::NST;
    extern __shared__ char dyn[];
    const uint32_t sa0 = smem_u32(dyn);
    __shared__ float s_sc[128], s_sh[128], s_bi[128];

    const int tid = threadIdx.x;
    const int lane = tid & 31, wid = tid >> 5;
    const int gid = lane >> 2, tig = lane & 3;
    const int wm = wid & 1, wn = wid >> 1;
    const int row0 = blockIdx.y * 128;
    const int col0 = blockIdx.x * 128;
    const int d = (row0 < 4096) ? 0 : (row0 < 16384) ? 1 : (row0 < 36864) ? 2
                : (row0 < 57344) ? 3 : 4;

    if (tid < 128) {
        int c = col0 + tid;
        float bias = (d == 0) ? bz[8 * 256 + c]
                              : bz[(2 * d - 2) * 256 + c] + bz[(2 * d - 1) * 256 + c];
        float gg = bnp[c], be = bnp[256 + c], mu = bnp[512 + c], va = bnp[768 + c];
        float sc = gg * rsqrtf(va + BN_EPS);
        s_sc[tid] = sc; s_sh[tid] = be - mu * sc; s_bi[tid] = bias;
    }

    const long wsz = (long)lda * 256;
    const __half* A0 = X + (long)row0 * lda;
    const __half* W0 = Wh + ((d == 0) ? 8 : (2 * d - 1)) * wsz;
    const __half* A1 = (d > 0) ? REL + (long)(row0 - 4096) * lda : A0;
    const __half* W1 = (d > 0) ? Wh + (2 * d - 2) * wsz : W0;
    const int T = ((d > 0) ? 2 : 1) * KCH;

    float acc[16][4];
#pragma unroll
    for (int i = 0; i < 16; i++)
        acc[i][0] = acc[i][1] = acc[i][2] = acc[i][3] = 0.f;

#pragma unroll
    for (int c = 0; c < NST - 1; c++) {
        if (c < T) {
            int pass = (c >= KCH), kc = c - pass * KCH;
            uint32_t sbase = sa0 + (c % NST) * GP<BKC>::STG;
            issue_chunk<BKC>(sbase, sbase + GP<BKC>::ASTG,
                             pass ? A1 : A0, lda, pass ? W1 : W0, 256, col0, kc * BKC, tid);
        }
        CP_COMMIT();
    }

    for (int c = 0; c < T; c++) {
        cp_wait<NST - 2>();
        __syncthreads();
        int n = c + NST - 1;
        if (n < T) {
            int pass = (n >= KCH), kc = n - pass * KCH;
            uint32_t sbase = sa0 + (n % NST) * GP<BKC>::STG;
            issue_chunk<BKC>(sbase, sbase + GP<BKC>::ASTG,
                             pass ? A1 : A0, lda, pass ? W1 : W0, 256, col0, kc * BKC, tid);
        }
        CP_COMMIT();
        uint32_t sbase = sa0 + (c % NST) * GP<BKC>::STG;
        compute_stage<BKC>(sbase, sbase + GP<BKC>::ASTG, acc, wm, wn, lane);
    }
    __syncthreads();

#pragma unroll
    for (int mt = 0; mt < 4; mt++) {
#pragma unroll
        for (int nt = 0; nt < 4; nt++) {
            int cl = wn * 32 + nt * 8 + tig * 2;
            int r = row0 + wm * 64 + mt * 16 + gid;
            float* a4 = acc[mt * 4 + nt];
            float sc0 = s_sc[cl], sc1 = s_sc[cl + 1];
            float sh0 = s_sh[cl], sh1 = s_sh[cl + 1];
            float bi0 = s_bi[cl], bi1 = s_bi[cl + 1];
            float x0 = fmaxf(a4[0] + bi0, 0.f) * sc0 + sh0;
            float x1 = fmaxf(a4[1] + bi1, 0.f) * sc1 + sh1;
            *reinterpret_cast<uint32_t*>(&Y[(long)r * 256 + col0 + cl]) = pkf16(x0, x1);
            x0 = fmaxf(a4[2] + bi0, 0.f) * sc0 + sh0;
            x1 = fmaxf(a4[3] + bi1, 0.f) * sc1 + sh1;
            *reinterpret_cast<uint32_t*>(&Y[(long)(r + 8) * 256 + col0 + cl]) = pkf16(x0, x1);
        }
    }
}

// ======================= dense GEMM + fused segment reduce (BKC=64) ==========
__global__ void __launch_bounds__(256, 2)
dense_gemm_h(const __half* __restrict__ X,     // (65536, 256)
             const __half* __restrict__ Wh,    // (256, 512)
             const float* __restrict__ bz,
             const float* __restrict__ bnp,
             const int* __restrict__ mem,
             float* __restrict__ ssum,
             unsigned* __restrict__ smax)
{
    constexpr int BKC = 64;
    constexpr int NST = GP<BKC>::NST;
    extern __shared__ char dyn[];
    const uint32_t sa0 = smem_u32(dyn);
    __shared__ float s_sc[128], s_sh[128], s_bi[128];

    const int tid = threadIdx.x;
    const int lane = tid & 31, wid = tid >> 5;
    const int gid = lane >> 2, tig = lane & 3;
    const int wm = wid & 1, wn = wid >> 1;
    const int row0 = blockIdx.y * 128;
    const int col0 = blockIdx.x * 128;
    const int T = 4;

    if (tid < 128) {
        int c = col0 + tid;
        float gg = bnp[c], be = bnp[512 + c], mu = bnp[1024 + c], va = bnp[1536 + c];
        float sc = gg * rsqrtf(va + BN_EPS);
        s_sc[tid] = sc; s_sh[tid] = be - mu * sc; s_bi[tid] = bz[c];
    }

    const __half* A = X + (long)row0 * 256;
    float acc[16][4];
#pragma unroll
    for (int i = 0; i < 16; i++)
        acc[i][0] = acc[i][1] = acc[i][2] = acc[i][3] = 0.f;

#pragma unroll
    for (int c = 0; c < NST - 1; c++) {
        if (c < T) {
            uint32_t sbase = sa0 + (c % NST) * GP<BKC>::STG;
            issue_chunk<BKC>(sbase, sbase + GP<BKC>::ASTG, A, 256, Wh, 512, col0,
                             c * BKC, tid);
        }
        CP_COMMIT();
    }
    for (int c = 0; c < T; c++) {
        cp_wait<NST - 2>();
        __syncthreads();
        int n = c + NST - 1;
        if (n < T) {
            uint32_t sbase = sa0 + (n % NST) * GP<BKC>::STG;
            issue_chunk<BKC>(sbase, sbase + GP<BKC>::ASTG, A, 256, Wh, 512, col0,
                             n * BKC, tid);
        }
        CP_COMMIT();
        uint32_t sbase = sa0 + (c % NST) * GP<BKC>::STG;
        compute_stage<BKC>(sbase, sbase + GP<BKC>::ASTG, acc, wm, wn, lane);
    }
    __syncthreads();

    // fused epilogue: BN3(relu(.)) + atomic segment sum/max
#pragma unroll
    for (int mt = 0; mt < 4; mt++) {
        int r = row0 + wm * 64 + mt * 16 + gid;
        int m0 = mem[r] * 512, m1 = mem[r + 8] * 512;
#pragma unroll
        for (int nt = 0; nt < 4; nt++) {
            int cl = wn * 32 + nt * 8 + tig * 2;
            int gc = col0 + cl;
            float* a4 = acc[mt * 4 + nt];
            float sc0 = s_sc[cl], sc1 = s_sc[cl + 1];
            float sh0 = s_sh[cl], sh1 = s_sh[cl + 1];
            float bi0 = s_bi[cl], bi1 = s_bi[cl + 1];
            float x00 = fmaxf(a4[0] + bi0, 0.f) * sc0 + sh0;
            float x01 = fmaxf(a4[1] + bi1, 0.f) * sc1 + sh1;
            float x10 = fmaxf(a4[2] + bi0, 0.f) * sc0 + sh0;
            float x11 = fmaxf(a4[3] + bi1, 0.f) * sc1 + sh1;
            atomicAdd(&ssum[m0 + gc],     x00);
            atomicAdd(&ssum[m0 + gc + 1], x01);
            atomicAdd(&ssum[m1 + gc],     x10);
            atomicAdd(&ssum[m1 + gc + 1], x11);
            atomicMax(&smax[m0 + gc],     ford(x00));
            atomicMax(&smax[m0 + gc + 1], ford(x01));
            atomicMax(&smax[m1 + gc],     ford(x10));
            atomicMax(&smax[m1 + gc + 1], ford(x11));
        }
    }
}

// ======================= merged converts + seg init =======================
#define CV_ATOM (65536L * 80)
#define CV_W1   (9L * 80 * 256)
#define CV_W2   (9L * 256 * 256)
#define CV_WD   (256L * 512)
#define CV_SEG  (1024L * 512)
__global__ void convert_all(const float* __restrict__ atomf,
                            const float* __restrict__ w1f,
                            const float* __restrict__ w2f,
                            const float* __restrict__ wdf,
                            __half* __restrict__ atomh, __half* __restrict__ w1h,
                            __half* __restrict__ w2h,   __half* __restrict__ wdh,
                            float* __restrict__ ssum,   unsigned* __restrict__ smax)
{
    long idx = (long)blockIdx.x * blockDim.x + threadIdx.x;
    if (idx < CV_ATOM) {
        int row = (int)(idx / 80), k = (int)(idx - (long)row * 80);
        atomh[idx] = (k < 75) ? __float2half(atomf[(long)row * 75 + k]) : __half(0.f);
        return;
    }
    idx -= CV_ATOM;
    if (idx < CV_W1) {
        int n = (int)(idx & 255);
        long t = idx >> 8;
        int k = (int)(t % 80), gg = (int)(t / 80);
        w1h[idx] = (k < 75) ? __float2half(w1f[((long)gg * 75 + k) * 256 + n]) : __half(0.f);
        return;
    }
    idx -= CV_W1;
    if (idx < CV_W2) { w2h[idx] = __float2half(w2f[idx]); return; }
    idx -= CV_W2;
    if (idx < CV_WD) { wdh[idx] = __float2half(wdf[idx]); return; }
    idx -= CV_WD;
    if (idx < CV_SEG) { ssum[idx] = 0.f; smax[idx] = 0x007FFFFFu; }
}

// ======================= gather / pool =======================
__device__ __forceinline__ void acc8(float2 s[4], uint4 v) {
    s[0].x += __low2float(*(__half2*)&v.x);  s[0].y += __high2float(*(__half2*)&v.x);
    s[1].x += __low2float(*(__half2*)&v.y);  s[1].y += __high2float(*(__half2*)&v.y);
    s[2].x += __low2float(*(__half2*)&v.z);  s[2].y += __high2float(*(__half2*)&v.z);
    s[3].x += __low2float(*(__half2*)&v.w);  s[3].y += __high2float(*(__half2*)&v.w);
}

template<int CH>
__global__ void gather_all_h(const __half* __restrict__ X,
                             const int* __restrict__ a1, const int* __restrict__ a2,
                             const int* __restrict__ a3, const int* __restrict__ a4,
                             __half* __restrict__ out)
{
    constexpr int LD = CH * 8;
    long idx = (long)blockIdx.x * blockDim.x + threadIdx.x;
    if (idx >= 61440L * CH) return;
    int i = (int)(idx / CH);
    int c = (int)(idx - (long)i * CH) * 8;
    const int* adj; int d, li;
    if (i < 12288)      { adj = a1; d = 1; li = i; }
    else if (i < 32768) { adj = a2; d = 2; li = i - 12288; }
    else if (i < 53248) { adj = a3; d = 3; li = i - 32768; }
    else                { adj = a4; d = 4; li = i - 53248; }
    float2 s[4];
    s[0] = s[1] = s[2] = s[3] = make_float2(0.f, 0.f);
    for (int j = 0; j < d; j++) {
        uint4 v = *reinterpret_cast<const uint4*>(X + (long)adj[li * d + j] * LD + c);
        acc8(s, v);
    }
    uint4 o;
    o.x = pkf16(s[0].x, s[0].y); o.y = pkf16(s[1].x, s[1].y);
    o.z = pkf16(s[2].x, s[2].y); o.w = pkf16(s[3].x, s[3].y);
    *reinterpret_cast<uint4*>(out + (long)i * LD + c) = o;
}

__device__ __forceinline__ void max8(uint4& m, uint4 v) {
    *(__half2*)&m.x = __hmax2(*(__half2*)&m.x, *(__half2*)&v.x);
    *(__half2*)&m.y = __hmax2(*(__half2*)&m.y, *(__half2*)&v.y);
    *(__half2*)&m.z = __hmax2(*(__half2*)&m.z, *(__half2*)&v.z);
    *(__half2*)&m.w = __hmax2(*(__half2*)&m.w, *(__half2*)&v.w);
}

// 32 halves (2 x uint4) per thread; 16 threads per 256-col row (R12 config: at DRAM floor)
__global__ void pool_all_h(const uint4* __restrict__ X,   // (65536, 32) of 8-half
                           const int* __restrict__ a1, const int* __restrict__ a2,
                           const int* __restrict__ a3, const int* __restrict__ a4,
                           uint4* __restrict__ out)
{
    long idx = (long)blockIdx.x * blockDim.x + threadIdx.x;
    if (idx >= 65536L * 16) return;
    int row = (int)(idx >> 4);
    int c = (int)(idx & 15) * 2;
    long base = (long)row * 32 + c;
    uint4 m0 = X[base], m1 = X[base + 1];
    if (row >= 4096) {
        const int* adj; int d, li;
        if (row < 16384)      { adj = a1; d = 1; li = row - 4096; }
        else if (row < 36864) { adj = a2; d = 2; li = row - 16384; }
        else if (row < 57344) { adj = a3; d = 3; li = row - 36864; }
        else                  { adj = a4; d = 4; li = row - 57344; }
        for (int j = 0; j < d; j++) {
            long nb = (long)adj[li * d + j] * 32 + c;
            max8(m0, X[nb]);
            max8(m1, X[nb + 1]);
        }
    }
    out[base] = m0;
    out[base + 1] = m1;
}

// ======================= head (+tanh fp write, warp-parallel GEMV) ===========
__global__ void head_kernel(const float* __restrict__ ssum,
                            const unsigned* __restrict__ smax,
                            const float* __restrict__ W,
                            const float* __restrict__ b,
                            float* __restrict__ soft,
                            float* __restrict__ logits,
                            float* __restrict__ out_fp)
{
    __shared__ float row[1024];
    __shared__ float lg[24];
    int bi = blockIdx.x;
    int tid = threadIdx.x, w = tid >> 5, lane = tid & 31;
    for (int c = tid; c < 1024; c += blockDim.x) {
        float v = (c < 512) ? ssum[bi * 512 + c] : funord(smax[bi * 512 + (c - 512)]);
        float t = tanhf(v);
        row[c] = t;
        out_fp[bi * 1024 + c] = t;
    }
    __syncthreads();
    for (int o = w; o < 24; o += 8) {
        float acc = 0.f;
        for (int k = lane; k < 1024; k += 32)
            acc += row[k] * W[k * 24 + o];
#pragma unroll
        for (int s = 16; s; s >>= 1)
            acc += __shfl_xor_sync(0xFFFFFFFFu, acc, s);
        if (lane == 0) lg[o] = acc + b[o];
    }
    __syncthreads();
    if (tid < 24) logits[bi * 24 + tid] = lg[tid];
    if (tid < 12) {
        float l0 = lg[2 * tid], l1 = lg[2 * tid + 1];
        float m  = fmaxf(l0, l1);
        float e0 = expf(l0 - m), e1 = expf(l1 - m);
        float inv = 1.f / (e0 + e1);
        soft[bi * 24 + 2 * tid]     = e0 * inv;
        soft[bi * 24 + 2 * tid + 1] = e1 * inv;
    }
}

// ======================= launch =======================
extern "C" void kernel_launch(void* const* d_in, const int* in_sizes, int n_in,
                              void* d_out, int out_size)
{
    const float* atom       = (const float*)d_in[0];
    const int*   membership = (const int*)  d_in[2];
    const int*   a1 = (const int*)d_in[4];
    const int*   a2 = (const int*)d_in[5];
    const int*   a3 = (const int*)d_in[6];
    const int*   a4 = (const int*)d_in[7];
    const float* gc1W = (const float*)d_in[8];
    const float* gc1b = (const float*)d_in[9];
    const float* gc2W = (const float*)d_in[10];
    const float* gc2b = (const float*)d_in[11];
    const float* bn1  = (const float*)d_in[12];
    const float* bn2  = (const float*)d_in[13];
    const float* bn3  = (const float*)d_in[14];
    const float* dW   = (const float*)d_in[15];
    const float* db   = (const float*)d_in[16];
    const float* hW   = (const float*)d_in[17];
    const float* hb   = (const float*)d_in[18];

    __half *atomh, *relh, *bufAh, *bufBh, *w1h, *w2h, *wdh;
    float *ssum; unsigned* smax;
    cudaGetSymbolAddress((void**)&atomh, g_atomh);
    cudaGetSymbolAddress((void**)&relh,  g_relh);
    cudaGetSymbolAddress((void**)&bufAh, g_bufAh);
    cudaGetSymbolAddress((void**)&bufBh, g_bufBh);
    cudaGetSymbolAddress((void**)&w1h,   g_w1h);
    cudaGetSymbolAddress((void**)&w2h,   g_w2h);
    cudaGetSymbolAddress((void**)&wdh,   g_wdh);
    cudaGetSymbolAddress((void**)&ssum,  g_sum);
    cudaGetSymbolAddress((void**)&smax,  g_maxu);

    cudaFuncSetAttribute(conv_gemm_t<80>, cudaFuncAttributeMaxDynamicSharedMemorySize,
                         GP<80>::SMEM);
    cudaFuncSetAttribute(conv_gemm_t<64>, cudaFuncAttributeMaxDynamicSharedMemorySize,
                         GP<64>::SMEM);
    cudaFuncSetAttribute(dense_gemm_h,    cudaFuncAttributeMaxDynamicSharedMemorySize,
                         GP<64>::SMEM);

    float* out        = (float*)d_out;
    float* out_soft   = out;
    float* out_logits = out + 1024 * 24;
    float* out_fp     = out + 2 * 1024 * 24;

    // converts + seg init (one launch)
    {
        long tot = CV_ATOM + CV_W1 + CV_W2 + CV_WD + CV_SEG;
        convert_all<<<(int)((tot + 255) / 256), 256>>>(
            atom, gc1W, gc2W, dW, atomh, w1h, w2h, wdh, ssum, smax);
    }

    // layer 1 (padded K=80; BKC=80, 1 chunk/pass)
    gather_all_h<10><<<(int)((61440L * 10 + 255) / 256), 256>>>(
        atomh, a1, a2, a3, a4, relh);
    conv_gemm_t<80><<<dim3(2, 512), 256, GP<80>::SMEM>>>(
        atomh, 80, 1, relh, w1h, gc1b, bn1, bufAh);
    pool_all_h<<<(int)((65536L * 16 + 255) / 256), 256>>>(
        (const uint4*)bufAh, a1, a2, a3, a4, (uint4*)bufBh);

    // layer 2 (K=256; BKC=64, 4 chunks/pass)
    gather_all_h<32><<<(int)((61440L * 32 + 255) / 256), 256>>>(
        bufBh, a1, a2, a3, a4, relh);
    conv_gemm_t<64><<<dim3(2, 512), 256, GP<64>::SMEM>>>(
        bufBh, 256, 4, relh, w2h, gc2b, bn2, bufAh);
    pool_all_h<<<(int)((65536L * 16 + 255) / 256), 256>>>(
        (const uint4*)bufAh, a1, a2, a3, a4, (uint4*)bufBh);

    // dense + BN3 + fused segment sum/max (BKC=64)
    dense_gemm_h<<<dim3(4, 512), 256, GP<64>::SMEM>>>(bufBh, wdh, db, bn3,
                                                      membership, ssum, smax);

    // head (+tanh fp write)
    head_kernel<<<1024, 256>>>(ssum, smax, hW, hb, out_soft, out_logits, out_fp);
}

// round 15
// speedup vs baseline: 4.0182x; 1.0287x over previous
#include <cuda_runtime.h>
#include <cuda_fp16.h>
#include <stdint.h>

#define BN_EPS 1e-3f

// Segment layout: atom rows d0 [0,4096) d1 [4096,16384) d2 [16384,36864) d3 [36864,57344) d4 [57344,65536)
// rel rows: d1 [0,12288) d2 [12288,32768) d3 [32768,53248) d4 [53248,61440)

// -------- scratch (static device globals) --------
__device__ __half   g_atomh[65536 * 80];
__device__ __half   g_relh [61440 * 256];
__device__ __half   g_bufAh[65536 * 256];
__device__ __half   g_bufBh[65536 * 256];
__device__ __half   g_w1h  [9 * 80 * 256];
__device__ __half   g_w2h  [9 * 256 * 256];
__device__ __half   g_wdh  [256 * 512];
__device__ float    g_sum  [1024 * 512];
__device__ unsigned g_maxu [1024 * 512];

// ======================= asm helpers =======================
__device__ __forceinline__ uint32_t smem_u32(const void* p) {
    uint32_t a;
    asm("{ .reg .u64 t; cvta.to.shared.u64 t, %1; cvt.u32.u64 %0, t; }" : "=r"(a) : "l"(p));
    return a;
}
__device__ __forceinline__ uint32_t pkf16(float lo, float hi) {
    uint32_t r; asm("cvt.rn.f16x2.f32 %0, %1, %2;" : "=r"(r) : "f"(hi), "f"(lo));
    return r;
}
__device__ __forceinline__ void cp16(uint32_t dst, const void* src) {
    asm volatile("cp.async.cg.shared.global [%0], [%1], 16;" :: "r"(dst), "l"(src));
}
#define CP_COMMIT() asm volatile("cp.async.commit_group;" ::: "memory")
template<int N>
__device__ __forceinline__ void cp_wait() {
    asm volatile("cp.async.wait_group %0;" :: "n"(N) : "memory");
}

__device__ __forceinline__ void ldsm_x4(uint32_t& r0, uint32_t& r1, uint32_t& r2, uint32_t& r3,
                                        uint32_t addr) {
    asm volatile("ldmatrix.sync.aligned.m8n8.x4.shared.b16 {%0,%1,%2,%3}, [%4];"
        : "=r"(r0), "=r"(r1), "=r"(r2), "=r"(r3) : "r"(addr));
}
__device__ __forceinline__ void ldsm_x2t(uint32_t& r0, uint32_t& r1, uint32_t addr) {
    asm volatile("ldmatrix.sync.aligned.m8n8.x2.trans.shared.b16 {%0,%1}, [%2];"
        : "=r"(r0), "=r"(r1) : "r"(addr));
}
__device__ __forceinline__ void mma16(float* d, const uint32_t* a, const uint32_t* b) {
    asm volatile("mma.sync.aligned.m16n8k16.row.col.f32.f16.f16.f32 "
        "{%0,%1,%2,%3}, {%4,%5,%6,%7}, {%8,%9}, {%0,%1,%2,%3};"
        : "+f"(d[0]), "+f"(d[1]), "+f"(d[2]), "+f"(d[3])
        : "r"(a[0]), "r"(a[1]), "r"(a[2]), "r"(a[3]), "r"(b[0]), "r"(b[1]));
}

__device__ __forceinline__ unsigned ford(float f) {
    unsigned u = __float_as_uint(f);
    return u ^ (unsigned)(((int)u >> 31) | 0x80000000);
}
__device__ __forceinline__ float funord(unsigned v) {
    unsigned u = (v & 0x80000000u) ? (v ^ 0x80000000u) : ~v;
    return __uint_as_float(u);
}

// ======================= GEMM pieces: 256 threads, 128x128 tile =======================
template<int BKC> struct GP {
    static constexpr int ARH  = BKC + 8;
    static constexpr int ASTG = 128 * ARH * 2;
    static constexpr int BSTG = BKC * 136 * 2;
    static constexpr int STG  = ASTG + BSTG;
    static constexpr int NST  = (BKC == 80) ? 2 : 3;
    static constexpr int SMEM = NST * STG;
};

template<int BKC>
__device__ __forceinline__ void issue_chunk(
    uint32_t sa, uint32_t sb,
    const __half* __restrict__ A, int lda,
    const __half* __restrict__ B, int ldb, int col0, int kt, int tid)
{
    constexpr int AU   = BKC / 8;
    constexpr int ATOT = 128 * AU;
    constexpr int APT  = ATOT / 256;
#pragma unroll
    for (int h = 0; h < APT; h++) {
        int id = tid + h * 256;
        int row = id / AU, u = id % AU;
        cp16(sa + (row * GP<BKC>::ARH + u * 8) * 2, A + (long)row * lda + kt + u * 8);
    }
    constexpr int BPT = BKC * 16 / 256;
#pragma unroll
    for (int h = 0; h < BPT; h++) {
        int id = tid + h * 256;
        int row = id >> 4, u = id & 15;
        cp16(sb + (row * 136 + u * 8) * 2, B + (long)(kt + row) * ldb + col0 + u * 8);
    }
}

template<int BKC>
__device__ __forceinline__ void compute_stage(
    uint32_t sa, uint32_t sb, float acc[16][4], int wm, int wn, int lane)
{
    const int arow = lane & 15, asel = (lane >> 4) * 8;
#pragma unroll
    for (int ks = 0; ks < BKC / 16; ks++) {
        uint32_t a[4][4];
#pragma unroll
        for (int mt = 0; mt < 4; mt++) {
            int m0 = wm * 64 + mt * 16;
            ldsm_x4(a[mt][0], a[mt][1], a[mt][2], a[mt][3],
                    sa + ((m0 + arow) * GP<BKC>::ARH + ks * 16 + asel) * 2);
        }
        uint32_t b[4][2];
        int krow = ks * 16 + (lane & 15);
#pragma unroll
        for (int nt = 0; nt < 4; nt++) {
            int n0 = wn * 32 + nt * 8;
            ldsm_x2t(b[nt][0], b[nt][1], sb + (krow * 136 + n0) * 2);
        }
#pragma unroll
        for (int mt = 0; mt < 4; mt++)
#pragma unroll
            for (int nt = 0; nt < 4; nt++)
                mma16(acc[mt * 4 + nt], a[mt], b[nt]);
    }
}

// ======================= conv GEMM (fp16, 128x128 CTA, 2 CTAs/SM) ==========
template<int BKC>
__global__ void __launch_bounds__(256, 2)
conv_gemm_t(const __half* __restrict__ X, int lda, int KCH,
            const __half* __restrict__ REL,
            const __half* __restrict__ Wh,
            const float* __restrict__ bz,
            const float* __restrict__ bnp,
            __half* __restrict__ Y)
{
    constexpr int NST = GP<BKC>::NST;
    extern __shared__ char dyn[];
    const uint32_t sa0 = smem_u32(dyn);
    __shared__ float s_sc[128], s_sh[128], s_bi[128];

    const int tid = threadIdx.x;
    const int lane = tid & 31, wid = tid >> 5;
    const int gid = lane >> 2, tig = lane & 3;
    const int wm = wid & 1, wn = wid >> 1;
    const int row0 = blockIdx.y * 128;
    const int col0 = blockIdx.x * 128;
    const int d = (row0 < 4096) ? 0 : (row0 < 16384) ? 1 : (row0 < 36864) ? 2
                : (row0 < 57344) ? 3 : 4;

    if (tid < 128) {
        int c = col0 + tid;
        float bias = (d == 0) ? bz[8 * 256 + c]
                              : bz[(2 * d - 2) * 256 + c] + bz[(2 * d - 1) * 256 + c];
        float gg = bnp[c], be = bnp[256 + c], mu = bnp[512 + c], va = bnp[768 + c];
        float sc = gg * rsqrtf(va + BN_EPS);
        s_sc[tid] = sc; s_sh[tid] = be - mu * sc; s_bi[tid] = bias;
    }

    const long wsz = (long)lda * 256;
    const __half* A0 = X + (long)row0 * lda;
    const __half* W0 = Wh + ((d == 0) ? 8 : (2 * d - 1)) * wsz;
    const __half* A1 = (d > 0) ? REL + (long)(row0 - 4096) * lda : A0;
    const __half* W1 = (d > 0) ? Wh + (2 * d - 2) * wsz : W0;
    const int T = ((d > 0) ? 2 : 1) * KCH;

    float acc[16][4];
#pragma unroll
    for (int i = 0; i < 16; i++)
        acc[i][0] = acc[i][1] = acc[i][2] = acc[i][3] = 0.f;

    if constexpr (BKC == 80) {
        // conv1 specialized path: T in {1,2}, NST=2; issue ALL chunks upfront
        issue_chunk<BKC>(sa0, sa0 + GP<BKC>::ASTG, A0, lda, W0, 256, col0, 0, tid);
        CP_COMMIT();
        if (T == 2) {
            uint32_t sb1 = sa0 + GP<BKC>::STG;
            issue_chunk<BKC>(sb1, sb1 + GP<BKC>::ASTG, A1, lda, W1, 256, col0, 0, tid);
            CP_COMMIT();
            cp_wait<1>();
            __syncthreads();
            compute_stage<BKC>(sa0, sa0 + GP<BKC>::ASTG, acc, wm, wn, lane);
            cp_wait<0>();
            __syncthreads();
            compute_stage<BKC>(sb1, sb1 + GP<BKC>::ASTG, acc, wm, wn, lane);
        } else {
            cp_wait<0>();
            __syncthreads();
            compute_stage<BKC>(sa0, sa0 + GP<BKC>::ASTG, acc, wm, wn, lane);
        }
    } else {
#pragma unroll
        for (int c = 0; c < NST - 1; c++) {
            if (c < T) {
                int pass = (c >= KCH), kc = c - pass * KCH;
                uint32_t sbase = sa0 + (c % NST) * GP<BKC>::STG;
                issue_chunk<BKC>(sbase, sbase + GP<BKC>::ASTG,
                                 pass ? A1 : A0, lda, pass ? W1 : W0, 256, col0,
                                 kc * BKC, tid);
            }
            CP_COMMIT();
        }
        for (int c = 0; c < T; c++) {
            cp_wait<NST - 2>();
            __syncthreads();
            int n = c + NST - 1;
            if (n < T) {
                int pass = (n >= KCH), kc = n - pass * KCH;
                uint32_t sbase = sa0 + (n % NST) * GP<BKC>::STG;
                issue_chunk<BKC>(sbase, sbase + GP<BKC>::ASTG,
                                 pass ? A1 : A0, lda, pass ? W1 : W0, 256, col0,
                                 kc * BKC, tid);
            }
            CP_COMMIT();
            uint32_t sbase = sa0 + (c % NST) * GP<BKC>::STG;
            compute_stage<BKC>(sbase, sbase + GP<BKC>::ASTG, acc, wm, wn, lane);
        }
    }
    __syncthreads();

#pragma unroll
    for (int mt = 0; mt < 4; mt++) {
#pragma unroll
        for (int nt = 0; nt < 4; nt++) {
            int cl = wn * 32 + nt * 8 + tig * 2;
            int r = row0 + wm * 64 + mt * 16 + gid;
            float* a4 = acc[mt * 4 + nt];
            float sc0 = s_sc[cl], sc1 = s_sc[cl + 1];
            float sh0 = s_sh[cl], sh1 = s_sh[cl + 1];
            float bi0 = s_bi[cl], bi1 = s_bi[cl + 1];
            float x0 = fmaxf(a4[0] + bi0, 0.f) * sc0 + sh0;
            float x1 = fmaxf(a4[1] + bi1, 0.f) * sc1 + sh1;
            *reinterpret_cast<uint32_t*>(&Y[(long)r * 256 + col0 + cl]) = pkf16(x0, x1);
            x0 = fmaxf(a4[2] + bi0, 0.f) * sc0 + sh0;
            x1 = fmaxf(a4[3] + bi1, 0.f) * sc1 + sh1;
            *reinterpret_cast<uint32_t*>(&Y[(long)(r + 8) * 256 + col0 + cl]) = pkf16(x0, x1);
        }
    }
}

// ======================= dense GEMM + fused segment reduce (BKC=64) ==========
__global__ void __launch_bounds__(256, 2)
dense_gemm_h(const __half* __restrict__ X,
             const __half* __restrict__ Wh,
             const float* __restrict__ bz,
             const float* __restrict__ bnp,
             const int* __restrict__ mem,
             float* __restrict__ ssum,
             unsigned* __restrict__ smax)
{
    constexpr int BKC = 64;
    constexpr int NST = GP<BKC>::NST;
    extern __shared__ char dyn[];
    const uint32_t sa0 = smem_u32(dyn);
    __shared__ float s_sc[128], s_sh[128], s_bi[128];

    const int tid = threadIdx.x;
    const int lane = tid & 31, wid = tid >> 5;
    const int gid = lane >> 2, tig = lane & 3;
    const int wm = wid & 1, wn = wid >> 1;
    const int row0 = blockIdx.y * 128;
    const int col0 = blockIdx.x * 128;
    const int T = 4;

    if (tid < 128) {
        int c = col0 + tid;
        float gg = bnp[c], be = bnp[512 + c], mu = bnp[1024 + c], va = bnp[1536 + c];
        float sc = gg * rsqrtf(va + BN_EPS);
        s_sc[tid] = sc; s_sh[tid] = be - mu * sc; s_bi[tid] = bz[c];
    }

    const __half* A = X + (long)row0 * 256;
    float acc[16][4];
#pragma unroll
    for (int i = 0; i < 16; i++)
        acc[i][0] = acc[i][1] = acc[i][2] = acc[i][3] = 0.f;

#pragma unroll
    for (int c = 0; c < NST - 1; c++) {
        if (c < T) {
            uint32_t sbase = sa0 + (c % NST) * GP<BKC>::STG;
            issue_chunk<BKC>(sbase, sbase + GP<BKC>::ASTG, A, 256, Wh, 512, col0,
                             c * BKC, tid);
        }
        CP_COMMIT();
    }
    for (int c = 0; c < T; c++) {
        cp_wait<NST - 2>();
        __syncthreads();
        int n = c + NST - 1;
        if (n < T) {
            uint32_t sbase = sa0 + (n % NST) * GP<BKC>::STG;
            issue_chunk<BKC>(sbase, sbase + GP<BKC>::ASTG, A, 256, Wh, 512, col0,
                             n * BKC, tid);
        }
        CP_COMMIT();
        uint32_t sbase = sa0 + (c % NST) * GP<BKC>::STG;
        compute_stage<BKC>(sbase, sbase + GP<BKC>::ASTG, acc, wm, wn, lane);
    }
    __syncthreads();

#pragma unroll
    for (int mt = 0; mt < 4; mt++) {
        int r = row0 + wm * 64 + mt * 16 + gid;
        int m0 = mem[r] * 512, m1 = mem[r + 8] * 512;
#pragma unroll
        for (int nt = 0; nt < 4; nt++) {
            int cl = wn * 32 + nt * 8 + tig * 2;
            int gc = col0 + cl;
            float* a4 = acc[mt * 4 + nt];
            float sc0 = s_sc[cl], sc1 = s_sc[cl + 1];
            float sh0 = s_sh[cl], sh1 = s_sh[cl + 1];
            float bi0 = s_bi[cl], bi1 = s_bi[cl + 1];
            float x00 = fmaxf(a4[0] + bi0, 0.f) * sc0 + sh0;
            float x01 = fmaxf(a4[1] + bi1, 0.f) * sc1 + sh1;
            float x10 = fmaxf(a4[2] + bi0, 0.f) * sc0 + sh0;
            float x11 = fmaxf(a4[3] + bi1, 0.f) * sc1 + sh1;
            atomicAdd(&ssum[m0 + gc],     x00);
            atomicAdd(&ssum[m0 + gc + 1], x01);
            atomicAdd(&ssum[m1 + gc],     x10);
            atomicAdd(&ssum[m1 + gc + 1], x11);
            atomicMax(&smax[m0 + gc],     ford(x00));
            atomicMax(&smax[m0 + gc + 1], ford(x01));
            atomicMax(&smax[m1 + gc],     ford(x10));
            atomicMax(&smax[m1 + gc + 1], ford(x11));
        }
    }
}

// ======================= vectorized converts + seg init (8 outs/thread) ========
#define V_ATOM (65536L * 10)   // vec8 over 80 cols
#define V_W1   (9L * 80 * 32)  // vec8 over 256 cols
#define V_W2   (9L * 256 * 32)
#define V_WD   (256L * 64)
#define V_SEG  (1024L * 128)   // vec4 over 512 cols
__global__ void convert_all(const float* __restrict__ atomf,
                            const float* __restrict__ w1f,
                            const float* __restrict__ w2f,
                            const float* __restrict__ wdf,
                            __half* __restrict__ atomh, __half* __restrict__ w1h,
                            __half* __restrict__ w2h,   __half* __restrict__ wdh,
                            float* __restrict__ ssum,   unsigned* __restrict__ smax)
{
    long v = (long)blockIdx.x * blockDim.x + threadIdx.x;
    if (v < V_ATOM) {
        int row = (int)(v / 10), u = (int)(v - (long)row * 10);
        int k0 = u * 8;
        const float* src = atomf + (long)row * 75 + k0;
        uint32_t p[4];
#pragma unroll
        for (int q = 0; q < 4; q++) {
            float lo = (k0 + 2 * q     < 75) ? src[2 * q]     : 0.f;
            float hi = (k0 + 2 * q + 1 < 75) ? src[2 * q + 1] : 0.f;
            p[q] = pkf16(lo, hi);
        }
        *reinterpret_cast<uint4*>(atomh + (long)row * 80 + k0) =
            make_uint4(p[0], p[1], p[2], p[3]);
        return;
    }
    v -= V_ATOM;
    if (v < V_W1) {
        int n0 = (int)(v & 31) * 8;
        long t = v >> 5;
        int k = (int)(t % 80), g = (int)(t / 80);
        uint32_t p[4] = {0u, 0u, 0u, 0u};
        if (k < 75) {
            const float* s = w1f + ((long)g * 75 + k) * 256 + n0;
            float4 a = *reinterpret_cast<const float4*>(s);
            float4 b = *reinterpret_cast<const float4*>(s + 4);
            p[0] = pkf16(a.x, a.y); p[1] = pkf16(a.z, a.w);
            p[2] = pkf16(b.x, b.y); p[3] = pkf16(b.z, b.w);
        }
        *reinterpret_cast<uint4*>(w1h + ((long)g * 80 + k) * 256 + n0) =
            make_uint4(p[0], p[1], p[2], p[3]);
        return;
    }
    v -= V_W1;
    if (v < V_W2) {
        const float* s = w2f + v * 8;
        float4 a = *reinterpret_cast<const float4*>(s);
        float4 b = *reinterpret_cast<const float4*>(s + 4);
        *reinterpret_cast<uint4*>(w2h + v * 8) =
            make_uint4(pkf16(a.x, a.y), pkf16(a.z, a.w), pkf16(b.x, b.y), pkf16(b.z, b.w));
        return;
    }
    v -= V_W2;
    if (v < V_WD) {
        const float* s = wdf + v * 8;
        float4 a = *reinterpret_cast<const float4*>(s);
        float4 b = *reinterpret_cast<const float4*>(s + 4);
        *reinterpret_cast<uint4*>(wdh + v * 8) =
            make_uint4(pkf16(a.x, a.y), pkf16(a.z, a.w), pkf16(b.x, b.y), pkf16(b.z, b.w));
        return;
    }
    v -= V_WD;
    if (v < V_SEG) {
        *reinterpret_cast<float4*>(ssum + v * 4) = make_float4(0.f, 0.f, 0.f, 0.f);
        *reinterpret_cast<uint4*>(smax + v * 4) =
            make_uint4(0x007FFFFFu, 0x007FFFFFu, 0x007FFFFFu, 0x007FFFFFu);
    }
}

// ======================= gather / pool =======================
__device__ __forceinline__ void acc8(float2 s[4], uint4 v) {
    s[0].x += __low2float(*(__half2*)&v.x);  s[0].y += __high2float(*(__half2*)&v.x);
    s[1].x += __low2float(*(__half2*)&v.y);  s[1].y += __high2float(*(__half2*)&v.y);
    s[2].x += __low2float(*(__half2*)&v.z);  s[2].y += __high2float(*(__half2*)&v.z);
    s[3].x += __low2float(*(__half2*)&v.w);  s[3].y += __high2float(*(__half2*)&v.w);
}

template<int CH>
__global__ void gather_all_h(const __half* __restrict__ X,
                             const int* __restrict__ a1, const int* __restrict__ a2,
                             const int* __restrict__ a3, const int* __restrict__ a4,
                             __half* __restrict__ out)
{
    constexpr int LD = CH * 8;
    long idx = (long)blockIdx.x * blockDim.x + threadIdx.x;
    if (idx >= 61440L * CH) return;
    int i = (int)(idx / CH);
    int c = (int)(idx - (long)i * CH) * 8;
    const int* adj; int d, li;
    if (i < 12288)      { adj = a1; d = 1; li = i; }
    else if (i < 32768) { adj = a2; d = 2; li = i - 12288; }
    else if (i < 53248) { adj = a3; d = 3; li = i - 32768; }
    else                { adj = a4; d = 4; li = i - 53248; }
    float2 s[4];
    s[0] = s[1] = s[2] = s[3] = make_float2(0.f, 0.f);
    for (int j = 0; j < d; j++) {
        uint4 v = *reinterpret_cast<const uint4*>(X + (long)adj[li * d + j] * LD + c);
        acc8(s, v);
    }
    uint4 o;
    o.x = pkf16(s[0].x, s[0].y); o.y = pkf16(s[1].x, s[1].y);
    o.z = pkf16(s[2].x, s[2].y); o.w = pkf16(s[3].x, s[3].y);
    *reinterpret_cast<uint4*>(out + (long)i * LD + c) = o;
}

__device__ __forceinline__ void max8(uint4& m, uint4 v) {
    *(__half2*)&m.x = __hmax2(*(__half2*)&m.x, *(__half2*)&v.x);
    *(__half2*)&m.y = __hmax2(*(__half2*)&m.y, *(__half2*)&v.y);
    *(__half2*)&m.z = __hmax2(*(__half2*)&m.z, *(__half2*)&v.z);
    *(__half2*)&m.w = __hmax2(*(__half2*)&m.w, *(__half2*)&v.w);
}

// 32 halves (2 x uint4) per thread; 16 threads per 256-col row (at DRAM floor)
__global__ void pool_all_h(const uint4* __restrict__ X,
                           const int* __restrict__ a1, const int* __restrict__ a2,
                           const int* __restrict__ a3, const int* __restrict__ a4,
                           uint4* __restrict__ out)
{
    long idx = (long)blockIdx.x * blockDim.x + threadIdx.x;
    if (idx >= 65536L * 16) return;
    int row = (int)(idx >> 4);
    int c = (int)(idx & 15) * 2;
    long base = (long)row * 32 + c;
    uint4 m0 = X[base], m1 = X[base + 1];
    if (row >= 4096) {
        const int* adj; int d, li;
        if (row < 16384)      { adj = a1; d = 1; li = row - 4096; }
        else if (row < 36864) { adj = a2; d = 2; li = row - 16384; }
        else if (row < 57344) { adj = a3; d = 3; li = row - 36864; }
        else                  { adj = a4; d = 4; li = row - 57344; }
        for (int j = 0; j < d; j++) {
            long nb = (long)adj[li * d + j] * 32 + c;
            max8(m0, X[nb]);
            max8(m1, X[nb + 1]);
        }
    }
    out[base] = m0;
    out[base + 1] = m1;
}

// ======================= head (+tanh fp write, warp-parallel GEMV) ===========
__global__ void head_kernel(const float* __restrict__ ssum,
                            const unsigned* __restrict__ smax,
                            const float* __restrict__ W,
                            const float* __restrict__ b,
                            float* __restrict__ soft,
                            float* __restrict__ logits,
                            float* __restrict__ out_fp)
{
    __shared__ float row[1024];
    __shared__ float lg[24];
    int bi = blockIdx.x;
    int tid = threadIdx.x, w = tid >> 5, lane = tid & 31;
    for (int c = tid; c < 1024; c += blockDim.x) {
        float v = (c < 512) ? ssum[bi * 512 + c] : funord(smax[bi * 512 + (c - 512)]);
        float t = tanhf(v);
        row[c] = t;
        out_fp[bi * 1024 + c] = t;
    }
    __syncthreads();
    for (int o = w; o < 24; o += 8) {
        float acc = 0.f;
        for (int k = lane; k < 1024; k += 32)
            acc += row[k] * W[k * 24 + o];
#pragma unroll
        for (int s = 16; s; s >>= 1)
            acc += __shfl_xor_sync(0xFFFFFFFFu, acc, s);
        if (lane == 0) lg[o] = acc + b[o];
    }
    __syncthreads();
    if (tid < 24) logits[bi * 24 + tid] = lg[tid];
    if (tid < 12) {
        float l0 = lg[2 * tid], l1 = lg[2 * tid + 1];
        float m  = fmaxf(l0, l1);
        float e0 = expf(l0 - m), e1 = expf(l1 - m);
        float inv = 1.f / (e0 + e1);
        soft[bi * 24 + 2 * tid]     = e0 * inv;
        soft[bi * 24 + 2 * tid + 1] = e1 * inv;
    }
}

// ======================= launch =======================
extern "C" void kernel_launch(void* const* d_in, const int* in_sizes, int n_in,
                              void* d_out, int out_size)
{
    const float* atom       = (const float*)d_in[0];
    const int*   membership = (const int*)  d_in[2];
    const int*   a1 = (const int*)d_in[4];
    const int*   a2 = (const int*)d_in[5];
    const int*   a3 = (const int*)d_in[6];
    const int*   a4 = (const int*)d_in[7];
    const float* gc1W = (const float*)d_in[8];
    const float* gc1b = (const float*)d_in[9];
    const float* gc2W = (const float*)d_in[10];
    const float* gc2b = (const float*)d_in[11];
    const float* bn1  = (const float*)d_in[12];
    const float* bn2  = (const float*)d_in[13];
    const float* bn3  = (const float*)d_in[14];
    const float* dW   = (const float*)d_in[15];
    const float* db   = (const float*)d_in[16];
    const float* hW   = (const float*)d_in[17];
    const float* hb   = (const float*)d_in[18];

    __half *atomh, *relh, *bufAh, *bufBh, *w1h, *w2h, *wdh;
    float *ssum; unsigned* smax;
    cudaGetSymbolAddress((void**)&atomh, g_atomh);
    cudaGetSymbolAddress((void**)&relh,  g_relh);
    cudaGetSymbolAddress((void**)&bufAh, g_bufAh);
    cudaGetSymbolAddress((void**)&bufBh, g_bufBh);
    cudaGetSymbolAddress((void**)&w1h,   g_w1h);
    cudaGetSymbolAddress((void**)&w2h,   g_w2h);
    cudaGetSymbolAddress((void**)&wdh,   g_wdh);
    cudaGetSymbolAddress((void**)&ssum,  g_sum);
    cudaGetSymbolAddress((void**)&smax,  g_maxu);

    cudaFuncSetAttribute(conv_gemm_t<80>, cudaFuncAttributeMaxDynamicSharedMemorySize,
                         GP<80>::SMEM);
    cudaFuncSetAttribute(conv_gemm_t<64>, cudaFuncAttributeMaxDynamicSharedMemorySize,
                         GP<64>::SMEM);
    cudaFuncSetAttribute(dense_gemm_h,    cudaFuncAttributeMaxDynamicSharedMemorySize,
                         GP<64>::SMEM);

    float* out        = (float*)d_out;
    float* out_soft   = out;
    float* out_logits = out + 1024 * 24;
    float* out_fp     = out + 2 * 1024 * 24;

    // vectorized converts + seg init (one launch)
    {
        long tot = V_ATOM + V_W1 + V_W2 + V_WD + V_SEG;
        convert_all<<<(int)((tot + 255) / 256), 256>>>(
            atom, gc1W, gc2W, dW, atomh, w1h, w2h, wdh, ssum, smax);
    }

    // layer 1 (padded K=80; BKC=80, both chunks issued upfront)
    gather_all_h<10><<<(int)((61440L * 10 + 255) / 256), 256>>>(
        atomh, a1, a2, a3, a4, relh);
    conv_gemm_t<80><<<dim3(2, 512), 256, GP<80>::SMEM>>>(
        atomh, 80, 1, relh, w1h, gc1b, bn1, bufAh);
    pool_all_h<<<(int)((65536L * 16 + 255) / 256), 256>>>(
        (const uint4*)bufAh, a1, a2, a3, a4, (uint4*)bufBh);

    // layer 2 (K=256; BKC=64, 4 chunks/pass)
    gather_all_h<32><<<(int)((61440L * 32 + 255) / 256), 256>>>(
        bufBh, a1, a2, a3, a4, relh);
    conv_gemm_t<64><<<dim3(2, 512), 256, GP<64>::SMEM>>>(
        bufBh, 256, 4, relh, w2h, gc2b, bn2, bufAh);
    pool_all_h<<<(int)((65536L * 16 + 255) / 256), 256>>>(
        (const uint4*)bufAh, a1, a2, a3, a4, (uint4*)bufBh);

    // dense + BN3 + fused segment sum/max (BKC=64)
    dense_gemm_h<<<dim3(4, 512), 256, GP<64>::SMEM>>>(bufBh, wdh, db, bn3,
                                                      membership, ssum, smax);

    // head (+tanh fp write)
    head_kernel<<<1024, 256>>>(ssum, smax, hW, hb, out_soft, out_logits, out_fp);
}